// round 2
// baseline (speedup 1.0000x reference)
#include <cuda_runtime.h>
#include <math.h>

#define B  32768
#define D  512
#define H  256
#define OO 128
#define E_ 10
#define T_ 3
#define G_ 64
#define NS 4
#define NT 2
#define NE (NS + NT)

// Scratch (allocation-free: __device__ globals)
__device__ float g_h1[(size_t)E_ * B * H];    // 335 MB
__device__ float g_h2[(size_t)E_ * B * H];    // 335 MB
__device__ float g_eo[(size_t)E_ * B * OO];   // 167 MB
__device__ float g_gw[(size_t)T_ * B * NE];
__device__ float g_sgw[(size_t)B * E_];

// ---------------------------------------------------------------------------
// Fused expert layer: Y[e,b,n] = relu( LN( X @ W[e] + bias[e] ) * g[e] + bt[e] )
// Block: ROWS rows x N cols (full row -> LN is a warp reduction).
// Threads: 256, arranged tr(0..7) x tc(0..31). Each warp owns ROWS/8 rows.
// ---------------------------------------------------------------------------
template <int N, int K, int ROWS>
__global__ void __launch_bounds__(256)
expert_layer_kernel(const float* __restrict__ X,   // [B][K] or [E][B][K]
                    const float* __restrict__ W,   // [E][K][N]
                    const float* __restrict__ bias,// [E][N]
                    const float* __restrict__ gam, // [E][N]
                    const float* __restrict__ bet, // [E][N]
                    float* __restrict__ Y,         // [E][B][N]
                    int x_per_expert)
{
    constexpr int KT = 16;
    constexpr int RT = ROWS / 8;   // rows per thread
    constexpr int CT = N / 32;     // cols per thread (strided by 32)

    __shared__ float xs[ROWS][KT];
    __shared__ float ws[KT][N];

    const int e   = blockIdx.y;
    const int b0  = blockIdx.x * ROWS;
    const int tid = threadIdx.x;
    const int tr  = tid >> 5;
    const int tc  = tid & 31;

    const float* Xe = X + (x_per_expert ? (size_t)e * B * K : (size_t)0)
                        + (size_t)b0 * K;
    const float* We = W + (size_t)e * K * N;

    float acc[RT][CT];
#pragma unroll
    for (int i = 0; i < RT; i++)
#pragma unroll
        for (int j = 0; j < CT; j++) acc[i][j] = 0.f;

    for (int k0 = 0; k0 < K; k0 += KT) {
#pragma unroll
        for (int idx = tid; idx < ROWS * KT; idx += 256) {
            int r = idx / KT, kk = idx % KT;
            xs[r][kk] = Xe[(size_t)r * K + k0 + kk];
        }
#pragma unroll
        for (int idx = tid; idx < KT * N; idx += 256) {
            int kk = idx / N, c = idx % N;
            ws[kk][c] = We[(size_t)(k0 + kk) * N + c];
        }
        __syncthreads();

#pragma unroll
        for (int kk = 0; kk < KT; kk++) {
            float a[RT], bv[CT];
#pragma unroll
            for (int i = 0; i < RT; i++) a[i] = xs[tr * RT + i][kk];
#pragma unroll
            for (int j = 0; j < CT; j++) bv[j] = ws[kk][tc + 32 * j];
#pragma unroll
            for (int i = 0; i < RT; i++)
#pragma unroll
                for (int j = 0; j < CT; j++)
                    acc[i][j] = fmaf(a[i], bv[j], acc[i][j]);
        }
        __syncthreads();
    }

    // Epilogue: bias + LayerNorm (warp-wide since CT*32 == N) + affine + relu
    const float* be  = bias + (size_t)e * N;
    const float* ge  = gam  + (size_t)e * N;
    const float* bte = bet  + (size_t)e * N;
    float bb[CT], gv[CT], btv[CT];
#pragma unroll
    for (int j = 0; j < CT; j++) {
        int c = tc + 32 * j;
        bb[j] = be[c]; gv[j] = ge[c]; btv[j] = bte[c];
    }

#pragma unroll
    for (int i = 0; i < RT; i++) {
        float s = 0.f, s2 = 0.f;
#pragma unroll
        for (int j = 0; j < CT; j++) {
            float v = acc[i][j] + bb[j];
            acc[i][j] = v;
            s += v; s2 += v * v;
        }
#pragma unroll
        for (int off = 16; off > 0; off >>= 1) {
            s  += __shfl_xor_sync(0xffffffffu, s,  off);
            s2 += __shfl_xor_sync(0xffffffffu, s2, off);
        }
        float mean = s * (1.0f / N);
        float var  = s2 * (1.0f / N) - mean * mean;
        float rs   = rsqrtf(var + 1e-5f);
        int   b    = b0 + tr * RT + i;
        float* yrow = Y + ((size_t)e * B + b) * N;
#pragma unroll
        for (int j = 0; j < CT; j++) {
            float v = (acc[i][j] - mean) * rs * gv[j] + btv[j];
            yrow[tc + 32 * j] = fmaxf(v, 0.f);
        }
    }
}

// ---------------------------------------------------------------------------
// Fused gate: gh = relu(X @ W1 + b1)  [B x G], then softmax(gh @ W2 + b2)
// blockIdx.y = t (task index); for the shared gate grid.y == 1 (t = 0).
// ---------------------------------------------------------------------------
template <int NOUT>
__global__ void __launch_bounds__(256)
gate_kernel(const float* __restrict__ X,   // [B][D]
            const float* __restrict__ W1,  // [T][D][G] or [D][G]
            const float* __restrict__ b1,  // [T][G] or [G]
            const float* __restrict__ W2,  // [T][G][NOUT] or [G][NOUT]
            const float* __restrict__ b2,  // [T][NOUT] or [NOUT]
            float* __restrict__ out)       // [T][B][NOUT] or [B][NOUT]
{
    constexpr int ROWS = 32;
    constexpr int KT   = 16;
    constexpr int RT   = 4;                 // ROWS / 8
    constexpr int CT   = G_ / 32;           // 2

    __shared__ float xs[ROWS][KT];
    __shared__ float ws[KT][G_];
    __shared__ float gh[ROWS][G_];
    __shared__ float logits[ROWS][NOUT];

    const int t   = blockIdx.y;
    const int b0  = blockIdx.x * ROWS;
    const int tid = threadIdx.x;
    const int tr  = tid >> 5;
    const int tc  = tid & 31;

    const float* W1t = W1 + (size_t)t * D * G_;
    const float* b1t = b1 + (size_t)t * G_;
    const float* W2t = W2 + (size_t)t * G_ * NOUT;
    const float* b2t = b2 + (size_t)t * NOUT;
    float* outt = out + (size_t)t * B * NOUT;

    float acc[RT][CT];
#pragma unroll
    for (int i = 0; i < RT; i++)
#pragma unroll
        for (int j = 0; j < CT; j++) acc[i][j] = 0.f;

    for (int k0 = 0; k0 < D; k0 += KT) {
#pragma unroll
        for (int idx = tid; idx < ROWS * KT; idx += 256) {
            int r = idx / KT, kk = idx % KT;
            xs[r][kk] = X[(size_t)(b0 + r) * D + k0 + kk];
        }
#pragma unroll
        for (int idx = tid; idx < KT * G_; idx += 256) {
            int kk = idx / G_, c = idx % G_;
            ws[kk][c] = W1t[(size_t)(k0 + kk) * G_ + c];
        }
        __syncthreads();
#pragma unroll
        for (int kk = 0; kk < KT; kk++) {
            float a[RT], bv[CT];
#pragma unroll
            for (int i = 0; i < RT; i++) a[i] = xs[tr * RT + i][kk];
#pragma unroll
            for (int j = 0; j < CT; j++) bv[j] = ws[kk][tc + 32 * j];
#pragma unroll
            for (int i = 0; i < RT; i++)
#pragma unroll
                for (int j = 0; j < CT; j++)
                    acc[i][j] = fmaf(a[i], bv[j], acc[i][j]);
        }
        __syncthreads();
    }

    // gh = relu(acc + b1)
#pragma unroll
    for (int i = 0; i < RT; i++) {
        int r = tr * RT + i;
#pragma unroll
        for (int j = 0; j < CT; j++) {
            int c = tc + 32 * j;
            gh[r][c] = fmaxf(acc[i][j] + b1t[c], 0.f);
        }
    }
    __syncthreads();

    // logits = gh @ W2 + b2
    for (int idx = tid; idx < ROWS * NOUT; idx += 256) {
        int r = idx / NOUT, j = idx % NOUT;
        float s = b2t[j];
#pragma unroll
        for (int k = 0; k < G_; k++) s += gh[r][k] * W2t[(size_t)k * NOUT + j];
        logits[r][j] = s;
    }
    __syncthreads();

    // softmax per row
    if (tid < ROWS) {
        float m = -1e30f;
#pragma unroll
        for (int j = 0; j < NOUT; j++) m = fmaxf(m, logits[tid][j]);
        float ex[NOUT], s = 0.f;
#pragma unroll
        for (int j = 0; j < NOUT; j++) { ex[j] = __expf(logits[tid][j] - m); s += ex[j]; }
        float inv = 1.0f / s;
#pragma unroll
        for (int j = 0; j < NOUT; j++)
            outt[(size_t)(b0 + tid) * NOUT + j] = ex[j] * inv;
    }
}

// ---------------------------------------------------------------------------
// Combine: task_out[t,b,o] = sum_j gw[t,b,j] * combined[t,j,b,o]
//          shared_out[b,o] = sum_e sgw[b,e] * eo[e,b,o]
// out layout: [4][B][O], rows 0..2 = tasks, row 3 = shared.
// ---------------------------------------------------------------------------
__global__ void __launch_bounds__(256)
combine_kernel(const float* __restrict__ eo,  // [E][B][O]
               const float* __restrict__ gw,  // [T][B][NE]
               const float* __restrict__ sgw, // [B][E]
               float* __restrict__ out)       // [4][B][O]
{
    const int b = blockIdx.x * 2 + (threadIdx.x >> 7);
    const int o = threadIdx.x & 127;

    float v[E_];
#pragma unroll
    for (int e = 0; e < E_; e++)
        v[e] = eo[((size_t)e * B + b) * OO + o];

#pragma unroll
    for (int t = 0; t < T_; t++) {
        const float* g = gw + ((size_t)t * B + b) * NE;
        float s = 0.f;
#pragma unroll
        for (int j = 0; j < NS; j++) s += g[j] * v[j];
#pragma unroll
        for (int n = 0; n < NT; n++) s += g[NS + n] * v[NS + t * NT + n];
        out[((size_t)t * B + b) * OO + o] = s;
    }

    const float* sg = sgw + (size_t)b * E_;
    float s = 0.f;
#pragma unroll
    for (int e = 0; e < E_; e++) s += sg[e] * v[e];
    out[((size_t)3 * B + b) * OO + o] = s;
}

// ---------------------------------------------------------------------------
extern "C" void kernel_launch(void* const* d_in, const int* in_sizes, int n_in,
                              void* d_out, int out_size)
{
    const float* x     = (const float*)d_in[0];
    const float* ew1   = (const float*)d_in[1];
    const float* eb1   = (const float*)d_in[2];
    const float* eg1   = (const float*)d_in[3];
    const float* ebt1  = (const float*)d_in[4];
    const float* ew2   = (const float*)d_in[5];
    const float* eb2   = (const float*)d_in[6];
    const float* eg2   = (const float*)d_in[7];
    const float* ebt2  = (const float*)d_in[8];
    const float* ew3   = (const float*)d_in[9];
    const float* eb3   = (const float*)d_in[10];
    const float* eg3   = (const float*)d_in[11];
    const float* ebt3  = (const float*)d_in[12];
    const float* tg_w1 = (const float*)d_in[13];
    const float* tg_b1 = (const float*)d_in[14];
    const float* tg_w2 = (const float*)d_in[15];
    const float* tg_b2 = (const float*)d_in[16];
    const float* sg_w1 = (const float*)d_in[17];
    const float* sg_b1 = (const float*)d_in[18];
    const float* sg_w2 = (const float*)d_in[19];
    const float* sg_b2 = (const float*)d_in[20];
    float* out = (float*)d_out;

    static float *h1 = nullptr, *h2 = nullptr, *eo = nullptr, *gw = nullptr, *sgw = nullptr;
    if (!h1) {
        cudaGetSymbolAddress((void**)&h1,  g_h1);
        cudaGetSymbolAddress((void**)&h2,  g_h2);
        cudaGetSymbolAddress((void**)&eo,  g_eo);
        cudaGetSymbolAddress((void**)&gw,  g_gw);
        cudaGetSymbolAddress((void**)&sgw, g_sgw);
    }

    dim3 blk(256);

    // Layer 1: x [B,512] @ ew1 [E,512,256] -> h1 [E,B,256]
    expert_layer_kernel<256, 512, 64><<<dim3(B / 64, E_), blk>>>(
        x, ew1, eb1, eg1, ebt1, h1, 0);
    // Layer 2: h1 [E,B,256] @ ew2 [E,256,256] -> h2
    expert_layer_kernel<256, 256, 64><<<dim3(B / 64, E_), blk>>>(
        h1, ew2, eb2, eg2, ebt2, h2, 1);
    // Layer 3: h2 [E,B,256] @ ew3 [E,256,128] -> eo [E,B,128]
    expert_layer_kernel<128, 256, 64><<<dim3(B / 64, E_), blk>>>(
        h2, ew3, eb3, eg3, ebt3, eo, 1);

    // Task gates (t = 0..2) and shared gate
    gate_kernel<NE><<<dim3(B / 32, T_), blk>>>(x, tg_w1, tg_b1, tg_w2, tg_b2, gw);
    gate_kernel<E_><<<dim3(B / 32, 1), blk>>>(x, sg_w1, sg_b1, sg_w2, sg_b2, sgw);

    // Final mixture
    combine_kernel<<<B / 2, blk>>>(eo, gw, sgw, out);
}

// round 3
// speedup vs baseline: 1.5534x; 1.5534x over previous
#include <cuda_runtime.h>
#include <cuda_bf16.h>
#include <math.h>

#define B  32768
#define D  512
#define H  256
#define OO 128
#define E_ 10
#define T_ 3
#define G_ 64
#define NS 4
#define NT_TASK 2
#define NE (NS + NT_TASK)

typedef __nv_bfloat16 bf16;

// ---------------- scratch (allocation-free) ----------------
__device__ bf16  g_xhi[(size_t)B * D];
__device__ bf16  g_xlo[(size_t)B * D];
__device__ bf16  g_h1hi[(size_t)E_ * B * H];
__device__ bf16  g_h1lo[(size_t)E_ * B * H];
__device__ bf16  g_h2hi[(size_t)E_ * B * H];
__device__ bf16  g_h2lo[(size_t)E_ * B * H];
__device__ float g_eo[(size_t)E_ * B * OO];
__device__ bf16  g_w1hi[(size_t)E_ * D * H];
__device__ bf16  g_w1lo[(size_t)E_ * D * H];
__device__ bf16  g_w2hi[(size_t)E_ * H * H];
__device__ bf16  g_w2lo[(size_t)E_ * H * H];
__device__ bf16  g_w3hi[(size_t)E_ * H * OO];
__device__ bf16  g_w3lo[(size_t)E_ * H * OO];
__device__ bf16  g_tgw1hi[(size_t)T_ * D * G_];
__device__ bf16  g_tgw1lo[(size_t)T_ * D * G_];
__device__ bf16  g_sgw1hi[(size_t)D * G_];
__device__ bf16  g_sgw1lo[(size_t)D * G_];
__device__ float g_gw[(size_t)T_ * B * NE];
__device__ float g_sgw[(size_t)B * E_];

// ---------------- helpers ----------------
__device__ __forceinline__ void mma_bf16(float* c, const unsigned* a, const unsigned* b) {
    asm volatile(
        "mma.sync.aligned.m16n8k16.row.col.f32.bf16.bf16.f32 "
        "{%0,%1,%2,%3}, {%4,%5,%6,%7}, {%8,%9}, {%0,%1,%2,%3};\n"
        : "+f"(c[0]), "+f"(c[1]), "+f"(c[2]), "+f"(c[3])
        : "r"(a[0]), "r"(a[1]), "r"(a[2]), "r"(a[3]), "r"(b[0]), "r"(b[1]));
}

__device__ __forceinline__ unsigned pack_bf16(bf16 lo, bf16 hi) {
    return (unsigned)__bfloat16_as_ushort(lo) | ((unsigned)__bfloat16_as_ushort(hi) << 16);
}

// hi = bf16(v), lo = bf16(v - hi). Vectorized x4.
__global__ void split_hi_lo(const float4* __restrict__ src,
                            unsigned* __restrict__ hi2, unsigned* __restrict__ lo2,
                            int n4)
{
    int i = blockIdx.x * blockDim.x + threadIdx.x;
    if (i >= n4) return;
    float4 v = src[i];
    bf16 h0 = __float2bfloat16(v.x), h1 = __float2bfloat16(v.y);
    bf16 h2 = __float2bfloat16(v.z), h3 = __float2bfloat16(v.w);
    bf16 l0 = __float2bfloat16(v.x - __bfloat162float(h0));
    bf16 l1 = __float2bfloat16(v.y - __bfloat162float(h1));
    bf16 l2 = __float2bfloat16(v.z - __bfloat162float(h2));
    bf16 l3 = __float2bfloat16(v.w - __bfloat162float(h3));
    hi2[i * 2]     = pack_bf16(h0, h1);
    hi2[i * 2 + 1] = pack_bf16(h2, h3);
    lo2[i * 2]     = pack_bf16(l0, l1);
    lo2[i * 2 + 1] = pack_bf16(l2, l3);
}

// ---------------------------------------------------------------------------
// Expert layer on tensor cores (split-bf16, 3 passes), fused bias+LN+ReLU.
// Block = WM*WN warps. Each warp: 16 rows x (N/WN) cols via m16n8k16 tiles.
// LN over full row N (cross-warp_n partials reduced through tiny smem).
// ---------------------------------------------------------------------------
template <int N, int K, int BM, int WM, int WN, bool SPLIT_OUT>
__global__ void __launch_bounds__(WM * WN * 32)
expert_mma(const bf16* __restrict__ Ahi, const bf16* __restrict__ Alo, // [B,K] or [E,B,K]
           const bf16* __restrict__ Whi, const bf16* __restrict__ Wlo, // [E,K,N]
           const float* __restrict__ bias, const float* __restrict__ gam,
           const float* __restrict__ bet,
           bf16* __restrict__ Yhi, bf16* __restrict__ Ylo,             // if SPLIT_OUT
           float* __restrict__ Yf,                                     // else
           int x_per_expert)
{
    constexpr int WNC = N / WN;       // cols per warp
    constexpr int NTI = WNC / 8;      // n-tiles per warp
    constexpr int NTHREADS = WM * WN * 32;

    __shared__ bf16 sAh[BM][16], sAl[BM][16];
    __shared__ bf16 sBh[N][18],  sBl[N][18];
    __shared__ float red[WN][BM][2];

    const int e   = blockIdx.y;
    const int b0  = blockIdx.x * BM;
    const int tid = threadIdx.x;
    const int wid = tid >> 5, lane = tid & 31;
    const int warp_m = wid % WM, warp_n = wid / WM;
    const int gr = lane >> 2, tg = lane & 3;
    const int ar = warp_m * 16 + gr;          // lane's row0 within block tile

    const bf16* Ae_h = Ahi + (x_per_expert ? (size_t)e * B * K : (size_t)0) + (size_t)b0 * K;
    const bf16* Ae_l = Alo + (x_per_expert ? (size_t)e * B * K : (size_t)0) + (size_t)b0 * K;
    const bf16* We_h = Whi + (size_t)e * K * N;
    const bf16* We_l = Wlo + (size_t)e * K * N;

    float acc[NTI][4];
#pragma unroll
    for (int nt = 0; nt < NTI; nt++)
#pragma unroll
        for (int j = 0; j < 4; j++) acc[nt][j] = 0.f;

    for (int k0 = 0; k0 < K; k0 += 16) {
        __syncthreads();
        // A tile (BM x 16), 4 bf16 per thread-chunk
#pragma unroll
        for (int i = tid * 4; i < BM * 16; i += NTHREADS * 4) {
            int r = i >> 4, kk = i & 15;
            *(uint2*)&sAh[r][kk] = *(const uint2*)&Ae_h[(size_t)r * K + k0 + kk];
            *(uint2*)&sAl[r][kk] = *(const uint2*)&Ae_l[(size_t)r * K + k0 + kk];
        }
        // B tile (16 x N) transposed into [N][18]
#pragma unroll
        for (int i = tid; i < 16 * (N / 2); i += NTHREADS) {
            int kk = i / (N / 2), cp = i % (N / 2);
            unsigned vh = *(const unsigned*)&We_h[(size_t)(k0 + kk) * N + cp * 2];
            unsigned vl = *(const unsigned*)&We_l[(size_t)(k0 + kk) * N + cp * 2];
            sBh[cp * 2    ][kk] = __ushort_as_bfloat16((unsigned short)(vh & 0xffff));
            sBh[cp * 2 + 1][kk] = __ushort_as_bfloat16((unsigned short)(vh >> 16));
            sBl[cp * 2    ][kk] = __ushort_as_bfloat16((unsigned short)(vl & 0xffff));
            sBl[cp * 2 + 1][kk] = __ushort_as_bfloat16((unsigned short)(vl >> 16));
        }
        __syncthreads();

        unsigned ah[4], al[4];
        ah[0] = *(unsigned*)&sAh[ar    ][tg * 2];
        ah[1] = *(unsigned*)&sAh[ar + 8][tg * 2];
        ah[2] = *(unsigned*)&sAh[ar    ][tg * 2 + 8];
        ah[3] = *(unsigned*)&sAh[ar + 8][tg * 2 + 8];
        al[0] = *(unsigned*)&sAl[ar    ][tg * 2];
        al[1] = *(unsigned*)&sAl[ar + 8][tg * 2];
        al[2] = *(unsigned*)&sAl[ar    ][tg * 2 + 8];
        al[3] = *(unsigned*)&sAl[ar + 8][tg * 2 + 8];

#pragma unroll
        for (int nt = 0; nt < NTI; nt++) {
            int bc = warp_n * WNC + nt * 8 + gr;
            unsigned bh[2], bl[2];
            bh[0] = *(unsigned*)&sBh[bc][tg * 2];
            bh[1] = *(unsigned*)&sBh[bc][tg * 2 + 8];
            bl[0] = *(unsigned*)&sBl[bc][tg * 2];
            bl[1] = *(unsigned*)&sBl[bc][tg * 2 + 8];
            mma_bf16(acc[nt], ah, bh);
            mma_bf16(acc[nt], ah, bl);
            mma_bf16(acc[nt], al, bh);
        }
    }

    // ---------------- epilogue: bias + LN + affine + relu ----------------
    const float* be  = bias + (size_t)e * N;
    const float* ge  = gam  + (size_t)e * N;
    const float* bte = bet  + (size_t)e * N;
    const int cbase = warp_n * WNC + tg * 2;

    float s0 = 0.f, q0 = 0.f, s1 = 0.f, q1 = 0.f;
#pragma unroll
    for (int nt = 0; nt < NTI; nt++) {
        int c = cbase + nt * 8;
        float bv0 = be[c], bv1 = be[c + 1];
        acc[nt][0] += bv0; acc[nt][1] += bv1;
        acc[nt][2] += bv0; acc[nt][3] += bv1;
        s0 += acc[nt][0] + acc[nt][1];
        q0 = fmaf(acc[nt][0], acc[nt][0], fmaf(acc[nt][1], acc[nt][1], q0));
        s1 += acc[nt][2] + acc[nt][3];
        q1 = fmaf(acc[nt][2], acc[nt][2], fmaf(acc[nt][3], acc[nt][3], q1));
    }
    // reduce over the 4 lanes of the row-group
#pragma unroll
    for (int off = 1; off <= 2; off <<= 1) {
        s0 += __shfl_xor_sync(0xffffffffu, s0, off);
        q0 += __shfl_xor_sync(0xffffffffu, q0, off);
        s1 += __shfl_xor_sync(0xffffffffu, s1, off);
        q1 += __shfl_xor_sync(0xffffffffu, q1, off);
    }
    if (WN > 1) {
        __syncthreads();
        if (tg == 0) {
            red[warp_n][ar    ][0] = s0; red[warp_n][ar    ][1] = q0;
            red[warp_n][ar + 8][0] = s1; red[warp_n][ar + 8][1] = q1;
        }
        __syncthreads();
        s0 = 0.f; q0 = 0.f; s1 = 0.f; q1 = 0.f;
#pragma unroll
        for (int w = 0; w < WN; w++) {
            s0 += red[w][ar][0];     q0 += red[w][ar][1];
            s1 += red[w][ar + 8][0]; q1 += red[w][ar + 8][1];
        }
    }
    const float invN = 1.0f / N;
    float m0 = s0 * invN, m1 = s1 * invN;
    float r0 = rsqrtf(q0 * invN - m0 * m0 + 1e-5f);
    float r1 = rsqrtf(q1 * invN - m1 * m1 + 1e-5f);

    size_t row0 = ((size_t)e * B + b0 + ar) * N;
    size_t row1 = row0 + (size_t)8 * N;

#pragma unroll
    for (int nt = 0; nt < NTI; nt++) {
        int c = cbase + nt * 8;
        float g0 = ge[c], g1 = ge[c + 1], t0 = bte[c], t1 = bte[c + 1];
        float v00 = fmaxf((acc[nt][0] - m0) * r0 * g0 + t0, 0.f);
        float v01 = fmaxf((acc[nt][1] - m0) * r0 * g1 + t1, 0.f);
        float v10 = fmaxf((acc[nt][2] - m1) * r1 * g0 + t0, 0.f);
        float v11 = fmaxf((acc[nt][3] - m1) * r1 * g1 + t1, 0.f);
        if (SPLIT_OUT) {
            bf16 h00 = __float2bfloat16(v00), h01 = __float2bfloat16(v01);
            bf16 h10 = __float2bfloat16(v10), h11 = __float2bfloat16(v11);
            *(unsigned*)&Yhi[row0 + c] = pack_bf16(h00, h01);
            *(unsigned*)&Yhi[row1 + c] = pack_bf16(h10, h11);
            bf16 l00 = __float2bfloat16(v00 - __bfloat162float(h00));
            bf16 l01 = __float2bfloat16(v01 - __bfloat162float(h01));
            bf16 l10 = __float2bfloat16(v10 - __bfloat162float(h10));
            bf16 l11 = __float2bfloat16(v11 - __bfloat162float(h11));
            *(unsigned*)&Ylo[row0 + c] = pack_bf16(l00, l01);
            *(unsigned*)&Ylo[row1 + c] = pack_bf16(l10, l11);
        } else {
            *(float2*)&Yf[row0 + c] = make_float2(v00, v01);
            *(float2*)&Yf[row1 + c] = make_float2(v10, v11);
        }
    }
}

// ---------------------------------------------------------------------------
// Gate: relu(x@W1+b1) on tensor cores, then tiny GEMM + softmax in smem.
// BM=128 rows/block, 8 warps (WM=8, WN=1), G=64 cols.
// ---------------------------------------------------------------------------
template <int NOUT>
__global__ void __launch_bounds__(256)
gate_mma(const bf16* __restrict__ xhi, const bf16* __restrict__ xlo,
         const bf16* __restrict__ w1hi, const bf16* __restrict__ w1lo, size_t w1stride,
         const float* __restrict__ b1, size_t b1stride,
         const float* __restrict__ w2, size_t w2stride,
         const float* __restrict__ b2, size_t b2stride,
         float* __restrict__ out, size_t outstride)
{
    constexpr int BM = 128, K = D, N = G_, NTI = N / 8;
    constexpr int NTHREADS = 256;

    __shared__ bf16 sAh[BM][16], sAl[BM][16];
    __shared__ bf16 sBh[N][18],  sBl[N][18];
    __shared__ float ghs[BM][G_ + 1];
    __shared__ float ws2[G_][NOUT];
    __shared__ float b2s[NOUT];

    const int t   = blockIdx.y;
    const int b0  = blockIdx.x * BM;
    const int tid = threadIdx.x;
    const int wid = tid >> 5, lane = tid & 31;
    const int gr = lane >> 2, tg = lane & 3;
    const int ar = wid * 16 + gr;

    const bf16* W1h = w1hi + (size_t)t * w1stride;
    const bf16* W1l = w1lo + (size_t)t * w1stride;
    const float* b1t = b1 + (size_t)t * b1stride;
    const float* w2t = w2 + (size_t)t * w2stride;
    const float* b2t = b2 + (size_t)t * b2stride;
    float* outt = out + (size_t)t * outstride;

    // preload W2/b2
    for (int i = tid; i < G_ * NOUT; i += NTHREADS) ws2[i / NOUT][i % NOUT] = w2t[i];
    if (tid < NOUT) b2s[tid] = b2t[tid];

    float acc[NTI][4];
#pragma unroll
    for (int nt = 0; nt < NTI; nt++)
#pragma unroll
        for (int j = 0; j < 4; j++) acc[nt][j] = 0.f;

    for (int k0 = 0; k0 < K; k0 += 16) {
        __syncthreads();
#pragma unroll
        for (int i = tid * 4; i < BM * 16; i += NTHREADS * 4) {
            int r = i >> 4, kk = i & 15;
            *(uint2*)&sAh[r][kk] = *(const uint2*)&xhi[(size_t)(b0 + r) * K + k0 + kk];
            *(uint2*)&sAl[r][kk] = *(const uint2*)&xlo[(size_t)(b0 + r) * K + k0 + kk];
        }
#pragma unroll
        for (int i = tid; i < 16 * (N / 2); i += NTHREADS) {
            int kk = i / (N / 2), cp = i % (N / 2);
            unsigned vh = *(const unsigned*)&W1h[(size_t)(k0 + kk) * N + cp * 2];
            unsigned vl = *(const unsigned*)&W1l[(size_t)(k0 + kk) * N + cp * 2];
            sBh[cp * 2    ][kk] = __ushort_as_bfloat16((unsigned short)(vh & 0xffff));
            sBh[cp * 2 + 1][kk] = __ushort_as_bfloat16((unsigned short)(vh >> 16));
            sBl[cp * 2    ][kk] = __ushort_as_bfloat16((unsigned short)(vl & 0xffff));
            sBl[cp * 2 + 1][kk] = __ushort_as_bfloat16((unsigned short)(vl >> 16));
        }
        __syncthreads();

        unsigned ah[4], al[4];
        ah[0] = *(unsigned*)&sAh[ar    ][tg * 2];
        ah[1] = *(unsigned*)&sAh[ar + 8][tg * 2];
        ah[2] = *(unsigned*)&sAh[ar    ][tg * 2 + 8];
        ah[3] = *(unsigned*)&sAh[ar + 8][tg * 2 + 8];
        al[0] = *(unsigned*)&sAl[ar    ][tg * 2];
        al[1] = *(unsigned*)&sAl[ar + 8][tg * 2];
        al[2] = *(unsigned*)&sAl[ar    ][tg * 2 + 8];
        al[3] = *(unsigned*)&sAl[ar + 8][tg * 2 + 8];

#pragma unroll
        for (int nt = 0; nt < NTI; nt++) {
            int bc = nt * 8 + gr;
            unsigned bh[2], bl[2];
            bh[0] = *(unsigned*)&sBh[bc][tg * 2];
            bh[1] = *(unsigned*)&sBh[bc][tg * 2 + 8];
            bl[0] = *(unsigned*)&sBl[bc][tg * 2];
            bl[1] = *(unsigned*)&sBl[bc][tg * 2 + 8];
            mma_bf16(acc[nt], ah, bh);
            mma_bf16(acc[nt], ah, bl);
            mma_bf16(acc[nt], al, bh);
        }
    }
    __syncthreads();

    // gh = relu(acc + b1) -> smem
#pragma unroll
    for (int nt = 0; nt < NTI; nt++) {
        int c = nt * 8 + tg * 2;
        float bv0 = b1t[c], bv1 = b1t[c + 1];
        ghs[ar    ][c]     = fmaxf(acc[nt][0] + bv0, 0.f);
        ghs[ar    ][c + 1] = fmaxf(acc[nt][1] + bv1, 0.f);
        ghs[ar + 8][c]     = fmaxf(acc[nt][2] + bv0, 0.f);
        ghs[ar + 8][c + 1] = fmaxf(acc[nt][3] + bv1, 0.f);
    }
    __syncthreads();

    // logits + softmax (one row per thread)
    if (tid < BM) {
        float lg[NOUT];
#pragma unroll
        for (int j = 0; j < NOUT; j++) lg[j] = b2s[j];
        for (int k = 0; k < G_; k++) {
            float g = ghs[tid][k];
#pragma unroll
            for (int j = 0; j < NOUT; j++) lg[j] = fmaf(g, ws2[k][j], lg[j]);
        }
        float mx = -1e30f;
#pragma unroll
        for (int j = 0; j < NOUT; j++) mx = fmaxf(mx, lg[j]);
        float sum = 0.f;
#pragma unroll
        for (int j = 0; j < NOUT; j++) { lg[j] = __expf(lg[j] - mx); sum += lg[j]; }
        float inv = 1.0f / sum;
#pragma unroll
        for (int j = 0; j < NOUT; j++)
            outt[(size_t)(b0 + tid) * NOUT + j] = lg[j] * inv;
    }
}

// ---------------------------------------------------------------------------
// Combine
// ---------------------------------------------------------------------------
__global__ void __launch_bounds__(256)
combine_kernel(const float* __restrict__ eo,  // [E][B][O]
               const float* __restrict__ gw,  // [T][B][NE]
               const float* __restrict__ sgw, // [B][E]
               float* __restrict__ out)       // [4][B][O]
{
    const int b = blockIdx.x * 2 + (threadIdx.x >> 7);
    const int o = threadIdx.x & 127;

    float v[E_];
#pragma unroll
    for (int e = 0; e < E_; e++)
        v[e] = eo[((size_t)e * B + b) * OO + o];

#pragma unroll
    for (int t = 0; t < T_; t++) {
        const float* g = gw + ((size_t)t * B + b) * NE;
        float s = 0.f;
#pragma unroll
        for (int j = 0; j < NS; j++) s += g[j] * v[j];
#pragma unroll
        for (int n = 0; n < NT_TASK; n++) s += g[NS + n] * v[NS + t * NT_TASK + n];
        out[((size_t)t * B + b) * OO + o] = s;
    }

    const float* sg = sgw + (size_t)b * E_;
    float s = 0.f;
#pragma unroll
    for (int e = 0; e < E_; e++) s += sg[e] * v[e];
    out[((size_t)3 * B + b) * OO + o] = s;
}

// ---------------------------------------------------------------------------
extern "C" void kernel_launch(void* const* d_in, const int* in_sizes, int n_in,
                              void* d_out, int out_size)
{
    const float* x     = (const float*)d_in[0];
    const float* ew1   = (const float*)d_in[1];
    const float* eb1   = (const float*)d_in[2];
    const float* eg1   = (const float*)d_in[3];
    const float* ebt1  = (const float*)d_in[4];
    const float* ew2   = (const float*)d_in[5];
    const float* eb2   = (const float*)d_in[6];
    const float* eg2   = (const float*)d_in[7];
    const float* ebt2  = (const float*)d_in[8];
    const float* ew3   = (const float*)d_in[9];
    const float* eb3   = (const float*)d_in[10];
    const float* eg3   = (const float*)d_in[11];
    const float* ebt3  = (const float*)d_in[12];
    const float* tg_w1 = (const float*)d_in[13];
    const float* tg_b1 = (const float*)d_in[14];
    const float* tg_w2 = (const float*)d_in[15];
    const float* tg_b2 = (const float*)d_in[16];
    const float* sg_w1 = (const float*)d_in[17];
    const float* sg_b1 = (const float*)d_in[18];
    const float* sg_w2 = (const float*)d_in[19];
    const float* sg_b2 = (const float*)d_in[20];
    float* out = (float*)d_out;

    static bf16 *xhi = nullptr, *xlo, *h1hi, *h1lo, *h2hi, *h2lo;
    static bf16 *w1hi, *w1lo, *w2hi, *w2lo, *w3hi, *w3lo, *tgw1hi, *tgw1lo, *sgw1hi, *sgw1lo;
    static float *eo, *gw, *sgw;
    if (!xhi) {
        cudaGetSymbolAddress((void**)&xhi, g_xhi);   cudaGetSymbolAddress((void**)&xlo, g_xlo);
        cudaGetSymbolAddress((void**)&h1hi, g_h1hi); cudaGetSymbolAddress((void**)&h1lo, g_h1lo);
        cudaGetSymbolAddress((void**)&h2hi, g_h2hi); cudaGetSymbolAddress((void**)&h2lo, g_h2lo);
        cudaGetSymbolAddress((void**)&w1hi, g_w1hi); cudaGetSymbolAddress((void**)&w1lo, g_w1lo);
        cudaGetSymbolAddress((void**)&w2hi, g_w2hi); cudaGetSymbolAddress((void**)&w2lo, g_w2lo);
        cudaGetSymbolAddress((void**)&w3hi, g_w3hi); cudaGetSymbolAddress((void**)&w3lo, g_w3lo);
        cudaGetSymbolAddress((void**)&tgw1hi, g_tgw1hi); cudaGetSymbolAddress((void**)&tgw1lo, g_tgw1lo);
        cudaGetSymbolAddress((void**)&sgw1hi, g_sgw1hi); cudaGetSymbolAddress((void**)&sgw1lo, g_sgw1lo);
        cudaGetSymbolAddress((void**)&eo, g_eo);
        cudaGetSymbolAddress((void**)&gw, g_gw);
        cudaGetSymbolAddress((void**)&sgw, g_sgw);
    }

    // ---- splits ----
    auto launch_split = [](const float* src, bf16* hi, bf16* lo, size_t n) {
        int n4 = (int)(n / 4);
        split_hi_lo<<<(n4 + 255) / 256, 256>>>((const float4*)src, (unsigned*)hi, (unsigned*)lo, n4);
    };
    launch_split(x,     xhi,    xlo,    (size_t)B * D);
    launch_split(ew1,   w1hi,   w1lo,   (size_t)E_ * D * H);
    launch_split(ew2,   w2hi,   w2lo,   (size_t)E_ * H * H);
    launch_split(ew3,   w3hi,   w3lo,   (size_t)E_ * H * OO);
    launch_split(tg_w1, tgw1hi, tgw1lo, (size_t)T_ * D * G_);
    launch_split(sg_w1, sgw1hi, sgw1lo, (size_t)D * G_);

    // ---- expert layers (tensor cores) ----
    // L1: x[B,512] @ ew1[E,512,256] -> h1 (split bf16)
    expert_mma<256, 512, 64, 4, 2, true><<<dim3(B / 64, E_), 256>>>(
        xhi, xlo, w1hi, w1lo, eb1, eg1, ebt1, h1hi, h1lo, nullptr, 0);
    // L2: h1 @ ew2[E,256,256] -> h2 (split bf16)
    expert_mma<256, 256, 64, 4, 2, true><<<dim3(B / 64, E_), 256>>>(
        h1hi, h1lo, w2hi, w2lo, eb2, eg2, ebt2, h2hi, h2lo, nullptr, 1);
    // L3: h2 @ ew3[E,256,128] -> eo (fp32)
    expert_mma<128, 256, 128, 8, 1, false><<<dim3(B / 128, E_), 256>>>(
        h2hi, h2lo, w3hi, w3lo, eb3, eg3, ebt3, nullptr, nullptr, eo, 1);

    // ---- gates ----
    gate_mma<NE><<<dim3(B / 128, T_), 256>>>(
        xhi, xlo, tgw1hi, tgw1lo, (size_t)D * G_,
        tg_b1, (size_t)G_, tg_w2, (size_t)G_ * NE, tg_b2, (size_t)NE,
        gw, (size_t)B * NE);
    gate_mma<E_><<<dim3(B / 128, 1), 256>>>(
        xhi, xlo, sgw1hi, sgw1lo, (size_t)0,
        sg_b1, (size_t)0, sg_w2, (size_t)0, sg_b2, (size_t)0,
        sgw, (size_t)0);

    // ---- final mixture ----
    combine_kernel<<<B / 2, 256>>>(eo, gw, sgw, out);
}

// round 4
// speedup vs baseline: 2.1138x; 1.3607x over previous
#include <cuda_runtime.h>
#include <cuda_bf16.h>
#include <math.h>

#define B  32768
#define D  512
#define H  256
#define OO 128
#define E_ 10
#define T_ 3
#define G_ 64
#define NS 4
#define NT_TASK 2
#define NE (NS + NT_TASK)

typedef __nv_bfloat16 bf16;

// ---------------- scratch (allocation-free) ----------------
__device__ bf16  g_xhi[(size_t)B * D];
__device__ bf16  g_xlo[(size_t)B * D];
__device__ bf16  g_w1th[(size_t)E_ * H * D];    // transposed [E][N=H][K=D]
__device__ bf16  g_w1tl[(size_t)E_ * H * D];
__device__ bf16  g_w2th[(size_t)E_ * H * H];
__device__ bf16  g_w2tl[(size_t)E_ * H * H];
__device__ bf16  g_w3th[(size_t)E_ * OO * H];
__device__ bf16  g_w3tl[(size_t)E_ * OO * H];
__device__ bf16  g_tgw1hi[(size_t)T_ * D * G_];
__device__ bf16  g_tgw1lo[(size_t)T_ * D * G_];
__device__ bf16  g_sgw1hi[(size_t)D * G_];
__device__ bf16  g_sgw1lo[(size_t)D * G_];
__device__ float g_eo[(size_t)E_ * B * OO];
__device__ float g_gw[(size_t)T_ * B * NE];
__device__ float g_sgw[(size_t)B * E_];

// ---------------- helpers ----------------
__device__ __forceinline__ void mma_bf16(float* c, const unsigned* a, const unsigned* b) {
    asm volatile(
        "mma.sync.aligned.m16n8k16.row.col.f32.bf16.bf16.f32 "
        "{%0,%1,%2,%3}, {%4,%5,%6,%7}, {%8,%9}, {%0,%1,%2,%3};\n"
        : "+f"(c[0]), "+f"(c[1]), "+f"(c[2]), "+f"(c[3])
        : "r"(a[0]), "r"(a[1]), "r"(a[2]), "r"(a[3]), "r"(b[0]), "r"(b[1]));
}

__device__ __forceinline__ unsigned pack_bf16(bf16 lo, bf16 hi) {
    return (unsigned)__bfloat16_as_ushort(lo) | ((unsigned)__bfloat16_as_ushort(hi) << 16);
}

__device__ __forceinline__ void cp16(void* s, const void* g) {
    unsigned sa = (unsigned)__cvta_generic_to_shared(s);
    asm volatile("cp.async.cg.shared.global [%0], [%1], 16;\n" :: "r"(sa), "l"(g));
}
__device__ __forceinline__ void cp_commit() { asm volatile("cp.async.commit_group;\n"); }
template <int N2> __device__ __forceinline__ void cp_wait() {
    asm volatile("cp.async.wait_group %0;\n" :: "n"(N2));
}

__device__ __forceinline__ void load_afrag(unsigned* a, const bf16* base, int stride, int r, int koff) {
    a[0] = *(const unsigned*)(base + (size_t)r * stride + koff);
    a[1] = *(const unsigned*)(base + (size_t)(r + 8) * stride + koff);
    a[2] = *(const unsigned*)(base + (size_t)r * stride + koff + 8);
    a[3] = *(const unsigned*)(base + (size_t)(r + 8) * stride + koff + 8);
}
__device__ __forceinline__ void load_bfrag(unsigned* b, const bf16* base, int stride, int n, int koff) {
    b[0] = *(const unsigned*)(base + (size_t)n * stride + koff);
    b[1] = *(const unsigned*)(base + (size_t)n * stride + koff + 8);
}

// hi = bf16(v), lo = bf16(v - hi). Vectorized x4.
__global__ void split_hi_lo(const float4* __restrict__ src,
                            unsigned* __restrict__ hi2, unsigned* __restrict__ lo2,
                            int n4)
{
    int i = blockIdx.x * blockDim.x + threadIdx.x;
    if (i >= n4) return;
    float4 v = src[i];
    bf16 h0 = __float2bfloat16(v.x), h1 = __float2bfloat16(v.y);
    bf16 h2 = __float2bfloat16(v.z), h3 = __float2bfloat16(v.w);
    bf16 l0 = __float2bfloat16(v.x - __bfloat162float(h0));
    bf16 l1 = __float2bfloat16(v.y - __bfloat162float(h1));
    bf16 l2 = __float2bfloat16(v.z - __bfloat162float(h2));
    bf16 l3 = __float2bfloat16(v.w - __bfloat162float(h3));
    hi2[i * 2]     = pack_bf16(h0, h1);
    hi2[i * 2 + 1] = pack_bf16(h2, h3);
    lo2[i * 2]     = pack_bf16(l0, l1);
    lo2[i * 2 + 1] = pack_bf16(l2, l3);
}

// Transpose + split: W [E][K][N] fp32 -> Th/Tl [E][N][K] bf16.
__global__ void transpose_split(const float* __restrict__ W,
                                bf16* __restrict__ Th, bf16* __restrict__ Tl,
                                int K, int N)
{
    __shared__ float t[32][33];
    const int e  = blockIdx.z;
    const int k0 = blockIdx.x * 32, n0 = blockIdx.y * 32;
    const int tid = threadIdx.x;
    const float* We = W + (size_t)e * K * N;
    for (int i = tid; i < 1024; i += 256) {
        int r = i >> 5, c = i & 31;
        t[r][c] = We[(size_t)(k0 + r) * N + n0 + c];
    }
    __syncthreads();
    size_t base = (size_t)e * N * K;
    for (int i = tid; i < 1024; i += 256) {
        int nn = i >> 5, kk = i & 31;
        float v = t[kk][nn];
        bf16 h = __float2bfloat16(v);
        bf16 l = __float2bfloat16(v - __bfloat162float(h));
        Th[base + (size_t)(n0 + nn) * K + k0 + kk] = h;
        Tl[base + (size_t)(n0 + nn) * K + k0 + kk] = l;
    }
}

// ---------------------------------------------------------------------------
// Fused expert tower: L1 -> LN -> L2 -> LN -> L3 -> LN, all on-chip.
// Block: 64 rows. 8 warps: warp_m = wid&3 (16 rows each), warp_n = wid>>2.
// ---------------------------------------------------------------------------
struct SmemT {
    bf16  sB[2][2][256][40];   // 80 KB  (double-buffered weight tiles, hi/lo)
    bf16  sX[2][2][64][40];    // 20 KB  (double-buffered x tiles, hi/lo)
    bf16  sH[2][64][264];      // 66 KB  (persistent activation tile, hi/lo)
    float red[2][64][2];       //  1 KB  (cross-warp LN partials)
};

__global__ void __launch_bounds__(256, 1)
expert_fused(const bf16* __restrict__ xhi, const bf16* __restrict__ xlo,
             const bf16* __restrict__ w1th, const bf16* __restrict__ w1tl,
             const bf16* __restrict__ w2th, const bf16* __restrict__ w2tl,
             const bf16* __restrict__ w3th, const bf16* __restrict__ w3tl,
             const float* __restrict__ eb1, const float* __restrict__ eg1, const float* __restrict__ ebt1,
             const float* __restrict__ eb2, const float* __restrict__ eg2, const float* __restrict__ ebt2,
             const float* __restrict__ eb3, const float* __restrict__ eg3, const float* __restrict__ ebt3,
             float* __restrict__ eo)
{
    extern __shared__ char raw[];
    SmemT& sm = *reinterpret_cast<SmemT*>(raw);

    const int e   = blockIdx.x;
    const int b0  = blockIdx.y * 64;
    const int tid = threadIdx.x;
    const int wid = tid >> 5, lane = tid & 31;
    const int warp_m = wid & 3, warp_n = wid >> 2;
    const int gr = lane >> 2, tg = lane & 3;
    const int ar = warp_m * 16 + gr;

    const bf16* W1h = w1th + (size_t)e * H * D;
    const bf16* W1l = w1tl + (size_t)e * H * D;
    const bf16* W2h = w2th + (size_t)e * H * H;
    const bf16* W2l = w2tl + (size_t)e * H * H;
    const bf16* W3h = w3th + (size_t)e * OO * H;
    const bf16* W3l = w3tl + (size_t)e * OO * H;

    // ---- tile load lambdas (cp.async 16B) ----
    auto loadB = [&](const bf16* Th, const bf16* Tl, int rows, int K, int buf, int k0) {
        for (int i = tid; i < rows * 4; i += 256) {
            int n = i >> 2, c = i & 3;
            cp16(&sm.sB[buf][0][n][c * 8], Th + (size_t)n * K + k0 + c * 8);
            cp16(&sm.sB[buf][1][n][c * 8], Tl + (size_t)n * K + k0 + c * 8);
        }
    };
    auto loadX = [&](int buf, int k0) {
        int r = tid >> 2, c = tid & 3;    // 64 rows x 4 chunks = 256 threads
        cp16(&sm.sX[buf][0][r][c * 8], xhi + (size_t)(b0 + r) * D + k0 + c * 8);
        cp16(&sm.sX[buf][1][r][c * 8], xlo + (size_t)(b0 + r) * D + k0 + c * 8);
    };

    float acc[16][4];

    // =================== Layer 1: x[64,512] @ W1 -> [64,256] ===================
#pragma unroll
    for (int nt = 0; nt < 16; nt++)
#pragma unroll
        for (int j = 0; j < 4; j++) acc[nt][j] = 0.f;

    int buf = 0;
    loadX(0, 0);
    loadB(W1h, W1l, 256, D, 0, 0);
    cp_commit();

    for (int ks = 0; ks < 16; ks++) {
        if (ks < 15) { loadX(buf ^ 1, (ks + 1) * 32); loadB(W1h, W1l, 256, D, buf ^ 1, (ks + 1) * 32); }
        cp_commit();
        cp_wait<1>(); __syncthreads();
#pragma unroll
        for (int ksub = 0; ksub < 2; ksub++) {
            const int koff = ksub * 16 + tg * 2;
            unsigned ah[4], al[4];
            load_afrag(ah, &sm.sX[buf][0][0][0], 40, ar, koff);
            load_afrag(al, &sm.sX[buf][1][0][0], 40, ar, koff);
#pragma unroll
            for (int nt = 0; nt < 16; nt++) {
                int bc = warp_n * 128 + nt * 8 + gr;
                unsigned bh[2], bl[2];
                load_bfrag(bh, &sm.sB[buf][0][0][0], 40, bc, koff);
                load_bfrag(bl, &sm.sB[buf][1][0][0], 40, bc, koff);
                mma_bf16(acc[nt], ah, bh);
                mma_bf16(acc[nt], ah, bl);
                mma_bf16(acc[nt], al, bh);
            }
        }
        __syncthreads();
        buf ^= 1;
    }
    // prefetch L2's first weight tile during epilogue (buf == 0 here)
    loadB(W2h, W2l, 256, H, 0, 0);
    cp_commit();

    // ---- epilogue 1: bias + LN + affine + relu -> sH ----
    {
        const float* be  = eb1  + (size_t)e * H;
        const float* ge  = eg1  + (size_t)e * H;
        const float* bte = ebt1 + (size_t)e * H;
        const int cbase = warp_n * 128 + tg * 2;
        float s0 = 0.f, q0 = 0.f, s1 = 0.f, q1 = 0.f;
#pragma unroll
        for (int nt = 0; nt < 16; nt++) {
            int c = cbase + nt * 8;
            float bv0 = be[c], bv1 = be[c + 1];
            acc[nt][0] += bv0; acc[nt][1] += bv1;
            acc[nt][2] += bv0; acc[nt][3] += bv1;
            s0 += acc[nt][0] + acc[nt][1];
            q0 = fmaf(acc[nt][0], acc[nt][0], fmaf(acc[nt][1], acc[nt][1], q0));
            s1 += acc[nt][2] + acc[nt][3];
            q1 = fmaf(acc[nt][2], acc[nt][2], fmaf(acc[nt][3], acc[nt][3], q1));
        }
#pragma unroll
        for (int off = 1; off <= 2; off <<= 1) {
            s0 += __shfl_xor_sync(0xffffffffu, s0, off);
            q0 += __shfl_xor_sync(0xffffffffu, q0, off);
            s1 += __shfl_xor_sync(0xffffffffu, s1, off);
            q1 += __shfl_xor_sync(0xffffffffu, q1, off);
        }
        __syncthreads();
        if (tg == 0) {
            sm.red[warp_n][ar][0] = s0;     sm.red[warp_n][ar][1] = q0;
            sm.red[warp_n][ar + 8][0] = s1; sm.red[warp_n][ar + 8][1] = q1;
        }
        __syncthreads();
        s0 = sm.red[0][ar][0] + sm.red[1][ar][0];
        q0 = sm.red[0][ar][1] + sm.red[1][ar][1];
        s1 = sm.red[0][ar + 8][0] + sm.red[1][ar + 8][0];
        q1 = sm.red[0][ar + 8][1] + sm.red[1][ar + 8][1];
        const float invN = 1.0f / H;
        float m0 = s0 * invN, m1 = s1 * invN;
        float r0 = rsqrtf(q0 * invN - m0 * m0 + 1e-5f);
        float r1 = rsqrtf(q1 * invN - m1 * m1 + 1e-5f);
#pragma unroll
        for (int nt = 0; nt < 16; nt++) {
            int c = cbase + nt * 8;
            float g0 = ge[c], g1 = ge[c + 1], t0 = bte[c], t1 = bte[c + 1];
            float v00 = fmaxf((acc[nt][0] - m0) * r0 * g0 + t0, 0.f);
            float v01 = fmaxf((acc[nt][1] - m0) * r0 * g1 + t1, 0.f);
            float v10 = fmaxf((acc[nt][2] - m1) * r1 * g0 + t0, 0.f);
            float v11 = fmaxf((acc[nt][3] - m1) * r1 * g1 + t1, 0.f);
            bf16 h00 = __float2bfloat16(v00), h01 = __float2bfloat16(v01);
            bf16 h10 = __float2bfloat16(v10), h11 = __float2bfloat16(v11);
            *(unsigned*)&sm.sH[0][ar][c]     = pack_bf16(h00, h01);
            *(unsigned*)&sm.sH[0][ar + 8][c] = pack_bf16(h10, h11);
            *(unsigned*)&sm.sH[1][ar][c]     = pack_bf16(__float2bfloat16(v00 - __bfloat162float(h00)),
                                                         __float2bfloat16(v01 - __bfloat162float(h01)));
            *(unsigned*)&sm.sH[1][ar + 8][c] = pack_bf16(__float2bfloat16(v10 - __bfloat162float(h10)),
                                                         __float2bfloat16(v11 - __bfloat162float(h11)));
        }
    }

    // =================== Layer 2: sH[64,256] @ W2 -> [64,256] ===================
#pragma unroll
    for (int nt = 0; nt < 16; nt++)
#pragma unroll
        for (int j = 0; j < 4; j++) acc[nt][j] = 0.f;

    buf = 0;
    for (int ks = 0; ks < 8; ks++) {
        if (ks < 7) loadB(W2h, W2l, 256, H, buf ^ 1, (ks + 1) * 32);
        cp_commit();
        cp_wait<1>(); __syncthreads();
#pragma unroll
        for (int ksub = 0; ksub < 2; ksub++) {
            const int koffA = ks * 32 + ksub * 16 + tg * 2;
            const int koffB = ksub * 16 + tg * 2;
            unsigned ah[4], al[4];
            load_afrag(ah, &sm.sH[0][0][0], 264, ar, koffA);
            load_afrag(al, &sm.sH[1][0][0], 264, ar, koffA);
#pragma unroll
            for (int nt = 0; nt < 16; nt++) {
                int bc = warp_n * 128 + nt * 8 + gr;
                unsigned bh[2], bl[2];
                load_bfrag(bh, &sm.sB[buf][0][0][0], 40, bc, koffB);
                load_bfrag(bl, &sm.sB[buf][1][0][0], 40, bc, koffB);
                mma_bf16(acc[nt], ah, bh);
                mma_bf16(acc[nt], ah, bl);
                mma_bf16(acc[nt], al, bh);
            }
        }
        __syncthreads();
        buf ^= 1;
    }
    // prefetch L3's first weight tile (buf == 0)
    loadB(W3h, W3l, 128, H, 0, 0);
    cp_commit();

    // ---- epilogue 2 -> sH (overwrite) ----
    {
        const float* be  = eb2  + (size_t)e * H;
        const float* ge  = eg2  + (size_t)e * H;
        const float* bte = ebt2 + (size_t)e * H;
        const int cbase = warp_n * 128 + tg * 2;
        float s0 = 0.f, q0 = 0.f, s1 = 0.f, q1 = 0.f;
#pragma unroll
        for (int nt = 0; nt < 16; nt++) {
            int c = cbase + nt * 8;
            float bv0 = be[c], bv1 = be[c + 1];
            acc[nt][0] += bv0; acc[nt][1] += bv1;
            acc[nt][2] += bv0; acc[nt][3] += bv1;
            s0 += acc[nt][0] + acc[nt][1];
            q0 = fmaf(acc[nt][0], acc[nt][0], fmaf(acc[nt][1], acc[nt][1], q0));
            s1 += acc[nt][2] + acc[nt][3];
            q1 = fmaf(acc[nt][2], acc[nt][2], fmaf(acc[nt][3], acc[nt][3], q1));
        }
#pragma unroll
        for (int off = 1; off <= 2; off <<= 1) {
            s0 += __shfl_xor_sync(0xffffffffu, s0, off);
            q0 += __shfl_xor_sync(0xffffffffu, q0, off);
            s1 += __shfl_xor_sync(0xffffffffu, s1, off);
            q1 += __shfl_xor_sync(0xffffffffu, q1, off);
        }
        __syncthreads();
        if (tg == 0) {
            sm.red[warp_n][ar][0] = s0;     sm.red[warp_n][ar][1] = q0;
            sm.red[warp_n][ar + 8][0] = s1; sm.red[warp_n][ar + 8][1] = q1;
        }
        __syncthreads();
        s0 = sm.red[0][ar][0] + sm.red[1][ar][0];
        q0 = sm.red[0][ar][1] + sm.red[1][ar][1];
        s1 = sm.red[0][ar + 8][0] + sm.red[1][ar + 8][0];
        q1 = sm.red[0][ar + 8][1] + sm.red[1][ar + 8][1];
        const float invN = 1.0f / H;
        float m0 = s0 * invN, m1 = s1 * invN;
        float r0 = rsqrtf(q0 * invN - m0 * m0 + 1e-5f);
        float r1 = rsqrtf(q1 * invN - m1 * m1 + 1e-5f);
        __syncthreads();   // all L2 reads of sH done (loop ended with sync), safe to overwrite
#pragma unroll
        for (int nt = 0; nt < 16; nt++) {
            int c = cbase + nt * 8;
            float g0 = ge[c], g1 = ge[c + 1], t0 = bte[c], t1 = bte[c + 1];
            float v00 = fmaxf((acc[nt][0] - m0) * r0 * g0 + t0, 0.f);
            float v01 = fmaxf((acc[nt][1] - m0) * r0 * g1 + t1, 0.f);
            float v10 = fmaxf((acc[nt][2] - m1) * r1 * g0 + t0, 0.f);
            float v11 = fmaxf((acc[nt][3] - m1) * r1 * g1 + t1, 0.f);
            bf16 h00 = __float2bfloat16(v00), h01 = __float2bfloat16(v01);
            bf16 h10 = __float2bfloat16(v10), h11 = __float2bfloat16(v11);
            *(unsigned*)&sm.sH[0][ar][c]     = pack_bf16(h00, h01);
            *(unsigned*)&sm.sH[0][ar + 8][c] = pack_bf16(h10, h11);
            *(unsigned*)&sm.sH[1][ar][c]     = pack_bf16(__float2bfloat16(v00 - __bfloat162float(h00)),
                                                         __float2bfloat16(v01 - __bfloat162float(h01)));
            *(unsigned*)&sm.sH[1][ar + 8][c] = pack_bf16(__float2bfloat16(v10 - __bfloat162float(h10)),
                                                         __float2bfloat16(v11 - __bfloat162float(h11)));
        }
    }

    // =================== Layer 3: sH[64,256] @ W3 -> [64,128] ===================
#pragma unroll
    for (int nt = 0; nt < 8; nt++)
#pragma unroll
        for (int j = 0; j < 4; j++) acc[nt][j] = 0.f;

    buf = 0;
    for (int ks = 0; ks < 8; ks++) {
        if (ks < 7) loadB(W3h, W3l, 128, H, buf ^ 1, (ks + 1) * 32);
        cp_commit();
        cp_wait<1>(); __syncthreads();
#pragma unroll
        for (int ksub = 0; ksub < 2; ksub++) {
            const int koffA = ks * 32 + ksub * 16 + tg * 2;
            const int koffB = ksub * 16 + tg * 2;
            unsigned ah[4], al[4];
            load_afrag(ah, &sm.sH[0][0][0], 264, ar, koffA);
            load_afrag(al, &sm.sH[1][0][0], 264, ar, koffA);
#pragma unroll
            for (int nt = 0; nt < 8; nt++) {
                int bc = warp_n * 64 + nt * 8 + gr;
                unsigned bh[2], bl[2];
                load_bfrag(bh, &sm.sB[buf][0][0][0], 40, bc, koffB);
                load_bfrag(bl, &sm.sB[buf][1][0][0], 40, bc, koffB);
                mma_bf16(acc[nt], ah, bh);
                mma_bf16(acc[nt], ah, bl);
                mma_bf16(acc[nt], al, bh);
            }
        }
        __syncthreads();
        buf ^= 1;
    }

    // ---- epilogue 3: bias + LN + affine + relu -> eo (fp32 global) ----
    {
        const float* be  = eb3  + (size_t)e * OO;
        const float* ge  = eg3  + (size_t)e * OO;
        const float* bte = ebt3 + (size_t)e * OO;
        const int cbase = warp_n * 64 + tg * 2;
        float s0 = 0.f, q0 = 0.f, s1 = 0.f, q1 = 0.f;
#pragma unroll
        for (int nt = 0; nt < 8; nt++) {
            int c = cbase + nt * 8;
            float bv0 = be[c], bv1 = be[c + 1];
            acc[nt][0] += bv0; acc[nt][1] += bv1;
            acc[nt][2] += bv0; acc[nt][3] += bv1;
            s0 += acc[nt][0] + acc[nt][1];
            q0 = fmaf(acc[nt][0], acc[nt][0], fmaf(acc[nt][1], acc[nt][1], q0));
            s1 += acc[nt][2] + acc[nt][3];
            q1 = fmaf(acc[nt][2], acc[nt][2], fmaf(acc[nt][3], acc[nt][3], q1));
        }
#pragma unroll
        for (int off = 1; off <= 2; off <<= 1) {
            s0 += __shfl_xor_sync(0xffffffffu, s0, off);
            q0 += __shfl_xor_sync(0xffffffffu, q0, off);
            s1 += __shfl_xor_sync(0xffffffffu, s1, off);
            q1 += __shfl_xor_sync(0xffffffffu, q1, off);
        }
        __syncthreads();
        if (tg == 0) {
            sm.red[warp_n][ar][0] = s0;     sm.red[warp_n][ar][1] = q0;
            sm.red[warp_n][ar + 8][0] = s1; sm.red[warp_n][ar + 8][1] = q1;
        }
        __syncthreads();
        s0 = sm.red[0][ar][0] + sm.red[1][ar][0];
        q0 = sm.red[0][ar][1] + sm.red[1][ar][1];
        s1 = sm.red[0][ar + 8][0] + sm.red[1][ar + 8][0];
        q1 = sm.red[0][ar + 8][1] + sm.red[1][ar + 8][1];
        const float invN = 1.0f / OO;
        float m0 = s0 * invN, m1 = s1 * invN;
        float r0 = rsqrtf(q0 * invN - m0 * m0 + 1e-5f);
        float r1 = rsqrtf(q1 * invN - m1 * m1 + 1e-5f);
        size_t row0 = ((size_t)e * B + b0 + ar) * OO;
        size_t row1 = row0 + (size_t)8 * OO;
#pragma unroll
        for (int nt = 0; nt < 8; nt++) {
            int c = cbase + nt * 8;
            float g0 = ge[c], g1 = ge[c + 1], t0 = bte[c], t1 = bte[c + 1];
            float v00 = fmaxf((acc[nt][0] - m0) * r0 * g0 + t0, 0.f);
            float v01 = fmaxf((acc[nt][1] - m0) * r0 * g1 + t1, 0.f);
            float v10 = fmaxf((acc[nt][2] - m1) * r1 * g0 + t0, 0.f);
            float v11 = fmaxf((acc[nt][3] - m1) * r1 * g1 + t1, 0.f);
            *(float2*)&eo[row0 + c] = make_float2(v00, v01);
            *(float2*)&eo[row1 + c] = make_float2(v10, v11);
        }
    }
}

// ---------------------------------------------------------------------------
// Gate: relu(x@W1+b1) on tensor cores, then tiny GEMM + softmax in smem.
// ---------------------------------------------------------------------------
template <int NOUT>
__global__ void __launch_bounds__(256)
gate_mma(const bf16* __restrict__ xhi, const bf16* __restrict__ xlo,
         const bf16* __restrict__ w1hi, const bf16* __restrict__ w1lo, size_t w1stride,
         const float* __restrict__ b1, size_t b1stride,
         const float* __restrict__ w2, size_t w2stride,
         const float* __restrict__ b2, size_t b2stride,
         float* __restrict__ out, size_t outstride)
{
    constexpr int BM = 128, K = D, N = G_, NTI = N / 8;
    constexpr int NTHREADS = 256;

    __shared__ bf16 sAh[BM][16], sAl[BM][16];
    __shared__ bf16 sBh[N][18],  sBl[N][18];
    __shared__ float ghs[BM][G_ + 1];
    __shared__ float ws2[G_][NOUT];
    __shared__ float b2s[NOUT];

    const int t   = blockIdx.y;
    const int b0  = blockIdx.x * BM;
    const int tid = threadIdx.x;
    const int wid = tid >> 5, lane = tid & 31;
    const int gr = lane >> 2, tg = lane & 3;
    const int ar = wid * 16 + gr;

    const bf16* W1h = w1hi + (size_t)t * w1stride;
    const bf16* W1l = w1lo + (size_t)t * w1stride;
    const float* b1t = b1 + (size_t)t * b1stride;
    const float* w2t = w2 + (size_t)t * w2stride;
    const float* b2t = b2 + (size_t)t * b2stride;
    float* outt = out + (size_t)t * outstride;

    for (int i = tid; i < G_ * NOUT; i += NTHREADS) ws2[i / NOUT][i % NOUT] = w2t[i];
    if (tid < NOUT) b2s[tid] = b2t[tid];

    float acc[NTI][4];
#pragma unroll
    for (int nt = 0; nt < NTI; nt++)
#pragma unroll
        for (int j = 0; j < 4; j++) acc[nt][j] = 0.f;

    for (int k0 = 0; k0 < K; k0 += 16) {
        __syncthreads();
#pragma unroll
        for (int i = tid * 4; i < BM * 16; i += NTHREADS * 4) {
            int r = i >> 4, kk = i & 15;
            *(uint2*)&sAh[r][kk] = *(const uint2*)&xhi[(size_t)(b0 + r) * K + k0 + kk];
            *(uint2*)&sAl[r][kk] = *(const uint2*)&xlo[(size_t)(b0 + r) * K + k0 + kk];
        }
#pragma unroll
        for (int i = tid; i < 16 * (N / 2); i += NTHREADS) {
            int kk = i / (N / 2), cp = i % (N / 2);
            unsigned vh = *(const unsigned*)&W1h[(size_t)(k0 + kk) * N + cp * 2];
            unsigned vl = *(const unsigned*)&W1l[(size_t)(k0 + kk) * N + cp * 2];
            sBh[cp * 2    ][kk] = __ushort_as_bfloat16((unsigned short)(vh & 0xffff));
            sBh[cp * 2 + 1][kk] = __ushort_as_bfloat16((unsigned short)(vh >> 16));
            sBl[cp * 2    ][kk] = __ushort_as_bfloat16((unsigned short)(vl & 0xffff));
            sBl[cp * 2 + 1][kk] = __ushort_as_bfloat16((unsigned short)(vl >> 16));
        }
        __syncthreads();

        unsigned ah[4], al[4];
        load_afrag(ah, &sAh[0][0], 16, ar, tg * 2);
        load_afrag(al, &sAl[0][0], 16, ar, tg * 2);

#pragma unroll
        for (int nt = 0; nt < NTI; nt++) {
            int bc = nt * 8 + gr;
            unsigned bh[2], bl[2];
            load_bfrag(bh, &sBh[0][0], 18, bc, tg * 2);
            load_bfrag(bl, &sBl[0][0], 18, bc, tg * 2);
            mma_bf16(acc[nt], ah, bh);
            mma_bf16(acc[nt], ah, bl);
            mma_bf16(acc[nt], al, bh);
        }
    }
    __syncthreads();

#pragma unroll
    for (int nt = 0; nt < NTI; nt++) {
        int c = nt * 8 + tg * 2;
        float bv0 = b1t[c], bv1 = b1t[c + 1];
        ghs[ar    ][c]     = fmaxf(acc[nt][0] + bv0, 0.f);
        ghs[ar    ][c + 1] = fmaxf(acc[nt][1] + bv1, 0.f);
        ghs[ar + 8][c]     = fmaxf(acc[nt][2] + bv0, 0.f);
        ghs[ar + 8][c + 1] = fmaxf(acc[nt][3] + bv1, 0.f);
    }
    __syncthreads();

    if (tid < BM) {
        float lg[NOUT];
#pragma unroll
        for (int j = 0; j < NOUT; j++) lg[j] = b2s[j];
        for (int k = 0; k < G_; k++) {
            float g = ghs[tid][k];
#pragma unroll
            for (int j = 0; j < NOUT; j++) lg[j] = fmaf(g, ws2[k][j], lg[j]);
        }
        float mx = -1e30f;
#pragma unroll
        for (int j = 0; j < NOUT; j++) mx = fmaxf(mx, lg[j]);
        float sum = 0.f;
#pragma unroll
        for (int j = 0; j < NOUT; j++) { lg[j] = __expf(lg[j] - mx); sum += lg[j]; }
        float inv = 1.0f / sum;
#pragma unroll
        for (int j = 0; j < NOUT; j++)
            outt[(size_t)(b0 + tid) * NOUT + j] = lg[j] * inv;
    }
}

// ---------------------------------------------------------------------------
// Combine
// ---------------------------------------------------------------------------
__global__ void __launch_bounds__(256)
combine_kernel(const float* __restrict__ eo,  // [E][B][O]
               const float* __restrict__ gw,  // [T][B][NE]
               const float* __restrict__ sgw, // [B][E]
               float* __restrict__ out)       // [4][B][O]
{
    const int b = blockIdx.x * 2 + (threadIdx.x >> 7);
    const int o = threadIdx.x & 127;

    float v[E_];
#pragma unroll
    for (int e = 0; e < E_; e++)
        v[e] = eo[((size_t)e * B + b) * OO + o];

#pragma unroll
    for (int t = 0; t < T_; t++) {
        const float* g = gw + ((size_t)t * B + b) * NE;
        float s = 0.f;
#pragma unroll
        for (int j = 0; j < NS; j++) s += g[j] * v[j];
#pragma unroll
        for (int n = 0; n < NT_TASK; n++) s += g[NS + n] * v[NS + t * NT_TASK + n];
        out[((size_t)t * B + b) * OO + o] = s;
    }

    const float* sg = sgw + (size_t)b * E_;
    float s = 0.f;
#pragma unroll
    for (int e = 0; e < E_; e++) s += sg[e] * v[e];
    out[((size_t)3 * B + b) * OO + o] = s;
}

// ---------------------------------------------------------------------------
extern "C" void kernel_launch(void* const* d_in, const int* in_sizes, int n_in,
                              void* d_out, int out_size)
{
    const float* x     = (const float*)d_in[0];
    const float* ew1   = (const float*)d_in[1];
    const float* eb1   = (const float*)d_in[2];
    const float* eg1   = (const float*)d_in[3];
    const float* ebt1  = (const float*)d_in[4];
    const float* ew2   = (const float*)d_in[5];
    const float* eb2   = (const float*)d_in[6];
    const float* eg2   = (const float*)d_in[7];
    const float* ebt2  = (const float*)d_in[8];
    const float* ew3   = (const float*)d_in[9];
    const float* eb3   = (const float*)d_in[10];
    const float* eg3   = (const float*)d_in[11];
    const float* ebt3  = (const float*)d_in[12];
    const float* tg_w1 = (const float*)d_in[13];
    const float* tg_b1 = (const float*)d_in[14];
    const float* tg_w2 = (const float*)d_in[15];
    const float* tg_b2 = (const float*)d_in[16];
    const float* sg_w1 = (const float*)d_in[17];
    const float* sg_b1 = (const float*)d_in[18];
    const float* sg_w2 = (const float*)d_in[19];
    const float* sg_b2 = (const float*)d_in[20];
    float* out = (float*)d_out;

    static bf16 *xhi = nullptr, *xlo;
    static bf16 *w1th, *w1tl, *w2th, *w2tl, *w3th, *w3tl;
    static bf16 *tgw1hi, *tgw1lo, *sgw1hi, *sgw1lo;
    static float *eo, *gw, *sgw;
    if (!xhi) {
        cudaGetSymbolAddress((void**)&xhi, g_xhi);   cudaGetSymbolAddress((void**)&xlo, g_xlo);
        cudaGetSymbolAddress((void**)&w1th, g_w1th); cudaGetSymbolAddress((void**)&w1tl, g_w1tl);
        cudaGetSymbolAddress((void**)&w2th, g_w2th); cudaGetSymbolAddress((void**)&w2tl, g_w2tl);
        cudaGetSymbolAddress((void**)&w3th, g_w3th); cudaGetSymbolAddress((void**)&w3tl, g_w3tl);
        cudaGetSymbolAddress((void**)&tgw1hi, g_tgw1hi); cudaGetSymbolAddress((void**)&tgw1lo, g_tgw1lo);
        cudaGetSymbolAddress((void**)&sgw1hi, g_sgw1hi); cudaGetSymbolAddress((void**)&sgw1lo, g_sgw1lo);
        cudaGetSymbolAddress((void**)&eo, g_eo);
        cudaGetSymbolAddress((void**)&gw, g_gw);
        cudaGetSymbolAddress((void**)&sgw, g_sgw);
        cudaFuncSetAttribute(expert_fused, cudaFuncAttributeMaxDynamicSharedMemorySize,
                             (int)sizeof(SmemT));
    }

    // ---- prep: splits + weight transposes ----
    auto launch_split = [](const float* src, bf16* hi, bf16* lo, size_t n) {
        int n4 = (int)(n / 4);
        split_hi_lo<<<(n4 + 255) / 256, 256>>>((const float4*)src, (unsigned*)hi, (unsigned*)lo, n4);
    };
    launch_split(x,     xhi,    xlo,    (size_t)B * D);
    launch_split(tg_w1, tgw1hi, tgw1lo, (size_t)T_ * D * G_);
    launch_split(sg_w1, sgw1hi, sgw1lo, (size_t)D * G_);

    transpose_split<<<dim3(D / 32, H / 32, E_), 256>>>(ew1, w1th, w1tl, D, H);
    transpose_split<<<dim3(H / 32, H / 32, E_), 256>>>(ew2, w2th, w2tl, H, H);
    transpose_split<<<dim3(H / 32, OO / 32, E_), 256>>>(ew3, w3th, w3tl, H, OO);

    // ---- fused expert tower ----
    expert_fused<<<dim3(E_, B / 64), 256, sizeof(SmemT)>>>(
        xhi, xlo, w1th, w1tl, w2th, w2tl, w3th, w3tl,
        eb1, eg1, ebt1, eb2, eg2, ebt2, eb3, eg3, ebt3, eo);

    // ---- gates ----
    gate_mma<NE><<<dim3(B / 128, T_), 256>>>(
        xhi, xlo, tgw1hi, tgw1lo, (size_t)D * G_,
        tg_b1, (size_t)G_, tg_w2, (size_t)G_ * NE, tg_b2, (size_t)NE,
        gw, (size_t)B * NE);
    gate_mma<E_><<<dim3(B / 128, 1), 256>>>(
        xhi, xlo, sgw1hi, sgw1lo, (size_t)0,
        sg_b1, (size_t)0, sg_w2, (size_t)0, sg_b2, (size_t)0,
        sgw, (size_t)0);

    // ---- final mixture ----
    combine_kernel<<<B / 2, 256>>>(eo, gw, sgw, out);
}

// round 6
// speedup vs baseline: 4.6741x; 2.2113x over previous
#include <cuda_runtime.h>
#include <cuda_fp16.h>
#include <math.h>
#include <stdint.h>

#define B  32768
#define D  512
#define H  256
#define OO 128
#define E_ 10
#define T_ 3
#define G_ 64
#define NS 4
#define NT_TASK 2
#define NE (NS + NT_TASK)

typedef __half h16;

// ---------------- scratch (allocation-free) ----------------
__device__ h16   g_xh[(size_t)B * D];
__device__ h16   g_w1t[(size_t)E_ * H * D];    // [E][N=256][K=512] fp16
__device__ h16   g_w2t[(size_t)E_ * H * H];    // [E][256][256]
__device__ h16   g_w3t[(size_t)E_ * OO * H];   // [E][128][256]
__device__ h16   g_tgw1[(size_t)T_ * D * G_];
__device__ h16   g_sgw1[(size_t)D * G_];
__device__ float g_eo[(size_t)E_ * B * OO];
__device__ float g_gw[(size_t)T_ * B * NE];
__device__ float g_sgw[(size_t)B * E_];

// ---------------- helpers ----------------
__device__ __forceinline__ void mma_fp16(float* c, const unsigned* a, const unsigned* b) {
    asm volatile(
        "mma.sync.aligned.m16n8k16.row.col.f32.f16.f16.f32 "
        "{%0,%1,%2,%3}, {%4,%5,%6,%7}, {%8,%9}, {%0,%1,%2,%3};\n"
        : "+f"(c[0]), "+f"(c[1]), "+f"(c[2]), "+f"(c[3])
        : "r"(a[0]), "r"(a[1]), "r"(a[2]), "r"(a[3]), "r"(b[0]), "r"(b[1]));
}
__device__ __forceinline__ unsigned pack_h2(h16 a, h16 b) {
    return (unsigned)__half_as_ushort(a) | ((unsigned)__half_as_ushort(b) << 16);
}
__device__ __forceinline__ void cp16(void* s, const void* g) {
    unsigned sa = (unsigned)__cvta_generic_to_shared(s);
    asm volatile("cp.async.cg.shared.global [%0], [%1], 16;\n" :: "r"(sa), "l"(g));
}
__device__ __forceinline__ void cp_commit() { asm volatile("cp.async.commit_group;\n"); }
template <int N2> __device__ __forceinline__ void cp_wait() {
    asm volatile("cp.async.wait_group %0;\n" :: "n"(N2));
}
__device__ __forceinline__ void load_afrag(unsigned* a, const h16* base, int stride, int r, int koff) {
    a[0] = *(const unsigned*)(base + (size_t)r * stride + koff);
    a[1] = *(const unsigned*)(base + (size_t)(r + 8) * stride + koff);
    a[2] = *(const unsigned*)(base + (size_t)r * stride + koff + 8);
    a[3] = *(const unsigned*)(base + (size_t)(r + 8) * stride + koff + 8);
}
__device__ __forceinline__ void load_bfrag(unsigned* b, const h16* base, int stride, int n, int koff) {
    b[0] = *(const unsigned*)(base + (size_t)n * stride + koff);
    b[1] = *(const unsigned*)(base + (size_t)n * stride + koff + 8);
}

// ---------------- prep kernels ----------------
__global__ void to_half(const float4* __restrict__ src, unsigned* __restrict__ dst2, int n4)
{
    int i = blockIdx.x * blockDim.x + threadIdx.x;
    if (i >= n4) return;
    float4 v = src[i];
    dst2[i * 2]     = pack_h2(__float2half_rn(v.x), __float2half_rn(v.y));
    dst2[i * 2 + 1] = pack_h2(__float2half_rn(v.z), __float2half_rn(v.w));
}

// W [E][K][N] fp32 -> T [E][N][K] fp16
__global__ void transpose_half(const float* __restrict__ W, h16* __restrict__ T, int K, int N)
{
    __shared__ float t[32][33];
    const int e  = blockIdx.z;
    const int k0 = blockIdx.x * 32, n0 = blockIdx.y * 32;
    const int tid = threadIdx.x;
    const float* We = W + (size_t)e * K * N;
    for (int i = tid; i < 1024; i += 256) {
        int r = i >> 5, c = i & 31;
        t[r][c] = We[(size_t)(k0 + r) * N + n0 + c];
    }
    __syncthreads();
    size_t base = (size_t)e * N * K;
    for (int i = tid; i < 1024; i += 256) {
        int nn = i >> 5, kk = i & 31;
        T[base + (size_t)(n0 + nn) * K + k0 + kk] = __float2half_rn(t[kk][nn]);
    }
}

// ---------------------------------------------------------------------------
// Fused expert tower (single-pass fp16): L1 -> LN -> L2 -> LN -> L3 -> LN.
// Block: 64 rows, 8 warps (4m x 2n), warp tile 16 x 128 (L3: 16 x 64).
// ---------------------------------------------------------------------------
struct SmemT {
    h16   sB[2][256][40];  // 40 KB  double-buffered weight tiles (k-chunk 32)
    h16   sX[2][64][40];   // 10 KB  double-buffered x tiles (L1 only)
    h16   sH[64][264];     // 33 KB  persistent activation tile
    float red[2][64][2];   //  1 KB  cross-warp LN partials
};

__global__ void __launch_bounds__(256, 2)
expert_fused(const h16* __restrict__ xh,
             const h16* __restrict__ w1t, const h16* __restrict__ w2t, const h16* __restrict__ w3t,
             const float* __restrict__ eb1, const float* __restrict__ eg1, const float* __restrict__ ebt1,
             const float* __restrict__ eb2, const float* __restrict__ eg2, const float* __restrict__ ebt2,
             const float* __restrict__ eb3, const float* __restrict__ eg3, const float* __restrict__ ebt3,
             float* __restrict__ eo)
{
    extern __shared__ char raw[];
    SmemT& sm = *reinterpret_cast<SmemT*>(raw);

    const int e   = blockIdx.x;
    const int b0  = blockIdx.y * 64;
    const int tid = threadIdx.x;
    const int wid = tid >> 5, lane = tid & 31;
    const int warp_m = wid & 3, warp_n = wid >> 2;
    const int gr = lane >> 2, tg = lane & 3;
    const int ar = warp_m * 16 + gr;

    const h16* W1 = w1t + (size_t)e * H * D;
    const h16* W2 = w2t + (size_t)e * H * H;
    const h16* W3 = w3t + (size_t)e * OO * H;

    auto loadB = [&](const h16* T, int rows, int K, int buf, int k0) {
        for (int i = tid; i < rows * 4; i += 256) {
            int n = i >> 2, c = i & 3;
            cp16(&sm.sB[buf][n][c * 8], T + (size_t)n * K + k0 + c * 8);
        }
    };
    auto loadX = [&](int buf, int k0) {
        int r = tid >> 2, c = tid & 3;
        cp16(&sm.sX[buf][r][c * 8], xh + (size_t)(b0 + r) * D + k0 + c * 8);
    };

    float acc[16][4];

    // =================== Layer 1: x[64,512] @ W1 -> [64,256] ===================
#pragma unroll
    for (int nt = 0; nt < 16; nt++)
#pragma unroll
        for (int j = 0; j < 4; j++) acc[nt][j] = 0.f;

    int buf = 0;
    loadX(0, 0);
    loadB(W1, 256, D, 0, 0);
    cp_commit();

    for (int ks = 0; ks < 16; ks++) {
        if (ks < 15) { loadX(buf ^ 1, (ks + 1) * 32); loadB(W1, 256, D, buf ^ 1, (ks + 1) * 32); }
        cp_commit();
        cp_wait<1>(); __syncthreads();
#pragma unroll
        for (int ksub = 0; ksub < 2; ksub++) {
            const int koff = ksub * 16 + tg * 2;
            unsigned ah[4];
            load_afrag(ah, &sm.sX[buf][0][0], 40, ar, koff);
#pragma unroll
            for (int nt = 0; nt < 16; nt++) {
                int bc = warp_n * 128 + nt * 8 + gr;
                unsigned bh[2];
                load_bfrag(bh, &sm.sB[buf][0][0], 40, bc, koff);
                mma_fp16(acc[nt], ah, bh);
            }
        }
        __syncthreads();
        buf ^= 1;
    }
    // prefetch L2's first weight tile during epilogue (buf == 0)
    loadB(W2, 256, H, 0, 0);
    cp_commit();

    // ---- epilogue 1: bias + LN + affine + relu -> sH (fp16) ----
    {
        const float* be  = eb1  + (size_t)e * H;
        const float* ge  = eg1  + (size_t)e * H;
        const float* bte = ebt1 + (size_t)e * H;
        const int cbase = warp_n * 128 + tg * 2;
        float s0 = 0.f, q0 = 0.f, s1 = 0.f, q1 = 0.f;
#pragma unroll
        for (int nt = 0; nt < 16; nt++) {
            int c = cbase + nt * 8;
            float bv0 = be[c], bv1 = be[c + 1];
            acc[nt][0] += bv0; acc[nt][1] += bv1;
            acc[nt][2] += bv0; acc[nt][3] += bv1;
            s0 += acc[nt][0] + acc[nt][1];
            q0 = fmaf(acc[nt][0], acc[nt][0], fmaf(acc[nt][1], acc[nt][1], q0));
            s1 += acc[nt][2] + acc[nt][3];
            q1 = fmaf(acc[nt][2], acc[nt][2], fmaf(acc[nt][3], acc[nt][3], q1));
        }
#pragma unroll
        for (int off = 1; off <= 2; off <<= 1) {
            s0 += __shfl_xor_sync(0xffffffffu, s0, off);
            q0 += __shfl_xor_sync(0xffffffffu, q0, off);
            s1 += __shfl_xor_sync(0xffffffffu, s1, off);
            q1 += __shfl_xor_sync(0xffffffffu, q1, off);
        }
        __syncthreads();
        if (tg == 0) {
            sm.red[warp_n][ar][0] = s0;     sm.red[warp_n][ar][1] = q0;
            sm.red[warp_n][ar + 8][0] = s1; sm.red[warp_n][ar + 8][1] = q1;
        }
        __syncthreads();
        s0 = sm.red[0][ar][0] + sm.red[1][ar][0];
        q0 = sm.red[0][ar][1] + sm.red[1][ar][1];
        s1 = sm.red[0][ar + 8][0] + sm.red[1][ar + 8][0];
        q1 = sm.red[0][ar + 8][1] + sm.red[1][ar + 8][1];
        const float invN = 1.0f / H;
        float m0 = s0 * invN, m1 = s1 * invN;
        float r0 = rsqrtf(q0 * invN - m0 * m0 + 1e-5f);
        float r1 = rsqrtf(q1 * invN - m1 * m1 + 1e-5f);
#pragma unroll
        for (int nt = 0; nt < 16; nt++) {
            int c = cbase + nt * 8;
            float g0 = ge[c], g1 = ge[c + 1], t0 = bte[c], t1 = bte[c + 1];
            float v00 = fmaxf((acc[nt][0] - m0) * r0 * g0 + t0, 0.f);
            float v01 = fmaxf((acc[nt][1] - m0) * r0 * g1 + t1, 0.f);
            float v10 = fmaxf((acc[nt][2] - m1) * r1 * g0 + t0, 0.f);
            float v11 = fmaxf((acc[nt][3] - m1) * r1 * g1 + t1, 0.f);
            *(unsigned*)&sm.sH[ar][c]     = pack_h2(__float2half_rn(v00), __float2half_rn(v01));
            *(unsigned*)&sm.sH[ar + 8][c] = pack_h2(__float2half_rn(v10), __float2half_rn(v11));
        }
    }

    // =================== Layer 2: sH[64,256] @ W2 -> [64,256] ===================
#pragma unroll
    for (int nt = 0; nt < 16; nt++)
#pragma unroll
        for (int j = 0; j < 4; j++) acc[nt][j] = 0.f;

    buf = 0;
    for (int ks = 0; ks < 8; ks++) {
        if (ks < 7) loadB(W2, 256, H, buf ^ 1, (ks + 1) * 32);
        cp_commit();
        cp_wait<1>(); __syncthreads();
#pragma unroll
        for (int ksub = 0; ksub < 2; ksub++) {
            const int koffA = ks * 32 + ksub * 16 + tg * 2;
            const int koffB = ksub * 16 + tg * 2;
            unsigned ah[4];
            load_afrag(ah, &sm.sH[0][0], 264, ar, koffA);
#pragma unroll
            for (int nt = 0; nt < 16; nt++) {
                int bc = warp_n * 128 + nt * 8 + gr;
                unsigned bh[2];
                load_bfrag(bh, &sm.sB[buf][0][0], 40, bc, koffB);
                mma_fp16(acc[nt], ah, bh);
            }
        }
        __syncthreads();
        buf ^= 1;
    }
    // prefetch L3's first weight tile (buf == 0)
    loadB(W3, 128, H, 0, 0);
    cp_commit();

    // ---- epilogue 2 -> sH (overwrite) ----
    {
        const float* be  = eb2  + (size_t)e * H;
        const float* ge  = eg2  + (size_t)e * H;
        const float* bte = ebt2 + (size_t)e * H;
        const int cbase = warp_n * 128 + tg * 2;
        float s0 = 0.f, q0 = 0.f, s1 = 0.f, q1 = 0.f;
#pragma unroll
        for (int nt = 0; nt < 16; nt++) {
            int c = cbase + nt * 8;
            float bv0 = be[c], bv1 = be[c + 1];
            acc[nt][0] += bv0; acc[nt][1] += bv1;
            acc[nt][2] += bv0; acc[nt][3] += bv1;
            s0 += acc[nt][0] + acc[nt][1];
            q0 = fmaf(acc[nt][0], acc[nt][0], fmaf(acc[nt][1], acc[nt][1], q0));
            s1 += acc[nt][2] + acc[nt][3];
            q1 = fmaf(acc[nt][2], acc[nt][2], fmaf(acc[nt][3], acc[nt][3], q1));
        }
#pragma unroll
        for (int off = 1; off <= 2; off <<= 1) {
            s0 += __shfl_xor_sync(0xffffffffu, s0, off);
            q0 += __shfl_xor_sync(0xffffffffu, q0, off);
            s1 += __shfl_xor_sync(0xffffffffu, s1, off);
            q1 += __shfl_xor_sync(0xffffffffu, q1, off);
        }
        __syncthreads();
        if (tg == 0) {
            sm.red[warp_n][ar][0] = s0;     sm.red[warp_n][ar][1] = q0;
            sm.red[warp_n][ar + 8][0] = s1; sm.red[warp_n][ar + 8][1] = q1;
        }
        __syncthreads();
        s0 = sm.red[0][ar][0] + sm.red[1][ar][0];
        q0 = sm.red[0][ar][1] + sm.red[1][ar][1];
        s1 = sm.red[0][ar + 8][0] + sm.red[1][ar + 8][0];
        q1 = sm.red[0][ar + 8][1] + sm.red[1][ar + 8][1];
        const float invN = 1.0f / H;
        float m0 = s0 * invN, m1 = s1 * invN;
        float r0 = rsqrtf(q0 * invN - m0 * m0 + 1e-5f);
        float r1 = rsqrtf(q1 * invN - m1 * m1 + 1e-5f);
        __syncthreads();   // all L2 reads of sH done
#pragma unroll
        for (int nt = 0; nt < 16; nt++) {
            int c = cbase + nt * 8;
            float g0 = ge[c], g1 = ge[c + 1], t0 = bte[c], t1 = bte[c + 1];
            float v00 = fmaxf((acc[nt][0] - m0) * r0 * g0 + t0, 0.f);
            float v01 = fmaxf((acc[nt][1] - m0) * r0 * g1 + t1, 0.f);
            float v10 = fmaxf((acc[nt][2] - m1) * r1 * g0 + t0, 0.f);
            float v11 = fmaxf((acc[nt][3] - m1) * r1 * g1 + t1, 0.f);
            *(unsigned*)&sm.sH[ar][c]     = pack_h2(__float2half_rn(v00), __float2half_rn(v01));
            *(unsigned*)&sm.sH[ar + 8][c] = pack_h2(__float2half_rn(v10), __float2half_rn(v11));
        }
    }

    // =================== Layer 3: sH[64,256] @ W3 -> [64,128] ===================
#pragma unroll
    for (int nt = 0; nt < 8; nt++)
#pragma unroll
        for (int j = 0; j < 4; j++) acc[nt][j] = 0.f;

    buf = 0;
    for (int ks = 0; ks < 8; ks++) {
        if (ks < 7) loadB(W3, 128, H, buf ^ 1, (ks + 1) * 32);
        cp_commit();
        cp_wait<1>(); __syncthreads();
#pragma unroll
        for (int ksub = 0; ksub < 2; ksub++) {
            const int koffA = ks * 32 + ksub * 16 + tg * 2;
            const int koffB = ksub * 16 + tg * 2;
            unsigned ah[4];
            load_afrag(ah, &sm.sH[0][0], 264, ar, koffA);
#pragma unroll
            for (int nt = 0; nt < 8; nt++) {
                int bc = warp_n * 64 + nt * 8 + gr;
                unsigned bh[2];
                load_bfrag(bh, &sm.sB[buf][0][0], 40, bc, koffB);
                mma_fp16(acc[nt], ah, bh);
            }
        }
        __syncthreads();
        buf ^= 1;
    }

    // ---- epilogue 3: bias + LN + affine + relu -> eo (fp32) ----
    {
        const float* be  = eb3  + (size_t)e * OO;
        const float* ge  = eg3  + (size_t)e * OO;
        const float* bte = ebt3 + (size_t)e * OO;
        const int cbase = warp_n * 64 + tg * 2;
        float s0 = 0.f, q0 = 0.f, s1 = 0.f, q1 = 0.f;
#pragma unroll
        for (int nt = 0; nt < 8; nt++) {
            int c = cbase + nt * 8;
            float bv0 = be[c], bv1 = be[c + 1];
            acc[nt][0] += bv0; acc[nt][1] += bv1;
            acc[nt][2] += bv0; acc[nt][3] += bv1;
            s0 += acc[nt][0] + acc[nt][1];
            q0 = fmaf(acc[nt][0], acc[nt][0], fmaf(acc[nt][1], acc[nt][1], q0));
            s1 += acc[nt][2] + acc[nt][3];
            q1 = fmaf(acc[nt][2], acc[nt][2], fmaf(acc[nt][3], acc[nt][3], q1));
        }
#pragma unroll
        for (int off = 1; off <= 2; off <<= 1) {
            s0 += __shfl_xor_sync(0xffffffffu, s0, off);
            q0 += __shfl_xor_sync(0xffffffffu, q0, off);
            s1 += __shfl_xor_sync(0xffffffffu, s1, off);
            q1 += __shfl_xor_sync(0xffffffffu, q1, off);
        }
        __syncthreads();
        if (tg == 0) {
            sm.red[warp_n][ar][0] = s0;     sm.red[warp_n][ar][1] = q0;
            sm.red[warp_n][ar + 8][0] = s1; sm.red[warp_n][ar + 8][1] = q1;
        }
        __syncthreads();
        s0 = sm.red[0][ar][0] + sm.red[1][ar][0];
        q0 = sm.red[0][ar][1] + sm.red[1][ar][1];
        s1 = sm.red[0][ar + 8][0] + sm.red[1][ar + 8][0];
        q1 = sm.red[0][ar + 8][1] + sm.red[1][ar + 8][1];
        const float invN = 1.0f / OO;
        float m0 = s0 * invN, m1 = s1 * invN;
        float r0 = rsqrtf(q0 * invN - m0 * m0 + 1e-5f);
        float r1 = rsqrtf(q1 * invN - m1 * m1 + 1e-5f);
        size_t row0 = ((size_t)e * B + b0 + ar) * OO;
        size_t row1 = row0 + (size_t)8 * OO;
#pragma unroll
        for (int nt = 0; nt < 8; nt++) {
            int c = cbase + nt * 8;
            float g0 = ge[c], g1 = ge[c + 1], t0 = bte[c], t1 = bte[c + 1];
            float v00 = fmaxf((acc[nt][0] - m0) * r0 * g0 + t0, 0.f);
            float v01 = fmaxf((acc[nt][1] - m0) * r0 * g1 + t1, 0.f);
            float v10 = fmaxf((acc[nt][2] - m1) * r1 * g0 + t0, 0.f);
            float v11 = fmaxf((acc[nt][3] - m1) * r1 * g1 + t1, 0.f);
            *(float2*)&eo[row0 + c] = make_float2(v00, v01);
            *(float2*)&eo[row1 + c] = make_float2(v10, v11);
        }
    }
}

// ---------------------------------------------------------------------------
// Gate: relu(x@W1+b1) single-pass fp16, then tiny GEMM + softmax in smem.
// ---------------------------------------------------------------------------
template <int NOUT>
__global__ void __launch_bounds__(256)
gate_mma(const h16* __restrict__ xh,
         const h16* __restrict__ w1, size_t w1stride,
         const float* __restrict__ b1, size_t b1stride,
         const float* __restrict__ w2, size_t w2stride,
         const float* __restrict__ b2, size_t b2stride,
         float* __restrict__ out, size_t outstride)
{
    constexpr int BM = 128, K = D, N = G_, NTI = N / 8;
    constexpr int NTHREADS = 256;

    __shared__ h16 sA[BM][16];
    __shared__ h16 sB[N][18];
    __shared__ float ghs[BM][G_ + 1];
    __shared__ float ws2[G_][NOUT];
    __shared__ float b2s[NOUT];

    const int t   = blockIdx.y;
    const int b0  = blockIdx.x * BM;
    const int tid = threadIdx.x;
    const int wid = tid >> 5, lane = tid & 31;
    const int gr = lane >> 2, tg = lane & 3;
    const int ar = wid * 16 + gr;

    const h16* W1t = w1 + (size_t)t * w1stride;
    const float* b1t = b1 + (size_t)t * b1stride;
    const float* w2t = w2 + (size_t)t * w2stride;
    const float* b2t = b2 + (size_t)t * b2stride;
    float* outt = out + (size_t)t * outstride;

    for (int i = tid; i < G_ * NOUT; i += NTHREADS) ws2[i / NOUT][i % NOUT] = w2t[i];
    if (tid < NOUT) b2s[tid] = b2t[tid];

    float acc[NTI][4];
#pragma unroll
    for (int nt = 0; nt < NTI; nt++)
#pragma unroll
        for (int j = 0; j < 4; j++) acc[nt][j] = 0.f;

    for (int k0 = 0; k0 < K; k0 += 16) {
        __syncthreads();
#pragma unroll
        for (int i = tid * 4; i < BM * 16; i += NTHREADS * 4) {
            int r = i >> 4, kk = i & 15;
            *(uint2*)&sA[r][kk] = *(const uint2*)&xh[(size_t)(b0 + r) * K + k0 + kk];
        }
#pragma unroll
        for (int i = tid; i < 16 * (N / 2); i += NTHREADS) {
            int kk = i / (N / 2), cp = i % (N / 2);
            unsigned vh = *(const unsigned*)&W1t[(size_t)(k0 + kk) * N + cp * 2];
            sB[cp * 2    ][kk] = __ushort_as_half((unsigned short)(vh & 0xffff));
            sB[cp * 2 + 1][kk] = __ushort_as_half((unsigned short)(vh >> 16));
        }
        __syncthreads();

        unsigned ah[4];
        load_afrag(ah, &sA[0][0], 16, ar, tg * 2);

#pragma unroll
        for (int nt = 0; nt < NTI; nt++) {
            int bc = nt * 8 + gr;
            unsigned bh[2];
            load_bfrag(bh, &sB[0][0], 18, bc, tg * 2);
            mma_fp16(acc[nt], ah, bh);
        }
    }
    __syncthreads();

#pragma unroll
    for (int nt = 0; nt < NTI; nt++) {
        int c = nt * 8 + tg * 2;
        float bv0 = b1t[c], bv1 = b1t[c + 1];
        ghs[ar    ][c]     = fmaxf(acc[nt][0] + bv0, 0.f);
        ghs[ar    ][c + 1] = fmaxf(acc[nt][1] + bv1, 0.f);
        ghs[ar + 8][c]     = fmaxf(acc[nt][2] + bv0, 0.f);
        ghs[ar + 8][c + 1] = fmaxf(acc[nt][3] + bv1, 0.f);
    }
    __syncthreads();

    if (tid < BM) {
        float lg[NOUT];
#pragma unroll
        for (int j = 0; j < NOUT; j++) lg[j] = b2s[j];
        for (int k = 0; k < G_; k++) {
            float g = ghs[tid][k];
#pragma unroll
            for (int j = 0; j < NOUT; j++) lg[j] = fmaf(g, ws2[k][j], lg[j]);
        }
        float mx = -1e30f;
#pragma unroll
        for (int j = 0; j < NOUT; j++) mx = fmaxf(mx, lg[j]);
        float sum = 0.f;
#pragma unroll
        for (int j = 0; j < NOUT; j++) { lg[j] = __expf(lg[j] - mx); sum += lg[j]; }
        float inv = 1.0f / sum;
#pragma unroll
        for (int j = 0; j < NOUT; j++)
            outt[(size_t)(b0 + tid) * NOUT + j] = lg[j] * inv;
    }
}

// ---------------------------------------------------------------------------
__global__ void __launch_bounds__(256)
combine_kernel(const float* __restrict__ eo, const float* __restrict__ gw,
               const float* __restrict__ sgw, float* __restrict__ out)
{
    const int b = blockIdx.x * 2 + (threadIdx.x >> 7);
    const int o = threadIdx.x & 127;

    float v[E_];
#pragma unroll
    for (int e = 0; e < E_; e++)
        v[e] = eo[((size_t)e * B + b) * OO + o];

#pragma unroll
    for (int t = 0; t < T_; t++) {
        const float* g = gw + ((size_t)t * B + b) * NE;
        float s = 0.f;
#pragma unroll
        for (int j = 0; j < NS; j++) s += g[j] * v[j];
#pragma unroll
        for (int n = 0; n < NT_TASK; n++) s += g[NS + n] * v[NS + t * NT_TASK + n];
        out[((size_t)t * B + b) * OO + o] = s;
    }

    const float* sg = sgw + (size_t)b * E_;
    float s = 0.f;
#pragma unroll
    for (int e = 0; e < E_; e++) s += sg[e] * v[e];
    out[((size_t)3 * B + b) * OO + o] = s;
}

// ---------------------------------------------------------------------------
extern "C" void kernel_launch(void* const* d_in, const int* in_sizes, int n_in,
                              void* d_out, int out_size)
{
    const float* x     = (const float*)d_in[0];
    const float* ew1   = (const float*)d_in[1];
    const float* eb1   = (const float*)d_in[2];
    const float* eg1   = (const float*)d_in[3];
    const float* ebt1  = (const float*)d_in[4];
    const float* ew2   = (const float*)d_in[5];
    const float* eb2   = (const float*)d_in[6];
    const float* eg2   = (const float*)d_in[7];
    const float* ebt2  = (const float*)d_in[8];
    const float* ew3   = (const float*)d_in[9];
    const float* eb3   = (const float*)d_in[10];
    const float* eg3   = (const float*)d_in[11];
    const float* ebt3  = (const float*)d_in[12];
    const float* tg_w1 = (const float*)d_in[13];
    const float* tg_b1 = (const float*)d_in[14];
    const float* tg_w2 = (const float*)d_in[15];
    const float* tg_b2 = (const float*)d_in[16];
    const float* sg_w1 = (const float*)d_in[17];
    const float* sg_b1 = (const float*)d_in[18];
    const float* sg_w2 = (const float*)d_in[19];
    const float* sg_b2 = (const float*)d_in[20];
    float* out = (float*)d_out;

    static h16 *xh = nullptr, *w1t, *w2t, *w3t, *tgw1, *sgw1;
    static float *eo, *gw, *sgw;
    if (!xh) {
        cudaGetSymbolAddress((void**)&xh,  g_xh);
        cudaGetSymbolAddress((void**)&w1t, g_w1t);
        cudaGetSymbolAddress((void**)&w2t, g_w2t);
        cudaGetSymbolAddress((void**)&w3t, g_w3t);
        cudaGetSymbolAddress((void**)&tgw1, g_tgw1);
        cudaGetSymbolAddress((void**)&sgw1, g_sgw1);
        cudaGetSymbolAddress((void**)&eo,  g_eo);
        cudaGetSymbolAddress((void**)&gw,  g_gw);
        cudaGetSymbolAddress((void**)&sgw, g_sgw);
        cudaFuncSetAttribute(expert_fused, cudaFuncAttributeMaxDynamicSharedMemorySize,
                             (int)sizeof(SmemT));
    }

    auto launch_half = [](const float* src, h16* dst, size_t n) {
        int n4 = (int)(n / 4);
        to_half<<<(n4 + 255) / 256, 256>>>((const float4*)src, (unsigned*)dst, n4);
    };
    launch_half(x,     xh,   (size_t)B * D);
    launch_half(tg_w1, tgw1, (size_t)T_ * D * G_);
    launch_half(sg_w1, sgw1, (size_t)D * G_);

    transpose_half<<<dim3(D / 32, H / 32, E_), 256>>>(ew1, w1t, D, H);
    transpose_half<<<dim3(H / 32, H / 32, E_), 256>>>(ew2, w2t, H, H);
    transpose_half<<<dim3(H / 32, OO / 32, E_), 256>>>(ew3, w3t, H, OO);

    expert_fused<<<dim3(E_, B / 64), 256, sizeof(SmemT)>>>(
        xh, w1t, w2t, w3t,
        eb1, eg1, ebt1, eb2, eg2, ebt2, eb3, eg3, ebt3, eo);

    gate_mma<NE><<<dim3(B / 128, T_), 256>>>(
        xh, tgw1, (size_t)D * G_,
        tg_b1, (size_t)G_, tg_w2, (size_t)G_ * NE, tg_b2, (size_t)NE,
        gw, (size_t)B * NE);
    gate_mma<E_><<<dim3(B / 128, 1), 256>>>(
        xh, sgw1, (size_t)0,
        sg_b1, (size_t)0, sg_w2, (size_t)0, sg_b2, (size_t)0,
        sgw, (size_t)0);

    combine_kernel<<<B / 2, 256>>>(eo, gw, sgw, out);
}

// round 7
// speedup vs baseline: 4.9413x; 1.0572x over previous
#include <cuda_runtime.h>
#include <cuda_fp16.h>
#include <math.h>
#include <stdint.h>

#define B  32768
#define D  512
#define H  256
#define OO 128
#define E_ 10
#define T_ 3
#define G_ 64
#define NS 4
#define NT_TASK 2
#define NE (NS + NT_TASK)

typedef __half h16;

// ---------------- scratch (allocation-free) ----------------
__device__ h16   g_xh[(size_t)B * D];
__device__ h16   g_w1t[(size_t)E_ * H * D];    // [E][N=256][K=512] fp16
__device__ h16   g_w2t[(size_t)E_ * H * H];    // [E][256][256]
__device__ h16   g_w3t[(size_t)E_ * OO * H];   // [E][128][256]
__device__ h16   g_wgt[(size_t)256 * D];       // combined gate W1^T [256][512]
__device__ float g_eo[(size_t)E_ * B * OO];
__device__ float g_gw[(size_t)T_ * B * NE];
__device__ float g_sgw[(size_t)B * E_];

// ---------------- helpers ----------------
__device__ __forceinline__ void mma_fp16(float* c, const unsigned* a, const unsigned* b) {
    asm volatile(
        "mma.sync.aligned.m16n8k16.row.col.f32.f16.f16.f32 "
        "{%0,%1,%2,%3}, {%4,%5,%6,%7}, {%8,%9}, {%0,%1,%2,%3};\n"
        : "+f"(c[0]), "+f"(c[1]), "+f"(c[2]), "+f"(c[3])
        : "r"(a[0]), "r"(a[1]), "r"(a[2]), "r"(a[3]), "r"(b[0]), "r"(b[1]));
}
__device__ __forceinline__ unsigned pack_h2(h16 a, h16 b) {
    return (unsigned)__half_as_ushort(a) | ((unsigned)__half_as_ushort(b) << 16);
}
__device__ __forceinline__ void cp16(void* s, const void* g) {
    unsigned sa = (unsigned)__cvta_generic_to_shared(s);
    asm volatile("cp.async.cg.shared.global [%0], [%1], 16;\n" :: "r"(sa), "l"(g));
}
__device__ __forceinline__ void cp_commit() { asm volatile("cp.async.commit_group;\n"); }
template <int N2> __device__ __forceinline__ void cp_wait() {
    asm volatile("cp.async.wait_group %0;\n" :: "n"(N2));
}
__device__ __forceinline__ void load_afrag(unsigned* a, const h16* base, int stride, int r, int koff) {
    a[0] = *(const unsigned*)(base + (size_t)r * stride + koff);
    a[1] = *(const unsigned*)(base + (size_t)(r + 8) * stride + koff);
    a[2] = *(const unsigned*)(base + (size_t)r * stride + koff + 8);
    a[3] = *(const unsigned*)(base + (size_t)(r + 8) * stride + koff + 8);
}
__device__ __forceinline__ void load_bfrag(unsigned* b, const h16* base, int stride, int n, int koff) {
    b[0] = *(const unsigned*)(base + (size_t)n * stride + koff);
    b[1] = *(const unsigned*)(base + (size_t)n * stride + koff + 8);
}

// ---------------- prep kernels ----------------
__global__ void to_half(const float4* __restrict__ src, unsigned* __restrict__ dst2, int n4)
{
    int i = blockIdx.x * blockDim.x + threadIdx.x;
    if (i >= n4) return;
    float4 v = src[i];
    dst2[i * 2]     = pack_h2(__float2half_rn(v.x), __float2half_rn(v.y));
    dst2[i * 2 + 1] = pack_h2(__float2half_rn(v.z), __float2half_rn(v.w));
}

// W [E][K][N] fp32 -> T [E][N][K] fp16
__global__ void transpose_half(const float* __restrict__ W, h16* __restrict__ T, int K, int N)
{
    __shared__ float t[32][33];
    const int e  = blockIdx.z;
    const int k0 = blockIdx.x * 32, n0 = blockIdx.y * 32;
    const int tid = threadIdx.x;
    const float* We = W + (size_t)e * K * N;
    for (int i = tid; i < 1024; i += 256) {
        int r = i >> 5, c = i & 31;
        t[r][c] = We[(size_t)(k0 + r) * N + n0 + c];
    }
    __syncthreads();
    size_t base = (size_t)e * N * K;
    for (int i = tid; i < 1024; i += 256) {
        int nn = i >> 5, kk = i & 31;
        T[base + (size_t)(n0 + nn) * K + k0 + kk] = __float2half_rn(t[kk][nn]);
    }
}

// Build combined gate weight: rows 0..191 = tg_w1[t][:,g]^T, rows 192..255 = sg_w1^T
__global__ void build_gate_wt(const float* __restrict__ tg_w1, const float* __restrict__ sg_w1,
                              h16* __restrict__ wgt)
{
    int i = blockIdx.x * blockDim.x + threadIdx.x;   // over 256*512
    if (i >= 256 * D) return;
    int n = i >> 9, d = i & 511;
    float v;
    if (n < 192) {
        int t = n >> 6, g = n & 63;
        v = tg_w1[((size_t)t * D + d) * G_ + g];
    } else {
        v = sg_w1[(size_t)d * G_ + (n - 192)];
    }
    wgt[(size_t)n * D + d] = __float2half_rn(v);
}

// ---------------------------------------------------------------------------
// Fused expert tower (single-pass fp16): L1 -> LN -> L2 -> LN -> L3 -> LN.
// ---------------------------------------------------------------------------
struct SmemT {
    h16   sB[2][256][40];  // 40 KB
    h16   sX[2][64][40];   // 10 KB
    h16   sH[64][264];     // 33 KB
    float red[2][64][2];   //  1 KB
};

__global__ void __launch_bounds__(256, 2)
expert_fused(const h16* __restrict__ xh,
             const h16* __restrict__ w1t, const h16* __restrict__ w2t, const h16* __restrict__ w3t,
             const float* __restrict__ eb1, const float* __restrict__ eg1, const float* __restrict__ ebt1,
             const float* __restrict__ eb2, const float* __restrict__ eg2, const float* __restrict__ ebt2,
             const float* __restrict__ eb3, const float* __restrict__ eg3, const float* __restrict__ ebt3,
             float* __restrict__ eo)
{
    extern __shared__ char raw[];
    SmemT& sm = *reinterpret_cast<SmemT*>(raw);

    const int e   = blockIdx.x;
    const int b0  = blockIdx.y * 64;
    const int tid = threadIdx.x;
    const int wid = tid >> 5, lane = tid & 31;
    const int warp_m = wid & 3, warp_n = wid >> 2;
    const int gr = lane >> 2, tg = lane & 3;
    const int ar = warp_m * 16 + gr;

    const h16* W1 = w1t + (size_t)e * H * D;
    const h16* W2 = w2t + (size_t)e * H * H;
    const h16* W3 = w3t + (size_t)e * OO * H;

    auto loadB = [&](const h16* T, int rows, int K, int buf, int k0) {
        for (int i = tid; i < rows * 4; i += 256) {
            int n = i >> 2, c = i & 3;
            cp16(&sm.sB[buf][n][c * 8], T + (size_t)n * K + k0 + c * 8);
        }
    };
    auto loadX = [&](int buf, int k0) {
        int r = tid >> 2, c = tid & 3;
        cp16(&sm.sX[buf][r][c * 8], xh + (size_t)(b0 + r) * D + k0 + c * 8);
    };

    float acc[16][4];

    // =================== Layer 1 ===================
#pragma unroll
    for (int nt = 0; nt < 16; nt++)
#pragma unroll
        for (int j = 0; j < 4; j++) acc[nt][j] = 0.f;

    int buf = 0;
    loadX(0, 0);
    loadB(W1, 256, D, 0, 0);
    cp_commit();

    for (int ks = 0; ks < 16; ks++) {
        if (ks < 15) { loadX(buf ^ 1, (ks + 1) * 32); loadB(W1, 256, D, buf ^ 1, (ks + 1) * 32); }
        cp_commit();
        cp_wait<1>(); __syncthreads();
#pragma unroll
        for (int ksub = 0; ksub < 2; ksub++) {
            const int koff = ksub * 16 + tg * 2;
            unsigned ah[4];
            load_afrag(ah, &sm.sX[buf][0][0], 40, ar, koff);
#pragma unroll
            for (int nt = 0; nt < 16; nt++) {
                int bc = warp_n * 128 + nt * 8 + gr;
                unsigned bh[2];
                load_bfrag(bh, &sm.sB[buf][0][0], 40, bc, koff);
                mma_fp16(acc[nt], ah, bh);
            }
        }
        __syncthreads();
        buf ^= 1;
    }
    loadB(W2, 256, H, 0, 0);
    cp_commit();

    // ---- epilogue 1 -> sH ----
    {
        const float* be  = eb1  + (size_t)e * H;
        const float* ge  = eg1  + (size_t)e * H;
        const float* bte = ebt1 + (size_t)e * H;
        const int cbase = warp_n * 128 + tg * 2;
        float s0 = 0.f, q0 = 0.f, s1 = 0.f, q1 = 0.f;
#pragma unroll
        for (int nt = 0; nt < 16; nt++) {
            int c = cbase + nt * 8;
            float bv0 = be[c], bv1 = be[c + 1];
            acc[nt][0] += bv0; acc[nt][1] += bv1;
            acc[nt][2] += bv0; acc[nt][3] += bv1;
            s0 += acc[nt][0] + acc[nt][1];
            q0 = fmaf(acc[nt][0], acc[nt][0], fmaf(acc[nt][1], acc[nt][1], q0));
            s1 += acc[nt][2] + acc[nt][3];
            q1 = fmaf(acc[nt][2], acc[nt][2], fmaf(acc[nt][3], acc[nt][3], q1));
        }
#pragma unroll
        for (int off = 1; off <= 2; off <<= 1) {
            s0 += __shfl_xor_sync(0xffffffffu, s0, off);
            q0 += __shfl_xor_sync(0xffffffffu, q0, off);
            s1 += __shfl_xor_sync(0xffffffffu, s1, off);
            q1 += __shfl_xor_sync(0xffffffffu, q1, off);
        }
        __syncthreads();
        if (tg == 0) {
            sm.red[warp_n][ar][0] = s0;     sm.red[warp_n][ar][1] = q0;
            sm.red[warp_n][ar + 8][0] = s1; sm.red[warp_n][ar + 8][1] = q1;
        }
        __syncthreads();
        s0 = sm.red[0][ar][0] + sm.red[1][ar][0];
        q0 = sm.red[0][ar][1] + sm.red[1][ar][1];
        s1 = sm.red[0][ar + 8][0] + sm.red[1][ar + 8][0];
        q1 = sm.red[0][ar + 8][1] + sm.red[1][ar + 8][1];
        const float invN = 1.0f / H;
        float m0 = s0 * invN, m1 = s1 * invN;
        float r0 = rsqrtf(q0 * invN - m0 * m0 + 1e-5f);
        float r1 = rsqrtf(q1 * invN - m1 * m1 + 1e-5f);
#pragma unroll
        for (int nt = 0; nt < 16; nt++) {
            int c = cbase + nt * 8;
            float g0 = ge[c], g1 = ge[c + 1], t0 = bte[c], t1 = bte[c + 1];
            float v00 = fmaxf((acc[nt][0] - m0) * r0 * g0 + t0, 0.f);
            float v01 = fmaxf((acc[nt][1] - m0) * r0 * g1 + t1, 0.f);
            float v10 = fmaxf((acc[nt][2] - m1) * r1 * g0 + t0, 0.f);
            float v11 = fmaxf((acc[nt][3] - m1) * r1 * g1 + t1, 0.f);
            *(unsigned*)&sm.sH[ar][c]     = pack_h2(__float2half_rn(v00), __float2half_rn(v01));
            *(unsigned*)&sm.sH[ar + 8][c] = pack_h2(__float2half_rn(v10), __float2half_rn(v11));
        }
    }

    // =================== Layer 2 ===================
#pragma unroll
    for (int nt = 0; nt < 16; nt++)
#pragma unroll
        for (int j = 0; j < 4; j++) acc[nt][j] = 0.f;

    buf = 0;
    for (int ks = 0; ks < 8; ks++) {
        if (ks < 7) loadB(W2, 256, H, buf ^ 1, (ks + 1) * 32);
        cp_commit();
        cp_wait<1>(); __syncthreads();
#pragma unroll
        for (int ksub = 0; ksub < 2; ksub++) {
            const int koffA = ks * 32 + ksub * 16 + tg * 2;
            const int koffB = ksub * 16 + tg * 2;
            unsigned ah[4];
            load_afrag(ah, &sm.sH[0][0], 264, ar, koffA);
#pragma unroll
            for (int nt = 0; nt < 16; nt++) {
                int bc = warp_n * 128 + nt * 8 + gr;
                unsigned bh[2];
                load_bfrag(bh, &sm.sB[buf][0][0], 40, bc, koffB);
                mma_fp16(acc[nt], ah, bh);
            }
        }
        __syncthreads();
        buf ^= 1;
    }
    loadB(W3, 128, H, 0, 0);
    cp_commit();

    // ---- epilogue 2 -> sH ----
    {
        const float* be  = eb2  + (size_t)e * H;
        const float* ge  = eg2  + (size_t)e * H;
        const float* bte = ebt2 + (size_t)e * H;
        const int cbase = warp_n * 128 + tg * 2;
        float s0 = 0.f, q0 = 0.f, s1 = 0.f, q1 = 0.f;
#pragma unroll
        for (int nt = 0; nt < 16; nt++) {
            int c = cbase + nt * 8;
            float bv0 = be[c], bv1 = be[c + 1];
            acc[nt][0] += bv0; acc[nt][1] += bv1;
            acc[nt][2] += bv0; acc[nt][3] += bv1;
            s0 += acc[nt][0] + acc[nt][1];
            q0 = fmaf(acc[nt][0], acc[nt][0], fmaf(acc[nt][1], acc[nt][1], q0));
            s1 += acc[nt][2] + acc[nt][3];
            q1 = fmaf(acc[nt][2], acc[nt][2], fmaf(acc[nt][3], acc[nt][3], q1));
        }
#pragma unroll
        for (int off = 1; off <= 2; off <<= 1) {
            s0 += __shfl_xor_sync(0xffffffffu, s0, off);
            q0 += __shfl_xor_sync(0xffffffffu, q0, off);
            s1 += __shfl_xor_sync(0xffffffffu, s1, off);
            q1 += __shfl_xor_sync(0xffffffffu, q1, off);
        }
        __syncthreads();
        if (tg == 0) {
            sm.red[warp_n][ar][0] = s0;     sm.red[warp_n][ar][1] = q0;
            sm.red[warp_n][ar + 8][0] = s1; sm.red[warp_n][ar + 8][1] = q1;
        }
        __syncthreads();
        s0 = sm.red[0][ar][0] + sm.red[1][ar][0];
        q0 = sm.red[0][ar][1] + sm.red[1][ar][1];
        s1 = sm.red[0][ar + 8][0] + sm.red[1][ar + 8][0];
        q1 = sm.red[0][ar + 8][1] + sm.red[1][ar + 8][1];
        const float invN = 1.0f / H;
        float m0 = s0 * invN, m1 = s1 * invN;
        float r0 = rsqrtf(q0 * invN - m0 * m0 + 1e-5f);
        float r1 = rsqrtf(q1 * invN - m1 * m1 + 1e-5f);
        __syncthreads();
#pragma unroll
        for (int nt = 0; nt < 16; nt++) {
            int c = cbase + nt * 8;
            float g0 = ge[c], g1 = ge[c + 1], t0 = bte[c], t1 = bte[c + 1];
            float v00 = fmaxf((acc[nt][0] - m0) * r0 * g0 + t0, 0.f);
            float v01 = fmaxf((acc[nt][1] - m0) * r0 * g1 + t1, 0.f);
            float v10 = fmaxf((acc[nt][2] - m1) * r1 * g0 + t0, 0.f);
            float v11 = fmaxf((acc[nt][3] - m1) * r1 * g1 + t1, 0.f);
            *(unsigned*)&sm.sH[ar][c]     = pack_h2(__float2half_rn(v00), __float2half_rn(v01));
            *(unsigned*)&sm.sH[ar + 8][c] = pack_h2(__float2half_rn(v10), __float2half_rn(v11));
        }
    }

    // =================== Layer 3 ===================
#pragma unroll
    for (int nt = 0; nt < 8; nt++)
#pragma unroll
        for (int j = 0; j < 4; j++) acc[nt][j] = 0.f;

    buf = 0;
    for (int ks = 0; ks < 8; ks++) {
        if (ks < 7) loadB(W3, 128, H, buf ^ 1, (ks + 1) * 32);
        cp_commit();
        cp_wait<1>(); __syncthreads();
#pragma unroll
        for (int ksub = 0; ksub < 2; ksub++) {
            const int koffA = ks * 32 + ksub * 16 + tg * 2;
            const int koffB = ksub * 16 + tg * 2;
            unsigned ah[4];
            load_afrag(ah, &sm.sH[0][0], 264, ar, koffA);
#pragma unroll
            for (int nt = 0; nt < 8; nt++) {
                int bc = warp_n * 64 + nt * 8 + gr;
                unsigned bh[2];
                load_bfrag(bh, &sm.sB[buf][0][0], 40, bc, koffB);
                mma_fp16(acc[nt], ah, bh);
            }
        }
        __syncthreads();
        buf ^= 1;
    }

    // ---- epilogue 3 -> eo ----
    {
        const float* be  = eb3  + (size_t)e * OO;
        const float* ge  = eg3  + (size_t)e * OO;
        const float* bte = ebt3 + (size_t)e * OO;
        const int cbase = warp_n * 64 + tg * 2;
        float s0 = 0.f, q0 = 0.f, s1 = 0.f, q1 = 0.f;
#pragma unroll
        for (int nt = 0; nt < 8; nt++) {
            int c = cbase + nt * 8;
            float bv0 = be[c], bv1 = be[c + 1];
            acc[nt][0] += bv0; acc[nt][1] += bv1;
            acc[nt][2] += bv0; acc[nt][3] += bv1;
            s0 += acc[nt][0] + acc[nt][1];
            q0 = fmaf(acc[nt][0], acc[nt][0], fmaf(acc[nt][1], acc[nt][1], q0));
            s1 += acc[nt][2] + acc[nt][3];
            q1 = fmaf(acc[nt][2], acc[nt][2], fmaf(acc[nt][3], acc[nt][3], q1));
        }
#pragma unroll
        for (int off = 1; off <= 2; off <<= 1) {
            s0 += __shfl_xor_sync(0xffffffffu, s0, off);
            q0 += __shfl_xor_sync(0xffffffffu, q0, off);
            s1 += __shfl_xor_sync(0xffffffffu, s1, off);
            q1 += __shfl_xor_sync(0xffffffffu, q1, off);
        }
        __syncthreads();
        if (tg == 0) {
            sm.red[warp_n][ar][0] = s0;     sm.red[warp_n][ar][1] = q0;
            sm.red[warp_n][ar + 8][0] = s1; sm.red[warp_n][ar + 8][1] = q1;
        }
        __syncthreads();
        s0 = sm.red[0][ar][0] + sm.red[1][ar][0];
        q0 = sm.red[0][ar][1] + sm.red[1][ar][1];
        s1 = sm.red[0][ar + 8][0] + sm.red[1][ar + 8][0];
        q1 = sm.red[0][ar + 8][1] + sm.red[1][ar + 8][1];
        const float invN = 1.0f / OO;
        float m0 = s0 * invN, m1 = s1 * invN;
        float r0 = rsqrtf(q0 * invN - m0 * m0 + 1e-5f);
        float r1 = rsqrtf(q1 * invN - m1 * m1 + 1e-5f);
        size_t row0 = ((size_t)e * B + b0 + ar) * OO;
        size_t row1 = row0 + (size_t)8 * OO;
#pragma unroll
        for (int nt = 0; nt < 8; nt++) {
            int c = cbase + nt * 8;
            float g0 = ge[c], g1 = ge[c + 1], t0 = bte[c], t1 = bte[c + 1];
            float v00 = fmaxf((acc[nt][0] - m0) * r0 * g0 + t0, 0.f);
            float v01 = fmaxf((acc[nt][1] - m0) * r0 * g1 + t1, 0.f);
            float v10 = fmaxf((acc[nt][2] - m1) * r1 * g0 + t0, 0.f);
            float v11 = fmaxf((acc[nt][3] - m1) * r1 * g1 + t1, 0.f);
            *(float2*)&eo[row0 + c] = make_float2(v00, v01);
            *(float2*)&eo[row1 + c] = make_float2(v10, v11);
        }
    }
}

// ---------------------------------------------------------------------------
// Fused gates: one GEMM x[64,512] @ Wg^T[256,512] -> gh[64,256], then all
// task softmaxes + shared softmax in-block.
// ---------------------------------------------------------------------------
struct GSmem {
    h16   sB[2][256][40];      // 40 KB
    h16   sX[2][64][40];       // 10 KB
    h16   ghs[64][266];        // 33.25 KB (266: odd word stride -> conflict-free)
    float w2s[T_ * G_ * NE];   // 1152 f
    float sw2s[G_ * E_];       // 640 f
    float b1s[256];
    float b2s[T_ * NE + E_];   // 28
};

__global__ void __launch_bounds__(256, 2)
gate_fused(const h16* __restrict__ xh, const h16* __restrict__ wgt,
           const float* __restrict__ tg_b1, const float* __restrict__ sg_b1,
           const float* __restrict__ tg_w2, const float* __restrict__ tg_b2,
           const float* __restrict__ sg_w2, const float* __restrict__ sg_b2,
           float* __restrict__ gw, float* __restrict__ sgw)
{
    extern __shared__ char raw[];
    GSmem& sm = *reinterpret_cast<GSmem*>(raw);

    const int b0  = blockIdx.x * 64;
    const int tid = threadIdx.x;
    const int wid = tid >> 5, lane = tid & 31;
    const int warp_m = wid & 3, warp_n = wid >> 2;
    const int gr = lane >> 2, tg = lane & 3;
    const int ar = warp_m * 16 + gr;

    // preload small params
    for (int i = tid; i < T_ * G_ * NE; i += 256) sm.w2s[i] = tg_w2[i];
    for (int i = tid; i < G_ * E_; i += 256) sm.sw2s[i] = sg_w2[i];
    sm.b1s[tid] = (tid < 192) ? tg_b1[tid] : sg_b1[tid - 192];
    if (tid < T_ * NE) sm.b2s[tid] = tg_b2[tid];
    else if (tid < T_ * NE + E_) sm.b2s[tid] = sg_b2[tid - T_ * NE];

    auto loadB = [&](int buf, int k0) {
        for (int i = tid; i < 256 * 4; i += 256) {
            int n = i >> 2, c = i & 3;
            cp16(&sm.sB[buf][n][c * 8], wgt + (size_t)n * D + k0 + c * 8);
        }
    };
    auto loadX = [&](int buf, int k0) {
        int r = tid >> 2, c = tid & 3;
        cp16(&sm.sX[buf][r][c * 8], xh + (size_t)(b0 + r) * D + k0 + c * 8);
    };

    float acc[16][4];
#pragma unroll
    for (int nt = 0; nt < 16; nt++)
#pragma unroll
        for (int j = 0; j < 4; j++) acc[nt][j] = 0.f;

    int buf = 0;
    loadX(0, 0);
    loadB(0, 0);
    cp_commit();

    for (int ks = 0; ks < 16; ks++) {
        if (ks < 15) { loadX(buf ^ 1, (ks + 1) * 32); loadB(buf ^ 1, (ks + 1) * 32); }
        cp_commit();
        cp_wait<1>(); __syncthreads();
#pragma unroll
        for (int ksub = 0; ksub < 2; ksub++) {
            const int koff = ksub * 16 + tg * 2;
            unsigned ah[4];
            load_afrag(ah, &sm.sX[buf][0][0], 40, ar, koff);
#pragma unroll
            for (int nt = 0; nt < 16; nt++) {
                int bc = warp_n * 128 + nt * 8 + gr;
                unsigned bh[2];
                load_bfrag(bh, &sm.sB[buf][0][0], 40, bc, koff);
                mma_fp16(acc[nt], ah, bh);
            }
        }
        __syncthreads();
        buf ^= 1;
    }

    // bias + relu -> ghs (fp16)
    {
        const int cbase = warp_n * 128 + tg * 2;
#pragma unroll
        for (int nt = 0; nt < 16; nt++) {
            int c = cbase + nt * 8;
            float bv0 = sm.b1s[c], bv1 = sm.b1s[c + 1];
            float v00 = fmaxf(acc[nt][0] + bv0, 0.f);
            float v01 = fmaxf(acc[nt][1] + bv1, 0.f);
            float v10 = fmaxf(acc[nt][2] + bv0, 0.f);
            float v11 = fmaxf(acc[nt][3] + bv1, 0.f);
            *(unsigned*)&sm.ghs[ar][c]     = pack_h2(__float2half_rn(v00), __float2half_rn(v01));
            *(unsigned*)&sm.ghs[ar + 8][c] = pack_h2(__float2half_rn(v10), __float2half_rn(v11));
        }
    }
    __syncthreads();

    if (tid < 192) {
        // task gates: row = tid & 63, t = tid >> 6
        const int row = tid & 63, t = tid >> 6;
        float lg[NE];
#pragma unroll
        for (int j = 0; j < NE; j++) lg[j] = sm.b2s[t * NE + j];
        for (int g = 0; g < G_; g++) {
            float gv = __half2float(sm.ghs[row][t * 64 + g]);
            const float* w = &sm.w2s[(t * G_ + g) * NE];
#pragma unroll
            for (int j = 0; j < NE; j++) lg[j] = fmaf(gv, w[j], lg[j]);
        }
        float mx = -1e30f;
#pragma unroll
        for (int j = 0; j < NE; j++) mx = fmaxf(mx, lg[j]);
        float sum = 0.f;
#pragma unroll
        for (int j = 0; j < NE; j++) { lg[j] = __expf(lg[j] - mx); sum += lg[j]; }
        float inv = 1.0f / sum;
#pragma unroll
        for (int j = 0; j < NE; j++)
            gw[((size_t)t * B + b0 + row) * NE + j] = lg[j] * inv;
    } else {
        // shared gate: row = tid - 192
        const int row = tid - 192;
        float lg[E_];
#pragma unroll
        for (int j = 0; j < E_; j++) lg[j] = sm.b2s[T_ * NE + j];
        for (int g = 0; g < G_; g++) {
            float gv = __half2float(sm.ghs[row][192 + g]);
            const float* w = &sm.sw2s[g * E_];
#pragma unroll
            for (int j = 0; j < E_; j++) lg[j] = fmaf(gv, w[j], lg[j]);
        }
        float mx = -1e30f;
#pragma unroll
        for (int j = 0; j < E_; j++) mx = fmaxf(mx, lg[j]);
        float sum = 0.f;
#pragma unroll
        for (int j = 0; j < E_; j++) { lg[j] = __expf(lg[j] - mx); sum += lg[j]; }
        float inv = 1.0f / sum;
#pragma unroll
        for (int j = 0; j < E_; j++)
            sgw[(size_t)(b0 + row) * E_ + j] = lg[j] * inv;
    }
}

// ---------------------------------------------------------------------------
__global__ void __launch_bounds__(256)
combine_kernel(const float* __restrict__ eo, const float* __restrict__ gw,
               const float* __restrict__ sgw, float* __restrict__ out)
{
    const int b = blockIdx.x * 2 + (threadIdx.x >> 7);
    const int o = threadIdx.x & 127;

    float v[E_];
#pragma unroll
    for (int e = 0; e < E_; e++)
        v[e] = eo[((size_t)e * B + b) * OO + o];

#pragma unroll
    for (int t = 0; t < T_; t++) {
        const float* g = gw + ((size_t)t * B + b) * NE;
        float s = 0.f;
#pragma unroll
        for (int j = 0; j < NS; j++) s += g[j] * v[j];
#pragma unroll
        for (int n = 0; n < NT_TASK; n++) s += g[NS + n] * v[NS + t * NT_TASK + n];
        out[((size_t)t * B + b) * OO + o] = s;
    }

    const float* sg = sgw + (size_t)b * E_;
    float s = 0.f;
#pragma unroll
    for (int e = 0; e < E_; e++) s += sg[e] * v[e];
    out[((size_t)3 * B + b) * OO + o] = s;
}

// ---------------------------------------------------------------------------
extern "C" void kernel_launch(void* const* d_in, const int* in_sizes, int n_in,
                              void* d_out, int out_size)
{
    const float* x     = (const float*)d_in[0];
    const float* ew1   = (const float*)d_in[1];
    const float* eb1   = (const float*)d_in[2];
    const float* eg1   = (const float*)d_in[3];
    const float* ebt1  = (const float*)d_in[4];
    const float* ew2   = (const float*)d_in[5];
    const float* eb2   = (const float*)d_in[6];
    const float* eg2   = (const float*)d_in[7];
    const float* ebt2  = (const float*)d_in[8];
    const float* ew3   = (const float*)d_in[9];
    const float* eb3   = (const float*)d_in[10];
    const float* eg3   = (const float*)d_in[11];
    const float* ebt3  = (const float*)d_in[12];
    const float* tg_w1 = (const float*)d_in[13];
    const float* tg_b1 = (const float*)d_in[14];
    const float* tg_w2 = (const float*)d_in[15];
    const float* tg_b2 = (const float*)d_in[16];
    const float* sg_w1 = (const float*)d_in[17];
    const float* sg_b1 = (const float*)d_in[18];
    const float* sg_w2 = (const float*)d_in[19];
    const float* sg_b2 = (const float*)d_in[20];
    float* out = (float*)d_out;

    static h16 *xh = nullptr, *w1t, *w2t, *w3t, *wgt;
    static float *eo, *gw, *sgw;
    if (!xh) {
        cudaGetSymbolAddress((void**)&xh,  g_xh);
        cudaGetSymbolAddress((void**)&w1t, g_w1t);
        cudaGetSymbolAddress((void**)&w2t, g_w2t);
        cudaGetSymbolAddress((void**)&w3t, g_w3t);
        cudaGetSymbolAddress((void**)&wgt, g_wgt);
        cudaGetSymbolAddress((void**)&eo,  g_eo);
        cudaGetSymbolAddress((void**)&gw,  g_gw);
        cudaGetSymbolAddress((void**)&sgw, g_sgw);
        cudaFuncSetAttribute(expert_fused, cudaFuncAttributeMaxDynamicSharedMemorySize,
                             (int)sizeof(SmemT));
        cudaFuncSetAttribute(gate_fused, cudaFuncAttributeMaxDynamicSharedMemorySize,
                             (int)sizeof(GSmem));
    }

    {
        int n4 = (int)((size_t)B * D / 4);
        to_half<<<(n4 + 255) / 256, 256>>>((const float4*)x, (unsigned*)xh, n4);
    }
    build_gate_wt<<<(256 * D + 255) / 256, 256>>>(tg_w1, sg_w1, wgt);

    transpose_half<<<dim3(D / 32, H / 32, E_), 256>>>(ew1, w1t, D, H);
    transpose_half<<<dim3(H / 32, H / 32, E_), 256>>>(ew2, w2t, H, H);
    transpose_half<<<dim3(H / 32, OO / 32, E_), 256>>>(ew3, w3t, H, OO);

    gate_fused<<<B / 64, 256, sizeof(GSmem)>>>(
        xh, wgt, tg_b1, sg_b1, tg_w2, tg_b2, sg_w2, sg_b2, gw, sgw);

    expert_fused<<<dim3(E_, B / 64), 256, sizeof(SmemT)>>>(
        xh, w1t, w2t, w3t,
        eb1, eg1, ebt1, eb2, eg2, ebt2, eb3, eg3, ebt3, eo);

    combine_kernel<<<B / 2, 256>>>(eo, gw, sgw, out);
}

// round 8
// speedup vs baseline: 5.0538x; 1.0228x over previous
#include <cuda_runtime.h>
#include <cuda_fp16.h>
#include <math.h>
#include <stdint.h>

#define B  32768
#define D  512
#define H  256
#define OO 128
#define E_ 10
#define T_ 3
#define G_ 64
#define NS 4
#define NT_TASK 2
#define NE (NS + NT_TASK)

typedef __half h16;

// ---------------- scratch (allocation-free) ----------------
__device__ h16   g_xh[(size_t)B * D];
__device__ h16   g_w1t[(size_t)E_ * H * D];    // [E][N=256][K=512] fp16
__device__ h16   g_w2t[(size_t)E_ * H * H];    // [E][256][256]
__device__ h16   g_w3t[(size_t)E_ * OO * H];   // [E][128][256]
__device__ h16   g_wgt[(size_t)256 * D];       // combined gate W1^T [256][512]
__device__ h16   g_eo[(size_t)E_ * B * OO];    // expert outputs, fp16
__device__ float g_gw[(size_t)T_ * B * NE];
__device__ float g_sgw[(size_t)B * E_];

// ---------------- helpers ----------------
__device__ __forceinline__ void mma_fp16(float* c, const unsigned* a, const unsigned* b) {
    asm volatile(
        "mma.sync.aligned.m16n8k16.row.col.f32.f16.f16.f32 "
        "{%0,%1,%2,%3}, {%4,%5,%6,%7}, {%8,%9}, {%0,%1,%2,%3};\n"
        : "+f"(c[0]), "+f"(c[1]), "+f"(c[2]), "+f"(c[3])
        : "r"(a[0]), "r"(a[1]), "r"(a[2]), "r"(a[3]), "r"(b[0]), "r"(b[1]));
}
__device__ __forceinline__ unsigned pack_h2(h16 a, h16 b) {
    return (unsigned)__half_as_ushort(a) | ((unsigned)__half_as_ushort(b) << 16);
}
__device__ __forceinline__ void cp16(void* s, const void* g) {
    unsigned sa = (unsigned)__cvta_generic_to_shared(s);
    asm volatile("cp.async.cg.shared.global [%0], [%1], 16;\n" :: "r"(sa), "l"(g));
}
__device__ __forceinline__ void cp_commit() { asm volatile("cp.async.commit_group;\n"); }
template <int N2> __device__ __forceinline__ void cp_wait() {
    asm volatile("cp.async.wait_group %0;\n" :: "n"(N2));
}
__device__ __forceinline__ void load_afrag(unsigned* a, const h16* base, int stride, int r, int koff) {
    a[0] = *(const unsigned*)(base + (size_t)r * stride + koff);
    a[1] = *(const unsigned*)(base + (size_t)(r + 8) * stride + koff);
    a[2] = *(const unsigned*)(base + (size_t)r * stride + koff + 8);
    a[3] = *(const unsigned*)(base + (size_t)(r + 8) * stride + koff + 8);
}
__device__ __forceinline__ void load_bfrag(unsigned* b, const h16* base, int stride, int n, int koff) {
    b[0] = *(const unsigned*)(base + (size_t)n * stride + koff);
    b[1] = *(const unsigned*)(base + (size_t)n * stride + koff + 8);
}

// ---------------- prep kernels (merged) ----------------
// blockIdx.x < 16384  : x fp32 -> fp16 (one float4 per thread)
// blockIdx.x >= 16384 : build combined gate W1^T [256][512] fp16
__global__ void prep_x_gate(const float4* __restrict__ x4, unsigned* __restrict__ xh2,
                            const float* __restrict__ tg_w1, const float* __restrict__ sg_w1,
                            h16* __restrict__ wgt)
{
    const int bx = blockIdx.x, tid = threadIdx.x;
    if (bx < 16384) {
        int i = bx * 256 + tid;             // n4 = B*D/4 = 4194304, exactly 16384 blocks
        float4 v = x4[i];
        xh2[i * 2]     = pack_h2(__float2half_rn(v.x), __float2half_rn(v.y));
        xh2[i * 2 + 1] = pack_h2(__float2half_rn(v.z), __float2half_rn(v.w));
    } else {
        int i = (bx - 16384) * 256 + tid;   // over 256*512
        int n = i >> 9, d = i & 511;
        float v;
        if (n < 192) {
            int t = n >> 6, g = n & 63;
            v = tg_w1[((size_t)t * D + d) * G_ + g];
        } else {
            v = sg_w1[(size_t)d * G_ + (n - 192)];
        }
        wgt[(size_t)n * D + d] = __float2half_rn(v);
    }
}

// All three expert-weight transposes in one launch.
// blockIdx.y = e; blockIdx.x: [0,128) W1 tiles, [128,192) W2, [192,224) W3.
__global__ void prep_weights(const float* __restrict__ ew1, const float* __restrict__ ew2,
                             const float* __restrict__ ew3,
                             h16* __restrict__ w1t, h16* __restrict__ w2t, h16* __restrict__ w3t)
{
    __shared__ float t[32][33];
    const int e = blockIdx.y, bx = blockIdx.x, tid = threadIdx.x;
    const float* W; h16* T; int K, N, k0, n0;
    if (bx < 128)      { W = ew1; T = w1t; K = D; N = H;  k0 = (bx & 15) * 32;        n0 = (bx >> 4) * 32; }
    else if (bx < 192) { W = ew2; T = w2t; K = H; N = H;  k0 = ((bx - 128) & 7) * 32; n0 = ((bx - 128) >> 3) * 32; }
    else               { W = ew3; T = w3t; K = H; N = OO; k0 = ((bx - 192) & 7) * 32; n0 = ((bx - 192) >> 3) * 32; }
    const float* We = W + (size_t)e * K * N;
    for (int i = tid; i < 1024; i += 256) {
        int r = i >> 5, c = i & 31;
        t[r][c] = We[(size_t)(k0 + r) * N + n0 + c];
    }
    __syncthreads();
    size_t base = (size_t)e * N * K;
    for (int i = tid; i < 1024; i += 256) {
        int nn = i >> 5, kk = i & 31;
        T[base + (size_t)(n0 + nn) * K + k0 + kk] = __float2half_rn(t[kk][nn]);
    }
}

// ---------------------------------------------------------------------------
// Fused expert tower (single-pass fp16): L1 -> LN -> L2 -> LN -> L3 -> LN.
// ---------------------------------------------------------------------------
struct SmemT {
    h16   sB[2][256][40];  // 40 KB
    h16   sX[2][64][40];   // 10 KB
    h16   sH[64][264];     // 33 KB
    float red[2][64][2];   //  1 KB
};

__global__ void __launch_bounds__(256, 2)
expert_fused(const h16* __restrict__ xh,
             const h16* __restrict__ w1t, const h16* __restrict__ w2t, const h16* __restrict__ w3t,
             const float* __restrict__ eb1, const float* __restrict__ eg1, const float* __restrict__ ebt1,
             const float* __restrict__ eb2, const float* __restrict__ eg2, const float* __restrict__ ebt2,
             const float* __restrict__ eb3, const float* __restrict__ eg3, const float* __restrict__ ebt3,
             h16* __restrict__ eo)
{
    extern __shared__ char raw[];
    SmemT& sm = *reinterpret_cast<SmemT*>(raw);

    const int e   = blockIdx.x;
    const int b0  = blockIdx.y * 64;
    const int tid = threadIdx.x;
    const int wid = tid >> 5, lane = tid & 31;
    const int warp_m = wid & 3, warp_n = wid >> 2;
    const int gr = lane >> 2, tg = lane & 3;
    const int ar = warp_m * 16 + gr;

    const h16* W1 = w1t + (size_t)e * H * D;
    const h16* W2 = w2t + (size_t)e * H * H;
    const h16* W3 = w3t + (size_t)e * OO * H;

    auto loadB = [&](const h16* T, int rows, int K, int buf, int k0) {
        for (int i = tid; i < rows * 4; i += 256) {
            int n = i >> 2, c = i & 3;
            cp16(&sm.sB[buf][n][c * 8], T + (size_t)n * K + k0 + c * 8);
        }
    };
    auto loadX = [&](int buf, int k0) {
        int r = tid >> 2, c = tid & 3;
        cp16(&sm.sX[buf][r][c * 8], xh + (size_t)(b0 + r) * D + k0 + c * 8);
    };

    float acc[16][4];

    // =================== Layer 1 ===================
#pragma unroll
    for (int nt = 0; nt < 16; nt++)
#pragma unroll
        for (int j = 0; j < 4; j++) acc[nt][j] = 0.f;

    int buf = 0;
    loadX(0, 0);
    loadB(W1, 256, D, 0, 0);
    cp_commit();

    for (int ks = 0; ks < 16; ks++) {
        if (ks < 15) { loadX(buf ^ 1, (ks + 1) * 32); loadB(W1, 256, D, buf ^ 1, (ks + 1) * 32); }
        cp_commit();
        cp_wait<1>(); __syncthreads();
#pragma unroll
        for (int ksub = 0; ksub < 2; ksub++) {
            const int koff = ksub * 16 + tg * 2;
            unsigned ah[4];
            load_afrag(ah, &sm.sX[buf][0][0], 40, ar, koff);
#pragma unroll
            for (int nt = 0; nt < 16; nt++) {
                int bc = warp_n * 128 + nt * 8 + gr;
                unsigned bh[2];
                load_bfrag(bh, &sm.sB[buf][0][0], 40, bc, koff);
                mma_fp16(acc[nt], ah, bh);
            }
        }
        __syncthreads();
        buf ^= 1;
    }
    loadB(W2, 256, H, 0, 0);
    cp_commit();

    // ---- epilogue 1 -> sH ----
    {
        const float* be  = eb1  + (size_t)e * H;
        const float* ge  = eg1  + (size_t)e * H;
        const float* bte = ebt1 + (size_t)e * H;
        const int cbase = warp_n * 128 + tg * 2;
        float s0 = 0.f, q0 = 0.f, s1 = 0.f, q1 = 0.f;
#pragma unroll
        for (int nt = 0; nt < 16; nt++) {
            int c = cbase + nt * 8;
            float bv0 = be[c], bv1 = be[c + 1];
            acc[nt][0] += bv0; acc[nt][1] += bv1;
            acc[nt][2] += bv0; acc[nt][3] += bv1;
            s0 += acc[nt][0] + acc[nt][1];
            q0 = fmaf(acc[nt][0], acc[nt][0], fmaf(acc[nt][1], acc[nt][1], q0));
            s1 += acc[nt][2] + acc[nt][3];
            q1 = fmaf(acc[nt][2], acc[nt][2], fmaf(acc[nt][3], acc[nt][3], q1));
        }
#pragma unroll
        for (int off = 1; off <= 2; off <<= 1) {
            s0 += __shfl_xor_sync(0xffffffffu, s0, off);
            q0 += __shfl_xor_sync(0xffffffffu, q0, off);
            s1 += __shfl_xor_sync(0xffffffffu, s1, off);
            q1 += __shfl_xor_sync(0xffffffffu, q1, off);
        }
        __syncthreads();
        if (tg == 0) {
            sm.red[warp_n][ar][0] = s0;     sm.red[warp_n][ar][1] = q0;
            sm.red[warp_n][ar + 8][0] = s1; sm.red[warp_n][ar + 8][1] = q1;
        }
        __syncthreads();
        s0 = sm.red[0][ar][0] + sm.red[1][ar][0];
        q0 = sm.red[0][ar][1] + sm.red[1][ar][1];
        s1 = sm.red[0][ar + 8][0] + sm.red[1][ar + 8][0];
        q1 = sm.red[0][ar + 8][1] + sm.red[1][ar + 8][1];
        const float invN = 1.0f / H;
        float m0 = s0 * invN, m1 = s1 * invN;
        float r0 = rsqrtf(q0 * invN - m0 * m0 + 1e-5f);
        float r1 = rsqrtf(q1 * invN - m1 * m1 + 1e-5f);
#pragma unroll
        for (int nt = 0; nt < 16; nt++) {
            int c = cbase + nt * 8;
            float g0 = ge[c], g1 = ge[c + 1], t0 = bte[c], t1 = bte[c + 1];
            float v00 = fmaxf((acc[nt][0] - m0) * r0 * g0 + t0, 0.f);
            float v01 = fmaxf((acc[nt][1] - m0) * r0 * g1 + t1, 0.f);
            float v10 = fmaxf((acc[nt][2] - m1) * r1 * g0 + t0, 0.f);
            float v11 = fmaxf((acc[nt][3] - m1) * r1 * g1 + t1, 0.f);
            *(unsigned*)&sm.sH[ar][c]     = pack_h2(__float2half_rn(v00), __float2half_rn(v01));
            *(unsigned*)&sm.sH[ar + 8][c] = pack_h2(__float2half_rn(v10), __float2half_rn(v11));
        }
    }

    // =================== Layer 2 ===================
#pragma unroll
    for (int nt = 0; nt < 16; nt++)
#pragma unroll
        for (int j = 0; j < 4; j++) acc[nt][j] = 0.f;

    buf = 0;
    for (int ks = 0; ks < 8; ks++) {
        if (ks < 7) loadB(W2, 256, H, buf ^ 1, (ks + 1) * 32);
        cp_commit();
        cp_wait<1>(); __syncthreads();
#pragma unroll
        for (int ksub = 0; ksub < 2; ksub++) {
            const int koffA = ks * 32 + ksub * 16 + tg * 2;
            const int koffB = ksub * 16 + tg * 2;
            unsigned ah[4];
            load_afrag(ah, &sm.sH[0][0], 264, ar, koffA);
#pragma unroll
            for (int nt = 0; nt < 16; nt++) {
                int bc = warp_n * 128 + nt * 8 + gr;
                unsigned bh[2];
                load_bfrag(bh, &sm.sB[buf][0][0], 40, bc, koffB);
                mma_fp16(acc[nt], ah, bh);
            }
        }
        __syncthreads();
        buf ^= 1;
    }
    loadB(W3, 128, H, 0, 0);
    cp_commit();

    // ---- epilogue 2 -> sH ----
    {
        const float* be  = eb2  + (size_t)e * H;
        const float* ge  = eg2  + (size_t)e * H;
        const float* bte = ebt2 + (size_t)e * H;
        const int cbase = warp_n * 128 + tg * 2;
        float s0 = 0.f, q0 = 0.f, s1 = 0.f, q1 = 0.f;
#pragma unroll
        for (int nt = 0; nt < 16; nt++) {
            int c = cbase + nt * 8;
            float bv0 = be[c], bv1 = be[c + 1];
            acc[nt][0] += bv0; acc[nt][1] += bv1;
            acc[nt][2] += bv0; acc[nt][3] += bv1;
            s0 += acc[nt][0] + acc[nt][1];
            q0 = fmaf(acc[nt][0], acc[nt][0], fmaf(acc[nt][1], acc[nt][1], q0));
            s1 += acc[nt][2] + acc[nt][3];
            q1 = fmaf(acc[nt][2], acc[nt][2], fmaf(acc[nt][3], acc[nt][3], q1));
        }
#pragma unroll
        for (int off = 1; off <= 2; off <<= 1) {
            s0 += __shfl_xor_sync(0xffffffffu, s0, off);
            q0 += __shfl_xor_sync(0xffffffffu, q0, off);
            s1 += __shfl_xor_sync(0xffffffffu, s1, off);
            q1 += __shfl_xor_sync(0xffffffffu, q1, off);
        }
        __syncthreads();
        if (tg == 0) {
            sm.red[warp_n][ar][0] = s0;     sm.red[warp_n][ar][1] = q0;
            sm.red[warp_n][ar + 8][0] = s1; sm.red[warp_n][ar + 8][1] = q1;
        }
        __syncthreads();
        s0 = sm.red[0][ar][0] + sm.red[1][ar][0];
        q0 = sm.red[0][ar][1] + sm.red[1][ar][1];
        s1 = sm.red[0][ar + 8][0] + sm.red[1][ar + 8][0];
        q1 = sm.red[0][ar + 8][1] + sm.red[1][ar + 8][1];
        const float invN = 1.0f / H;
        float m0 = s0 * invN, m1 = s1 * invN;
        float r0 = rsqrtf(q0 * invN - m0 * m0 + 1e-5f);
        float r1 = rsqrtf(q1 * invN - m1 * m1 + 1e-5f);
        __syncthreads();
#pragma unroll
        for (int nt = 0; nt < 16; nt++) {
            int c = cbase + nt * 8;
            float g0 = ge[c], g1 = ge[c + 1], t0 = bte[c], t1 = bte[c + 1];
            float v00 = fmaxf((acc[nt][0] - m0) * r0 * g0 + t0, 0.f);
            float v01 = fmaxf((acc[nt][1] - m0) * r0 * g1 + t1, 0.f);
            float v10 = fmaxf((acc[nt][2] - m1) * r1 * g0 + t0, 0.f);
            float v11 = fmaxf((acc[nt][3] - m1) * r1 * g1 + t1, 0.f);
            *(unsigned*)&sm.sH[ar][c]     = pack_h2(__float2half_rn(v00), __float2half_rn(v01));
            *(unsigned*)&sm.sH[ar + 8][c] = pack_h2(__float2half_rn(v10), __float2half_rn(v11));
        }
    }

    // =================== Layer 3 ===================
#pragma unroll
    for (int nt = 0; nt < 8; nt++)
#pragma unroll
        for (int j = 0; j < 4; j++) acc[nt][j] = 0.f;

    buf = 0;
    for (int ks = 0; ks < 8; ks++) {
        if (ks < 7) loadB(W3, 128, H, buf ^ 1, (ks + 1) * 32);
        cp_commit();
        cp_wait<1>(); __syncthreads();
#pragma unroll
        for (int ksub = 0; ksub < 2; ksub++) {
            const int koffA = ks * 32 + ksub * 16 + tg * 2;
            const int koffB = ksub * 16 + tg * 2;
            unsigned ah[4];
            load_afrag(ah, &sm.sH[0][0], 264, ar, koffA);
#pragma unroll
            for (int nt = 0; nt < 8; nt++) {
                int bc = warp_n * 64 + nt * 8 + gr;
                unsigned bh[2];
                load_bfrag(bh, &sm.sB[buf][0][0], 40, bc, koffB);
                mma_fp16(acc[nt], ah, bh);
            }
        }
        __syncthreads();
        buf ^= 1;
    }

    // ---- epilogue 3 -> eo (fp16) ----
    {
        const float* be  = eb3  + (size_t)e * OO;
        const float* ge  = eg3  + (size_t)e * OO;
        const float* bte = ebt3 + (size_t)e * OO;
        const int cbase = warp_n * 64 + tg * 2;
        float s0 = 0.f, q0 = 0.f, s1 = 0.f, q1 = 0.f;
#pragma unroll
        for (int nt = 0; nt < 8; nt++) {
            int c = cbase + nt * 8;
            float bv0 = be[c], bv1 = be[c + 1];
            acc[nt][0] += bv0; acc[nt][1] += bv1;
            acc[nt][2] += bv0; acc[nt][3] += bv1;
            s0 += acc[nt][0] + acc[nt][1];
            q0 = fmaf(acc[nt][0], acc[nt][0], fmaf(acc[nt][1], acc[nt][1], q0));
            s1 += acc[nt][2] + acc[nt][3];
            q1 = fmaf(acc[nt][2], acc[nt][2], fmaf(acc[nt][3], acc[nt][3], q1));
        }
#pragma unroll
        for (int off = 1; off <= 2; off <<= 1) {
            s0 += __shfl_xor_sync(0xffffffffu, s0, off);
            q0 += __shfl_xor_sync(0xffffffffu, q0, off);
            s1 += __shfl_xor_sync(0xffffffffu, s1, off);
            q1 += __shfl_xor_sync(0xffffffffu, q1, off);
        }
        __syncthreads();
        if (tg == 0) {
            sm.red[warp_n][ar][0] = s0;     sm.red[warp_n][ar][1] = q0;
            sm.red[warp_n][ar + 8][0] = s1; sm.red[warp_n][ar + 8][1] = q1;
        }
        __syncthreads();
        s0 = sm.red[0][ar][0] + sm.red[1][ar][0];
        q0 = sm.red[0][ar][1] + sm.red[1][ar][1];
        s1 = sm.red[0][ar + 8][0] + sm.red[1][ar + 8][0];
        q1 = sm.red[0][ar + 8][1] + sm.red[1][ar + 8][1];
        const float invN = 1.0f / OO;
        float m0 = s0 * invN, m1 = s1 * invN;
        float r0 = rsqrtf(q0 * invN - m0 * m0 + 1e-5f);
        float r1 = rsqrtf(q1 * invN - m1 * m1 + 1e-5f);
        size_t row0 = ((size_t)e * B + b0 + ar) * OO;
        size_t row1 = row0 + (size_t)8 * OO;
#pragma unroll
        for (int nt = 0; nt < 8; nt++) {
            int c = cbase + nt * 8;
            float g0 = ge[c], g1 = ge[c + 1], t0 = bte[c], t1 = bte[c + 1];
            float v00 = fmaxf((acc[nt][0] - m0) * r0 * g0 + t0, 0.f);
            float v01 = fmaxf((acc[nt][1] - m0) * r0 * g1 + t1, 0.f);
            float v10 = fmaxf((acc[nt][2] - m1) * r1 * g0 + t0, 0.f);
            float v11 = fmaxf((acc[nt][3] - m1) * r1 * g1 + t1, 0.f);
            *(unsigned*)&eo[row0 + c] = pack_h2(__float2half_rn(v00), __float2half_rn(v01));
            *(unsigned*)&eo[row1 + c] = pack_h2(__float2half_rn(v10), __float2half_rn(v11));
        }
    }
}

// ---------------------------------------------------------------------------
// Fused gates: one GEMM x[64,512] @ Wg^T[256,512] -> gh[64,256], then all
// task softmaxes + shared softmax in-block.
// ---------------------------------------------------------------------------
struct GSmem {
    h16   sB[2][256][40];      // 40 KB
    h16   sX[2][64][40];       // 10 KB
    h16   ghs[64][266];        // 33.25 KB
    float w2s[T_ * G_ * NE];
    float sw2s[G_ * E_];
    float b1s[256];
    float b2s[T_ * NE + E_];
};

__global__ void __launch_bounds__(256, 2)
gate_fused(const h16* __restrict__ xh, const h16* __restrict__ wgt,
           const float* __restrict__ tg_b1, const float* __restrict__ sg_b1,
           const float* __restrict__ tg_w2, const float* __restrict__ tg_b2,
           const float* __restrict__ sg_w2, const float* __restrict__ sg_b2,
           float* __restrict__ gw, float* __restrict__ sgw)
{
    extern __shared__ char raw[];
    GSmem& sm = *reinterpret_cast<GSmem*>(raw);

    const int b0  = blockIdx.x * 64;
    const int tid = threadIdx.x;
    const int wid = tid >> 5, lane = tid & 31;
    const int warp_m = wid & 3, warp_n = wid >> 2;
    const int gr = lane >> 2, tg = lane & 3;
    const int ar = warp_m * 16 + gr;

    for (int i = tid; i < T_ * G_ * NE; i += 256) sm.w2s[i] = tg_w2[i];
    for (int i = tid; i < G_ * E_; i += 256) sm.sw2s[i] = sg_w2[i];
    sm.b1s[tid] = (tid < 192) ? tg_b1[tid] : sg_b1[tid - 192];
    if (tid < T_ * NE) sm.b2s[tid] = tg_b2[tid];
    else if (tid < T_ * NE + E_) sm.b2s[tid] = sg_b2[tid - T_ * NE];

    auto loadB = [&](int buf, int k0) {
        for (int i = tid; i < 256 * 4; i += 256) {
            int n = i >> 2, c = i & 3;
            cp16(&sm.sB[buf][n][c * 8], wgt + (size_t)n * D + k0 + c * 8);
        }
    };
    auto loadX = [&](int buf, int k0) {
        int r = tid >> 2, c = tid & 3;
        cp16(&sm.sX[buf][r][c * 8], xh + (size_t)(b0 + r) * D + k0 + c * 8);
    };

    float acc[16][4];
#pragma unroll
    for (int nt = 0; nt < 16; nt++)
#pragma unroll
        for (int j = 0; j < 4; j++) acc[nt][j] = 0.f;

    int buf = 0;
    loadX(0, 0);
    loadB(0, 0);
    cp_commit();

    for (int ks = 0; ks < 16; ks++) {
        if (ks < 15) { loadX(buf ^ 1, (ks + 1) * 32); loadB(buf ^ 1, (ks + 1) * 32); }
        cp_commit();
        cp_wait<1>(); __syncthreads();
#pragma unroll
        for (int ksub = 0; ksub < 2; ksub++) {
            const int koff = ksub * 16 + tg * 2;
            unsigned ah[4];
            load_afrag(ah, &sm.sX[buf][0][0], 40, ar, koff);
#pragma unroll
            for (int nt = 0; nt < 16; nt++) {
                int bc = warp_n * 128 + nt * 8 + gr;
                unsigned bh[2];
                load_bfrag(bh, &sm.sB[buf][0][0], 40, bc, koff);
                mma_fp16(acc[nt], ah, bh);
            }
        }
        __syncthreads();
        buf ^= 1;
    }

    {
        const int cbase = warp_n * 128 + tg * 2;
#pragma unroll
        for (int nt = 0; nt < 16; nt++) {
            int c = cbase + nt * 8;
            float bv0 = sm.b1s[c], bv1 = sm.b1s[c + 1];
            float v00 = fmaxf(acc[nt][0] + bv0, 0.f);
            float v01 = fmaxf(acc[nt][1] + bv1, 0.f);
            float v10 = fmaxf(acc[nt][2] + bv0, 0.f);
            float v11 = fmaxf(acc[nt][3] + bv1, 0.f);
            *(unsigned*)&sm.ghs[ar][c]     = pack_h2(__float2half_rn(v00), __float2half_rn(v01));
            *(unsigned*)&sm.ghs[ar + 8][c] = pack_h2(__float2half_rn(v10), __float2half_rn(v11));
        }
    }
    __syncthreads();

    if (tid < 192) {
        const int row = tid & 63, t = tid >> 6;
        float lg[NE];
#pragma unroll
        for (int j = 0; j < NE; j++) lg[j] = sm.b2s[t * NE + j];
        for (int g = 0; g < G_; g++) {
            float gv = __half2float(sm.ghs[row][t * 64 + g]);
            const float* w = &sm.w2s[(t * G_ + g) * NE];
#pragma unroll
            for (int j = 0; j < NE; j++) lg[j] = fmaf(gv, w[j], lg[j]);
        }
        float mx = -1e30f;
#pragma unroll
        for (int j = 0; j < NE; j++) mx = fmaxf(mx, lg[j]);
        float sum = 0.f;
#pragma unroll
        for (int j = 0; j < NE; j++) { lg[j] = __expf(lg[j] - mx); sum += lg[j]; }
        float inv = 1.0f / sum;
#pragma unroll
        for (int j = 0; j < NE; j++)
            gw[((size_t)t * B + b0 + row) * NE + j] = lg[j] * inv;
    } else {
        const int row = tid - 192;
        float lg[E_];
#pragma unroll
        for (int j = 0; j < E_; j++) lg[j] = sm.b2s[T_ * NE + j];
        for (int g = 0; g < G_; g++) {
            float gv = __half2float(sm.ghs[row][192 + g]);
            const float* w = &sm.sw2s[g * E_];
#pragma unroll
            for (int j = 0; j < E_; j++) lg[j] = fmaf(gv, w[j], lg[j]);
        }
        float mx = -1e30f;
#pragma unroll
        for (int j = 0; j < E_; j++) mx = fmaxf(mx, lg[j]);
        float sum = 0.f;
#pragma unroll
        for (int j = 0; j < E_; j++) { lg[j] = __expf(lg[j] - mx); sum += lg[j]; }
        float inv = 1.0f / sum;
#pragma unroll
        for (int j = 0; j < E_; j++)
            sgw[(size_t)(b0 + row) * E_ + j] = lg[j] * inv;
    }
}

// ---------------------------------------------------------------------------
__global__ void __launch_bounds__(256)
combine_kernel(const h16* __restrict__ eo, const float* __restrict__ gw,
               const float* __restrict__ sgw, float* __restrict__ out)
{
    const int b = blockIdx.x * 2 + (threadIdx.x >> 7);
    const int o = threadIdx.x & 127;

    float v[E_];
#pragma unroll
    for (int e = 0; e < E_; e++)
        v[e] = __half2float(eo[((size_t)e * B + b) * OO + o]);

#pragma unroll
    for (int t = 0; t < T_; t++) {
        const float* g = gw + ((size_t)t * B + b) * NE;
        float s = 0.f;
#pragma unroll
        for (int j = 0; j < NS; j++) s += g[j] * v[j];
#pragma unroll
        for (int n = 0; n < NT_TASK; n++) s += g[NS + n] * v[NS + t * NT_TASK + n];
        out[((size_t)t * B + b) * OO + o] = s;
    }

    const float* sg = sgw + (size_t)b * E_;
    float s = 0.f;
#pragma unroll
    for (int e = 0; e < E_; e++) s += sg[e] * v[e];
    out[((size_t)3 * B + b) * OO + o] = s;
}

// ---------------------------------------------------------------------------
extern "C" void kernel_launch(void* const* d_in, const int* in_sizes, int n_in,
                              void* d_out, int out_size)
{
    const float* x     = (const float*)d_in[0];
    const float* ew1   = (const float*)d_in[1];
    const float* eb1   = (const float*)d_in[2];
    const float* eg1   = (const float*)d_in[3];
    const float* ebt1  = (const float*)d_in[4];
    const float* ew2   = (const float*)d_in[5];
    const float* eb2   = (const float*)d_in[6];
    const float* eg2   = (const float*)d_in[7];
    const float* ebt2  = (const float*)d_in[8];
    const float* ew3   = (const float*)d_in[9];
    const float* eb3   = (const float*)d_in[10];
    const float* eg3   = (const float*)d_in[11];
    const float* ebt3  = (const float*)d_in[12];
    const float* tg_w1 = (const float*)d_in[13];
    const float* tg_b1 = (const float*)d_in[14];
    const float* tg_w2 = (const float*)d_in[15];
    const float* tg_b2 = (const float*)d_in[16];
    const float* sg_w1 = (const float*)d_in[17];
    const float* sg_b1 = (const float*)d_in[18];
    const float* sg_w2 = (const float*)d_in[19];
    const float* sg_b2 = (const float*)d_in[20];
    float* out = (float*)d_out;

    static h16 *xh = nullptr, *w1t, *w2t, *w3t, *wgt, *eo;
    static float *gw, *sgw;
    if (!xh) {
        cudaGetSymbolAddress((void**)&xh,  g_xh);
        cudaGetSymbolAddress((void**)&w1t, g_w1t);
        cudaGetSymbolAddress((void**)&w2t, g_w2t);
        cudaGetSymbolAddress((void**)&w3t, g_w3t);
        cudaGetSymbolAddress((void**)&wgt, g_wgt);
        cudaGetSymbolAddress((void**)&eo,  g_eo);
        cudaGetSymbolAddress((void**)&gw,  g_gw);
        cudaGetSymbolAddress((void**)&sgw, g_sgw);
        cudaFuncSetAttribute(expert_fused, cudaFuncAttributeMaxDynamicSharedMemorySize,
                             (int)sizeof(SmemT));
        cudaFuncSetAttribute(gate_fused, cudaFuncAttributeMaxDynamicSharedMemorySize,
                             (int)sizeof(GSmem));
    }

    // prep (2 launches)
    prep_x_gate<<<16384 + 512, 256>>>((const float4*)x, (unsigned*)xh, tg_w1, sg_w1, wgt);
    prep_weights<<<dim3(224, E_), 256>>>(ew1, ew2, ew3, w1t, w2t, w3t);

    gate_fused<<<B / 64, 256, sizeof(GSmem)>>>(
        xh, wgt, tg_b1, sg_b1, tg_w2, tg_b2, sg_w2, sg_b2, gw, sgw);

    expert_fused<<<dim3(E_, B / 64), 256, sizeof(SmemT)>>>(
        xh, w1t, w2t, w3t,
        eb1, eg1, ebt1, eb2, eg2, ebt2, eb3, eg3, ebt3, eo);

    combine_kernel<<<B / 2, 256>>>(eo, gw, sgw, out);
}

// round 9
// speedup vs baseline: 5.4524x; 1.0789x over previous
#include <cuda_runtime.h>
#include <cuda_fp16.h>
#include <math.h>
#include <stdint.h>

#define B  32768
#define D  512
#define H  256
#define OO 128
#define E_ 10
#define T_ 3
#define G_ 64
#define NS 4
#define NT_TASK 2
#define NE (NS + NT_TASK)

typedef __half h16;

// ---------------- scratch (allocation-free) ----------------
__device__ h16   g_xh[(size_t)B * D];
__device__ h16   g_w1t[(size_t)E_ * H * D];    // [E][N=256][K=512] fp16
__device__ h16   g_w2t[(size_t)E_ * H * H];    // [E][256][256]
__device__ h16   g_w3t[(size_t)E_ * OO * H];   // [E][128][256]
__device__ h16   g_wgt[(size_t)256 * D];       // combined gate W1^T [256][512]
__device__ h16   g_eo[(size_t)E_ * B * OO];    // expert outputs, fp16
__device__ float g_gw[(size_t)T_ * B * NE];
__device__ float g_sgw[(size_t)B * E_];

// ---------------- helpers ----------------
__device__ __forceinline__ void mma_fp16(float* c, const unsigned* a, const unsigned* b) {
    asm volatile(
        "mma.sync.aligned.m16n8k16.row.col.f32.f16.f16.f32 "
        "{%0,%1,%2,%3}, {%4,%5,%6,%7}, {%8,%9}, {%0,%1,%2,%3};\n"
        : "+f"(c[0]), "+f"(c[1]), "+f"(c[2]), "+f"(c[3])
        : "r"(a[0]), "r"(a[1]), "r"(a[2]), "r"(a[3]), "r"(b[0]), "r"(b[1]));
}
__device__ __forceinline__ unsigned pack_h2(h16 a, h16 b) {
    return (unsigned)__half_as_ushort(a) | ((unsigned)__half_as_ushort(b) << 16);
}
__device__ __forceinline__ void cp16(void* s, const void* g) {
    unsigned sa = (unsigned)__cvta_generic_to_shared(s);
    asm volatile("cp.async.cg.shared.global [%0], [%1], 16;\n" :: "r"(sa), "l"(g));
}
__device__ __forceinline__ void cp_commit() { asm volatile("cp.async.commit_group;\n"); }
template <int N2> __device__ __forceinline__ void cp_wait() {
    asm volatile("cp.async.wait_group %0;\n" :: "n"(N2));
}
__device__ __forceinline__ unsigned lds_u32(const void* p) {
    return (unsigned)__cvta_generic_to_shared(p);
}
__device__ __forceinline__ void ldsm_x4(unsigned* r, unsigned addr) {
    asm volatile("ldmatrix.sync.aligned.m8n8.x4.shared.b16 {%0,%1,%2,%3}, [%4];"
        : "=r"(r[0]), "=r"(r[1]), "=r"(r[2]), "=r"(r[3]) : "r"(addr));
}

// ---------------- prep kernels (merged) ----------------
__global__ void prep_x_gate(const float4* __restrict__ x4, unsigned* __restrict__ xh2,
                            const float* __restrict__ tg_w1, const float* __restrict__ sg_w1,
                            h16* __restrict__ wgt)
{
    const int bx = blockIdx.x, tid = threadIdx.x;
    if (bx < 16384) {
        int i = bx * 256 + tid;
        float4 v = x4[i];
        xh2[i * 2]     = pack_h2(__float2half_rn(v.x), __float2half_rn(v.y));
        xh2[i * 2 + 1] = pack_h2(__float2half_rn(v.z), __float2half_rn(v.w));
    } else {
        int i = (bx - 16384) * 256 + tid;
        int n = i >> 9, d = i & 511;
        float v;
        if (n < 192) {
            int t = n >> 6, g = n & 63;
            v = tg_w1[((size_t)t * D + d) * G_ + g];
        } else {
            v = sg_w1[(size_t)d * G_ + (n - 192)];
        }
        wgt[(size_t)n * D + d] = __float2half_rn(v);
    }
}

__global__ void prep_weights(const float* __restrict__ ew1, const float* __restrict__ ew2,
                             const float* __restrict__ ew3,
                             h16* __restrict__ w1t, h16* __restrict__ w2t, h16* __restrict__ w3t)
{
    __shared__ float t[32][33];
    const int e = blockIdx.y, bx = blockIdx.x, tid = threadIdx.x;
    const float* W; h16* T; int K, N, k0, n0;
    if (bx < 128)      { W = ew1; T = w1t; K = D; N = H;  k0 = (bx & 15) * 32;        n0 = (bx >> 4) * 32; }
    else if (bx < 192) { W = ew2; T = w2t; K = H; N = H;  k0 = ((bx - 128) & 7) * 32; n0 = ((bx - 128) >> 3) * 32; }
    else               { W = ew3; T = w3t; K = H; N = OO; k0 = ((bx - 192) & 7) * 32; n0 = ((bx - 192) >> 3) * 32; }
    const float* We = W + (size_t)e * K * N;
    for (int i = tid; i < 1024; i += 256) {
        int r = i >> 5, c = i & 31;
        t[r][c] = We[(size_t)(k0 + r) * N + n0 + c];
    }
    __syncthreads();
    size_t base = (size_t)e * N * K;
    for (int i = tid; i < 1024; i += 256) {
        int nn = i >> 5, kk = i & 31;
        T[base + (size_t)(n0 + nn) * K + k0 + kk] = __float2half_rn(t[kk][nn]);
    }
}

// ---------------------------------------------------------------------------
// Fused expert tower (single-pass fp16) with ldmatrix fragment loads.
// ---------------------------------------------------------------------------
struct SmemT {
    h16   sB[2][256][40];  // 40 KB
    h16   sX[2][64][40];   // 10 KB
    h16   sH[64][264];     // 33 KB
    float red[2][64][2];   //  1 KB
};

__global__ void __launch_bounds__(256, 2)
expert_fused(const h16* __restrict__ xh,
             const h16* __restrict__ w1t, const h16* __restrict__ w2t, const h16* __restrict__ w3t,
             const float* __restrict__ eb1, const float* __restrict__ eg1, const float* __restrict__ ebt1,
             const float* __restrict__ eb2, const float* __restrict__ eg2, const float* __restrict__ ebt2,
             const float* __restrict__ eb3, const float* __restrict__ eg3, const float* __restrict__ ebt3,
             h16* __restrict__ eo)
{
    extern __shared__ char raw[];
    SmemT& sm = *reinterpret_cast<SmemT*>(raw);

    const int e   = blockIdx.x;
    const int b0  = blockIdx.y * 64;
    const int tid = threadIdx.x;
    const int wid = tid >> 5, lane = tid & 31;
    const int warp_m = wid & 3, warp_n = wid >> 2;
    const int gr = lane >> 2, tg = lane & 3;
    const int ar = warp_m * 16 + gr;
    const int l8 = lane & 7, lm = lane >> 3;       // ldmatrix row / matrix id
    const int a_row = warp_m * 16 + (lm & 1) * 8 + l8;   // A-frag ldmatrix row
    const int a_kx  = (lm >> 1) * 8;                      // A-frag k sub-offset
    const int b_row8 = (lm >> 1) * 8 + l8;                // B-frag row within pair
    const int b_kx   = (lm & 1) * 8;                      // B-frag k sub-offset

    const h16* W1 = w1t + (size_t)e * H * D;
    const h16* W2 = w2t + (size_t)e * H * H;
    const h16* W3 = w3t + (size_t)e * OO * H;

    auto loadB = [&](const h16* T, int rows, int K, int buf, int k0) {
        for (int i = tid; i < rows * 4; i += 256) {
            int n = i >> 2, c = i & 3;
            cp16(&sm.sB[buf][n][c * 8], T + (size_t)n * K + k0 + c * 8);
        }
    };
    auto loadX = [&](int buf, int k0) {
        int r = tid >> 2, c = tid & 3;
        cp16(&sm.sX[buf][r][c * 8], xh + (size_t)(b0 + r) * D + k0 + c * 8);
    };

    float acc[16][4];

    // =================== Layer 1 ===================
#pragma unroll
    for (int nt = 0; nt < 16; nt++)
#pragma unroll
        for (int j = 0; j < 4; j++) acc[nt][j] = 0.f;

    int buf = 0;
    loadX(0, 0);
    loadB(W1, 256, D, 0, 0);
    cp_commit();

    for (int ks = 0; ks < 16; ks++) {
        if (ks < 15) { loadX(buf ^ 1, (ks + 1) * 32); loadB(W1, 256, D, buf ^ 1, (ks + 1) * 32); }
        cp_commit();
        cp_wait<1>(); __syncthreads();
#pragma unroll
        for (int ksub = 0; ksub < 2; ksub++) {
            const int koff = ksub * 16;
            unsigned ah[4];
            ldsm_x4(ah, lds_u32(&sm.sX[buf][a_row][koff + a_kx]));
#pragma unroll
            for (int np = 0; np < 8; np++) {
                unsigned bb[4];
                ldsm_x4(bb, lds_u32(&sm.sB[buf][warp_n * 128 + np * 16 + b_row8][koff + b_kx]));
                mma_fp16(acc[2 * np],     ah, bb);
                mma_fp16(acc[2 * np + 1], ah, bb + 2);
            }
        }
        __syncthreads();
        buf ^= 1;
    }
    loadB(W2, 256, H, 0, 0);
    cp_commit();

    // ---- epilogue 1 -> sH ----
    {
        const float* be  = eb1  + (size_t)e * H;
        const float* ge  = eg1  + (size_t)e * H;
        const float* bte = ebt1 + (size_t)e * H;
        const int cbase = warp_n * 128 + tg * 2;
        float s0 = 0.f, q0 = 0.f, s1 = 0.f, q1 = 0.f;
#pragma unroll
        for (int nt = 0; nt < 16; nt++) {
            int c = cbase + nt * 8;
            float bv0 = be[c], bv1 = be[c + 1];
            acc[nt][0] += bv0; acc[nt][1] += bv1;
            acc[nt][2] += bv0; acc[nt][3] += bv1;
            s0 += acc[nt][0] + acc[nt][1];
            q0 = fmaf(acc[nt][0], acc[nt][0], fmaf(acc[nt][1], acc[nt][1], q0));
            s1 += acc[nt][2] + acc[nt][3];
            q1 = fmaf(acc[nt][2], acc[nt][2], fmaf(acc[nt][3], acc[nt][3], q1));
        }
#pragma unroll
        for (int off = 1; off <= 2; off <<= 1) {
            s0 += __shfl_xor_sync(0xffffffffu, s0, off);
            q0 += __shfl_xor_sync(0xffffffffu, q0, off);
            s1 += __shfl_xor_sync(0xffffffffu, s1, off);
            q1 += __shfl_xor_sync(0xffffffffu, q1, off);
        }
        __syncthreads();
        if (tg == 0) {
            sm.red[warp_n][ar][0] = s0;     sm.red[warp_n][ar][1] = q0;
            sm.red[warp_n][ar + 8][0] = s1; sm.red[warp_n][ar + 8][1] = q1;
        }
        __syncthreads();
        s0 = sm.red[0][ar][0] + sm.red[1][ar][0];
        q0 = sm.red[0][ar][1] + sm.red[1][ar][1];
        s1 = sm.red[0][ar + 8][0] + sm.red[1][ar + 8][0];
        q1 = sm.red[0][ar + 8][1] + sm.red[1][ar + 8][1];
        const float invN = 1.0f / H;
        float m0 = s0 * invN, m1 = s1 * invN;
        float r0 = rsqrtf(q0 * invN - m0 * m0 + 1e-5f);
        float r1 = rsqrtf(q1 * invN - m1 * m1 + 1e-5f);
#pragma unroll
        for (int nt = 0; nt < 16; nt++) {
            int c = cbase + nt * 8;
            float g0 = ge[c], g1 = ge[c + 1], t0 = bte[c], t1 = bte[c + 1];
            float v00 = fmaxf((acc[nt][0] - m0) * r0 * g0 + t0, 0.f);
            float v01 = fmaxf((acc[nt][1] - m0) * r0 * g1 + t1, 0.f);
            float v10 = fmaxf((acc[nt][2] - m1) * r1 * g0 + t0, 0.f);
            float v11 = fmaxf((acc[nt][3] - m1) * r1 * g1 + t1, 0.f);
            *(unsigned*)&sm.sH[ar][c]     = pack_h2(__float2half_rn(v00), __float2half_rn(v01));
            *(unsigned*)&sm.sH[ar + 8][c] = pack_h2(__float2half_rn(v10), __float2half_rn(v11));
        }
    }

    // =================== Layer 2 ===================
#pragma unroll
    for (int nt = 0; nt < 16; nt++)
#pragma unroll
        for (int j = 0; j < 4; j++) acc[nt][j] = 0.f;

    buf = 0;
    for (int ks = 0; ks < 8; ks++) {
        if (ks < 7) loadB(W2, 256, H, buf ^ 1, (ks + 1) * 32);
        cp_commit();
        cp_wait<1>(); __syncthreads();
#pragma unroll
        for (int ksub = 0; ksub < 2; ksub++) {
            const int koffA = ks * 32 + ksub * 16;
            const int koffB = ksub * 16;
            unsigned ah[4];
            ldsm_x4(ah, lds_u32(&sm.sH[a_row][koffA + a_kx]));
#pragma unroll
            for (int np = 0; np < 8; np++) {
                unsigned bb[4];
                ldsm_x4(bb, lds_u32(&sm.sB[buf][warp_n * 128 + np * 16 + b_row8][koffB + b_kx]));
                mma_fp16(acc[2 * np],     ah, bb);
                mma_fp16(acc[2 * np + 1], ah, bb + 2);
            }
        }
        __syncthreads();
        buf ^= 1;
    }
    loadB(W3, 128, H, 0, 0);
    cp_commit();

    // ---- epilogue 2 -> sH ----
    {
        const float* be  = eb2  + (size_t)e * H;
        const float* ge  = eg2  + (size_t)e * H;
        const float* bte = ebt2 + (size_t)e * H;
        const int cbase = warp_n * 128 + tg * 2;
        float s0 = 0.f, q0 = 0.f, s1 = 0.f, q1 = 0.f;
#pragma unroll
        for (int nt = 0; nt < 16; nt++) {
            int c = cbase + nt * 8;
            float bv0 = be[c], bv1 = be[c + 1];
            acc[nt][0] += bv0; acc[nt][1] += bv1;
            acc[nt][2] += bv0; acc[nt][3] += bv1;
            s0 += acc[nt][0] + acc[nt][1];
            q0 = fmaf(acc[nt][0], acc[nt][0], fmaf(acc[nt][1], acc[nt][1], q0));
            s1 += acc[nt][2] + acc[nt][3];
            q1 = fmaf(acc[nt][2], acc[nt][2], fmaf(acc[nt][3], acc[nt][3], q1));
        }
#pragma unroll
        for (int off = 1; off <= 2; off <<= 1) {
            s0 += __shfl_xor_sync(0xffffffffu, s0, off);
            q0 += __shfl_xor_sync(0xffffffffu, q0, off);
            s1 += __shfl_xor_sync(0xffffffffu, s1, off);
            q1 += __shfl_xor_sync(0xffffffffu, q1, off);
        }
        __syncthreads();
        if (tg == 0) {
            sm.red[warp_n][ar][0] = s0;     sm.red[warp_n][ar][1] = q0;
            sm.red[warp_n][ar + 8][0] = s1; sm.red[warp_n][ar + 8][1] = q1;
        }
        __syncthreads();
        s0 = sm.red[0][ar][0] + sm.red[1][ar][0];
        q0 = sm.red[0][ar][1] + sm.red[1][ar][1];
        s1 = sm.red[0][ar + 8][0] + sm.red[1][ar + 8][0];
        q1 = sm.red[0][ar + 8][1] + sm.red[1][ar + 8][1];
        const float invN = 1.0f / H;
        float m0 = s0 * invN, m1 = s1 * invN;
        float r0 = rsqrtf(q0 * invN - m0 * m0 + 1e-5f);
        float r1 = rsqrtf(q1 * invN - m1 * m1 + 1e-5f);
        __syncthreads();
#pragma unroll
        for (int nt = 0; nt < 16; nt++) {
            int c = cbase + nt * 8;
            float g0 = ge[c], g1 = ge[c + 1], t0 = bte[c], t1 = bte[c + 1];
            float v00 = fmaxf((acc[nt][0] - m0) * r0 * g0 + t0, 0.f);
            float v01 = fmaxf((acc[nt][1] - m0) * r0 * g1 + t1, 0.f);
            float v10 = fmaxf((acc[nt][2] - m1) * r1 * g0 + t0, 0.f);
            float v11 = fmaxf((acc[nt][3] - m1) * r1 * g1 + t1, 0.f);
            *(unsigned*)&sm.sH[ar][c]     = pack_h2(__float2half_rn(v00), __float2half_rn(v01));
            *(unsigned*)&sm.sH[ar + 8][c] = pack_h2(__float2half_rn(v10), __float2half_rn(v11));
        }
    }

    // =================== Layer 3 ===================
#pragma unroll
    for (int nt = 0; nt < 8; nt++)
#pragma unroll
        for (int j = 0; j < 4; j++) acc[nt][j] = 0.f;

    buf = 0;
    for (int ks = 0; ks < 8; ks++) {
        if (ks < 7) loadB(W3, 128, H, buf ^ 1, (ks + 1) * 32);
        cp_commit();
        cp_wait<1>(); __syncthreads();
#pragma unroll
        for (int ksub = 0; ksub < 2; ksub++) {
            const int koffA = ks * 32 + ksub * 16;
            const int koffB = ksub * 16;
            unsigned ah[4];
            ldsm_x4(ah, lds_u32(&sm.sH[a_row][koffA + a_kx]));
#pragma unroll
            for (int np = 0; np < 4; np++) {
                unsigned bb[4];
                ldsm_x4(bb, lds_u32(&sm.sB[buf][warp_n * 64 + np * 16 + b_row8][koffB + b_kx]));
                mma_fp16(acc[2 * np],     ah, bb);
                mma_fp16(acc[2 * np + 1], ah, bb + 2);
            }
        }
        __syncthreads();
        buf ^= 1;
    }

    // ---- epilogue 3 -> eo (fp16) ----
    {
        const float* be  = eb3  + (size_t)e * OO;
        const float* ge  = eg3  + (size_t)e * OO;
        const float* bte = ebt3 + (size_t)e * OO;
        const int cbase = warp_n * 64 + tg * 2;
        float s0 = 0.f, q0 = 0.f, s1 = 0.f, q1 = 0.f;
#pragma unroll
        for (int nt = 0; nt < 8; nt++) {
            int c = cbase + nt * 8;
            float bv0 = be[c], bv1 = be[c + 1];
            acc[nt][0] += bv0; acc[nt][1] += bv1;
            acc[nt][2] += bv0; acc[nt][3] += bv1;
            s0 += acc[nt][0] + acc[nt][1];
            q0 = fmaf(acc[nt][0], acc[nt][0], fmaf(acc[nt][1], acc[nt][1], q0));
            s1 += acc[nt][2] + acc[nt][3];
            q1 = fmaf(acc[nt][2], acc[nt][2], fmaf(acc[nt][3], acc[nt][3], q1));
        }
#pragma unroll
        for (int off = 1; off <= 2; off <<= 1) {
            s0 += __shfl_xor_sync(0xffffffffu, s0, off);
            q0 += __shfl_xor_sync(0xffffffffu, q0, off);
            s1 += __shfl_xor_sync(0xffffffffu, s1, off);
            q1 += __shfl_xor_sync(0xffffffffu, q1, off);
        }
        __syncthreads();
        if (tg == 0) {
            sm.red[warp_n][ar][0] = s0;     sm.red[warp_n][ar][1] = q0;
            sm.red[warp_n][ar + 8][0] = s1; sm.red[warp_n][ar + 8][1] = q1;
        }
        __syncthreads();
        s0 = sm.red[0][ar][0] + sm.red[1][ar][0];
        q0 = sm.red[0][ar][1] + sm.red[1][ar][1];
        s1 = sm.red[0][ar + 8][0] + sm.red[1][ar + 8][0];
        q1 = sm.red[0][ar + 8][1] + sm.red[1][ar + 8][1];
        const float invN = 1.0f / OO;
        float m0 = s0 * invN, m1 = s1 * invN;
        float r0 = rsqrtf(q0 * invN - m0 * m0 + 1e-5f);
        float r1 = rsqrtf(q1 * invN - m1 * m1 + 1e-5f);
        size_t row0 = ((size_t)e * B + b0 + ar) * OO;
        size_t row1 = row0 + (size_t)8 * OO;
#pragma unroll
        for (int nt = 0; nt < 8; nt++) {
            int c = cbase + nt * 8;
            float g0 = ge[c], g1 = ge[c + 1], t0 = bte[c], t1 = bte[c + 1];
            float v00 = fmaxf((acc[nt][0] - m0) * r0 * g0 + t0, 0.f);
            float v01 = fmaxf((acc[nt][1] - m0) * r0 * g1 + t1, 0.f);
            float v10 = fmaxf((acc[nt][2] - m1) * r1 * g0 + t0, 0.f);
            float v11 = fmaxf((acc[nt][3] - m1) * r1 * g1 + t1, 0.f);
            *(unsigned*)&eo[row0 + c] = pack_h2(__float2half_rn(v00), __float2half_rn(v01));
            *(unsigned*)&eo[row1 + c] = pack_h2(__float2half_rn(v10), __float2half_rn(v11));
        }
    }
}

// ---------------------------------------------------------------------------
// Fused gates with ldmatrix fragment loads.
// ---------------------------------------------------------------------------
struct GSmem {
    h16   sB[2][256][40];
    h16   sX[2][64][40];
    h16   ghs[64][266];
    float w2s[T_ * G_ * NE];
    float sw2s[G_ * E_];
    float b1s[256];
    float b2s[T_ * NE + E_];
};

__global__ void __launch_bounds__(256, 2)
gate_fused(const h16* __restrict__ xh, const h16* __restrict__ wgt,
           const float* __restrict__ tg_b1, const float* __restrict__ sg_b1,
           const float* __restrict__ tg_w2, const float* __restrict__ tg_b2,
           const float* __restrict__ sg_w2, const float* __restrict__ sg_b2,
           float* __restrict__ gw, float* __restrict__ sgw)
{
    extern __shared__ char raw[];
    GSmem& sm = *reinterpret_cast<GSmem*>(raw);

    const int b0  = blockIdx.x * 64;
    const int tid = threadIdx.x;
    const int wid = tid >> 5, lane = tid & 31;
    const int warp_m = wid & 3, warp_n = wid >> 2;
    const int gr = lane >> 2, tg = lane & 3;
    const int ar = warp_m * 16 + gr;
    const int l8 = lane & 7, lm = lane >> 3;
    const int a_row = warp_m * 16 + (lm & 1) * 8 + l8;
    const int a_kx  = (lm >> 1) * 8;
    const int b_row8 = (lm >> 1) * 8 + l8;
    const int b_kx   = (lm & 1) * 8;

    for (int i = tid; i < T_ * G_ * NE; i += 256) sm.w2s[i] = tg_w2[i];
    for (int i = tid; i < G_ * E_; i += 256) sm.sw2s[i] = sg_w2[i];
    sm.b1s[tid] = (tid < 192) ? tg_b1[tid] : sg_b1[tid - 192];
    if (tid < T_ * NE) sm.b2s[tid] = tg_b2[tid];
    else if (tid < T_ * NE + E_) sm.b2s[tid] = sg_b2[tid - T_ * NE];

    auto loadB = [&](int buf, int k0) {
        for (int i = tid; i < 256 * 4; i += 256) {
            int n = i >> 2, c = i & 3;
            cp16(&sm.sB[buf][n][c * 8], wgt + (size_t)n * D + k0 + c * 8);
        }
    };
    auto loadX = [&](int buf, int k0) {
        int r = tid >> 2, c = tid & 3;
        cp16(&sm.sX[buf][r][c * 8], xh + (size_t)(b0 + r) * D + k0 + c * 8);
    };

    float acc[16][4];
#pragma unroll
    for (int nt = 0; nt < 16; nt++)
#pragma unroll
        for (int j = 0; j < 4; j++) acc[nt][j] = 0.f;

    int buf = 0;
    loadX(0, 0);
    loadB(0, 0);
    cp_commit();

    for (int ks = 0; ks < 16; ks++) {
        if (ks < 15) { loadX(buf ^ 1, (ks + 1) * 32); loadB(buf ^ 1, (ks + 1) * 32); }
        cp_commit();
        cp_wait<1>(); __syncthreads();
#pragma unroll
        for (int ksub = 0; ksub < 2; ksub++) {
            const int koff = ksub * 16;
            unsigned ah[4];
            ldsm_x4(ah, lds_u32(&sm.sX[buf][a_row][koff + a_kx]));
#pragma unroll
            for (int np = 0; np < 8; np++) {
                unsigned bb[4];
                ldsm_x4(bb, lds_u32(&sm.sB[buf][warp_n * 128 + np * 16 + b_row8][koff + b_kx]));
                mma_fp16(acc[2 * np],     ah, bb);
                mma_fp16(acc[2 * np + 1], ah, bb + 2);
            }
        }
        __syncthreads();
        buf ^= 1;
    }

    {
        const int cbase = warp_n * 128 + tg * 2;
#pragma unroll
        for (int nt = 0; nt < 16; nt++) {
            int c = cbase + nt * 8;
            float bv0 = sm.b1s[c], bv1 = sm.b1s[c + 1];
            float v00 = fmaxf(acc[nt][0] + bv0, 0.f);
            float v01 = fmaxf(acc[nt][1] + bv1, 0.f);
            float v10 = fmaxf(acc[nt][2] + bv0, 0.f);
            float v11 = fmaxf(acc[nt][3] + bv1, 0.f);
            *(unsigned*)&sm.ghs[ar][c]     = pack_h2(__float2half_rn(v00), __float2half_rn(v01));
            *(unsigned*)&sm.ghs[ar + 8][c] = pack_h2(__float2half_rn(v10), __float2half_rn(v11));
        }
    }
    __syncthreads();

    if (tid < 192) {
        const int row = tid & 63, t = tid >> 6;
        float lg[NE];
#pragma unroll
        for (int j = 0; j < NE; j++) lg[j] = sm.b2s[t * NE + j];
        for (int g = 0; g < G_; g++) {
            float gv = __half2float(sm.ghs[row][t * 64 + g]);
            const float* w = &sm.w2s[(t * G_ + g) * NE];
#pragma unroll
            for (int j = 0; j < NE; j++) lg[j] = fmaf(gv, w[j], lg[j]);
        }
        float mx = -1e30f;
#pragma unroll
        for (int j = 0; j < NE; j++) mx = fmaxf(mx, lg[j]);
        float sum = 0.f;
#pragma unroll
        for (int j = 0; j < NE; j++) { lg[j] = __expf(lg[j] - mx); sum += lg[j]; }
        float inv = 1.0f / sum;
#pragma unroll
        for (int j = 0; j < NE; j++)
            gw[((size_t)t * B + b0 + row) * NE + j] = lg[j] * inv;
    } else {
        const int row = tid - 192;
        float lg[E_];
#pragma unroll
        for (int j = 0; j < E_; j++) lg[j] = sm.b2s[T_ * NE + j];
        for (int g = 0; g < G_; g++) {
            float gv = __half2float(sm.ghs[row][192 + g]);
            const float* w = &sm.sw2s[g * E_];
#pragma unroll
            for (int j = 0; j < E_; j++) lg[j] = fmaf(gv, w[j], lg[j]);
        }
        float mx = -1e30f;
#pragma unroll
        for (int j = 0; j < E_; j++) mx = fmaxf(mx, lg[j]);
        float sum = 0.f;
#pragma unroll
        for (int j = 0; j < E_; j++) { lg[j] = __expf(lg[j] - mx); sum += lg[j]; }
        float inv = 1.0f / sum;
#pragma unroll
        for (int j = 0; j < E_; j++)
            sgw[(size_t)(b0 + row) * E_ + j] = lg[j] * inv;
    }
}

// ---------------------------------------------------------------------------
__global__ void __launch_bounds__(256)
combine_kernel(const h16* __restrict__ eo, const float* __restrict__ gw,
               const float* __restrict__ sgw, float* __restrict__ out)
{
    const int b = blockIdx.x * 2 + (threadIdx.x >> 7);
    const int o = threadIdx.x & 127;

    float v[E_];
#pragma unroll
    for (int e = 0; e < E_; e++)
        v[e] = __half2float(eo[((size_t)e * B + b) * OO + o]);

#pragma unroll
    for (int t = 0; t < T_; t++) {
        const float* g = gw + ((size_t)t * B + b) * NE;
        float s = 0.f;
#pragma unroll
        for (int j = 0; j < NS; j++) s += g[j] * v[j];
#pragma unroll
        for (int n = 0; n < NT_TASK; n++) s += g[NS + n] * v[NS + t * NT_TASK + n];
        out[((size_t)t * B + b) * OO + o] = s;
    }

    const float* sg = sgw + (size_t)b * E_;
    float s = 0.f;
#pragma unroll
    for (int e = 0; e < E_; e++) s += sg[e] * v[e];
    out[((size_t)3 * B + b) * OO + o] = s;
}

// ---------------------------------------------------------------------------
extern "C" void kernel_launch(void* const* d_in, const int* in_sizes, int n_in,
                              void* d_out, int out_size)
{
    const float* x     = (const float*)d_in[0];
    const float* ew1   = (const float*)d_in[1];
    const float* eb1   = (const float*)d_in[2];
    const float* eg1   = (const float*)d_in[3];
    const float* ebt1  = (const float*)d_in[4];
    const float* ew2   = (const float*)d_in[5];
    const float* eb2   = (const float*)d_in[6];
    const float* eg2   = (const float*)d_in[7];
    const float* ebt2  = (const float*)d_in[8];
    const float* ew3   = (const float*)d_in[9];
    const float* eb3   = (const float*)d_in[10];
    const float* eg3   = (const float*)d_in[11];
    const float* ebt3  = (const float*)d_in[12];
    const float* tg_w1 = (const float*)d_in[13];
    const float* tg_b1 = (const float*)d_in[14];
    const float* tg_w2 = (const float*)d_in[15];
    const float* tg_b2 = (const float*)d_in[16];
    const float* sg_w1 = (const float*)d_in[17];
    const float* sg_b1 = (const float*)d_in[18];
    const float* sg_w2 = (const float*)d_in[19];
    const float* sg_b2 = (const float*)d_in[20];
    float* out = (float*)d_out;

    static h16 *xh = nullptr, *w1t, *w2t, *w3t, *wgt, *eo;
    static float *gw, *sgw;
    if (!xh) {
        cudaGetSymbolAddress((void**)&xh,  g_xh);
        cudaGetSymbolAddress((void**)&w1t, g_w1t);
        cudaGetSymbolAddress((void**)&w2t, g_w2t);
        cudaGetSymbolAddress((void**)&w3t, g_w3t);
        cudaGetSymbolAddress((void**)&wgt, g_wgt);
        cudaGetSymbolAddress((void**)&eo,  g_eo);
        cudaGetSymbolAddress((void**)&gw,  g_gw);
        cudaGetSymbolAddress((void**)&sgw, g_sgw);
        cudaFuncSetAttribute(expert_fused, cudaFuncAttributeMaxDynamicSharedMemorySize,
                             (int)sizeof(SmemT));
        cudaFuncSetAttribute(gate_fused, cudaFuncAttributeMaxDynamicSharedMemorySize,
                             (int)sizeof(GSmem));
    }

    prep_x_gate<<<16384 + 512, 256>>>((const float4*)x, (unsigned*)xh, tg_w1, sg_w1, wgt);
    prep_weights<<<dim3(224, E_), 256>>>(ew1, ew2, ew3, w1t, w2t, w3t);

    gate_fused<<<B / 64, 256, sizeof(GSmem)>>>(
        xh, wgt, tg_b1, sg_b1, tg_w2, tg_b2, sg_w2, sg_b2, gw, sgw);

    expert_fused<<<dim3(E_, B / 64), 256, sizeof(SmemT)>>>(
        xh, w1t, w2t, w3t,
        eb1, eg1, ebt1, eb2, eg2, ebt2, eb3, eg3, ebt3, eo);

    combine_kernel<<<B / 2, 256>>>(eo, gw, sgw, out);
}

// round 11
// speedup vs baseline: 6.0102x; 1.1023x over previous
#include <cuda_runtime.h>
#include <cuda_fp16.h>
#include <math.h>
#include <stdint.h>

#define B  32768
#define D  512
#define H  256
#define OO 128
#define E_ 10
#define T_ 3
#define G_ 64
#define NS 4
#define NT_TASK 2
#define NE (NS + NT_TASK)

typedef __half h16;

// ---------------- scratch (allocation-free) ----------------
__device__ h16   g_xh[(size_t)B * D];
__device__ h16   g_w1t[(size_t)E_ * H * D];    // [E][N=256][K=512] fp16
__device__ h16   g_w2t[(size_t)E_ * H * H];    // [E][256][256]
__device__ h16   g_w3t[(size_t)E_ * OO * H];   // [E][128][256]
__device__ h16   g_wgt[(size_t)256 * D];       // combined gate W1^T [256][512]
__device__ h16   g_eo[(size_t)E_ * B * OO];    // expert outputs, fp16
__device__ float g_gw[(size_t)T_ * B * NE];
__device__ float g_sgw[(size_t)B * E_];

// ---------------- helpers ----------------
__device__ __forceinline__ void mma_fp16(float* c, const unsigned* a, const unsigned* b) {
    asm volatile(
        "mma.sync.aligned.m16n8k16.row.col.f32.f16.f16.f32 "
        "{%0,%1,%2,%3}, {%4,%5,%6,%7}, {%8,%9}, {%0,%1,%2,%3};\n"
        : "+f"(c[0]), "+f"(c[1]), "+f"(c[2]), "+f"(c[3])
        : "r"(a[0]), "r"(a[1]), "r"(a[2]), "r"(a[3]), "r"(b[0]), "r"(b[1]));
}
__device__ __forceinline__ unsigned pack_h2(h16 a, h16 b) {
    return (unsigned)__half_as_ushort(a) | ((unsigned)__half_as_ushort(b) << 16);
}
__device__ __forceinline__ void cp16(void* s, const void* g) {
    unsigned sa = (unsigned)__cvta_generic_to_shared(s);
    asm volatile("cp.async.cg.shared.global [%0], [%1], 16;\n" :: "r"(sa), "l"(g));
}
__device__ __forceinline__ void cp_commit() { asm volatile("cp.async.commit_group;\n"); }
template <int N2> __device__ __forceinline__ void cp_wait() {
    asm volatile("cp.async.wait_group %0;\n" :: "n"(N2));
}
__device__ __forceinline__ unsigned lds_u32(const void* p) {
    return (unsigned)__cvta_generic_to_shared(p);
}
__device__ __forceinline__ void ldsm_x4(unsigned* r, unsigned addr) {
    asm volatile("ldmatrix.sync.aligned.m8n8.x4.shared.b16 {%0,%1,%2,%3}, [%4];"
        : "=r"(r[0]), "=r"(r[1]), "=r"(r[2]), "=r"(r[3]) : "r"(addr));
}

// ---------------- prep kernels (merged) ----------------
__global__ void prep_x_gate(const float4* __restrict__ x4, unsigned* __restrict__ xh2,
                            const float* __restrict__ tg_w1, const float* __restrict__ sg_w1,
                            h16* __restrict__ wgt)
{
    const int bx = blockIdx.x, tid = threadIdx.x;
    if (bx < 16384) {
        int i = bx * 256 + tid;
        float4 v = x4[i];
        xh2[i * 2]     = pack_h2(__float2half_rn(v.x), __float2half_rn(v.y));
        xh2[i * 2 + 1] = pack_h2(__float2half_rn(v.z), __float2half_rn(v.w));
    } else {
        int i = (bx - 16384) * 256 + tid;
        int n = i >> 9, d = i & 511;
        float v;
        if (n < 192) {
            int t = n >> 6, g = n & 63;
            v = tg_w1[((size_t)t * D + d) * G_ + g];
        } else {
            v = sg_w1[(size_t)d * G_ + (n - 192)];
        }
        wgt[(size_t)n * D + d] = __float2half_rn(v);
    }
}

__global__ void prep_weights(const float* __restrict__ ew1, const float* __restrict__ ew2,
                             const float* __restrict__ ew3,
                             h16* __restrict__ w1t, h16* __restrict__ w2t, h16* __restrict__ w3t)
{
    __shared__ float t[32][33];
    const int e = blockIdx.y, bx = blockIdx.x, tid = threadIdx.x;
    const float* W; h16* T; int K, N, k0, n0;
    if (bx < 128)      { W = ew1; T = w1t; K = D; N = H;  k0 = (bx & 15) * 32;        n0 = (bx >> 4) * 32; }
    else if (bx < 192) { W = ew2; T = w2t; K = H; N = H;  k0 = ((bx - 128) & 7) * 32; n0 = ((bx - 128) >> 3) * 32; }
    else               { W = ew3; T = w3t; K = H; N = OO; k0 = ((bx - 192) & 7) * 32; n0 = ((bx - 192) >> 3) * 32; }
    const float* We = W + (size_t)e * K * N;
    for (int i = tid; i < 1024; i += 256) {
        int r = i >> 5, c = i & 31;
        t[r][c] = We[(size_t)(k0 + r) * N + n0 + c];
    }
    __syncthreads();
    size_t base = (size_t)e * N * K;
    for (int i = tid; i < 1024; i += 256) {
        int nn = i >> 5, kk = i & 31;
        T[base + (size_t)(n0 + nn) * K + k0 + kk] = __float2half_rn(t[kk][nn]);
    }
}

// ---------------------------------------------------------------------------
// Fused expert tower. Warp tile 32x64 (warp_m=2 x warp_n=4 over 64x256 CTA).
// ---------------------------------------------------------------------------
struct SmemT {
    h16   sB[2][256][40];  // 40 KB
    h16   sX[2][64][40];   // 10 KB
    h16   sH[64][264];     // 33 KB
    float red[4][64][2];   //  2 KB
};

__global__ void __launch_bounds__(256, 2)
expert_fused(const h16* __restrict__ xh,
             const h16* __restrict__ w1t, const h16* __restrict__ w2t, const h16* __restrict__ w3t,
             const float* __restrict__ eb1, const float* __restrict__ eg1, const float* __restrict__ ebt1,
             const float* __restrict__ eb2, const float* __restrict__ eg2, const float* __restrict__ ebt2,
             const float* __restrict__ eb3, const float* __restrict__ eg3, const float* __restrict__ ebt3,
             h16* __restrict__ eo)
{
    extern __shared__ char raw[];
    SmemT& sm = *reinterpret_cast<SmemT*>(raw);

    const int e   = blockIdx.x;
    const int b0  = blockIdx.y * 64;
    const int tid = threadIdx.x;
    const int wid = tid >> 5, lane = tid & 31;
    const int warp_m = wid & 1, warp_n = wid >> 1;   // 2 x 4
    const int gr = lane >> 2, tg = lane & 3;
    const int l8 = lane & 7, lm = lane >> 3;
    const int a_row0 = warp_m * 32 + (lm & 1) * 8 + l8;  // + mt*16
    const int a_kx   = (lm >> 1) * 8;
    const int b_row8 = (lm >> 1) * 8 + l8;               // + colbase + np*16
    const int b_kx   = (lm & 1) * 8;

    const h16* W1 = w1t + (size_t)e * H * D;
    const h16* W2 = w2t + (size_t)e * H * H;
    const h16* W3 = w3t + (size_t)e * OO * H;

    auto loadB = [&](const h16* T, int rows, int K, int buf, int k0) {
        for (int i = tid; i < rows * 4; i += 256) {
            int n = i >> 2, c = i & 3;
            cp16(&sm.sB[buf][n][c * 8], T + (size_t)n * K + k0 + c * 8);
        }
    };
    auto loadX = [&](int buf, int k0) {
        int r = tid >> 2, c = tid & 3;
        cp16(&sm.sX[buf][r][c * 8], xh + (size_t)(b0 + r) * D + k0 + c * 8);
    };

    float acc[2][8][4];
    float s[2][2], q[2][2], mean[2][2], rstd[2][2];

    // =================== Layer 1: 64x512 @ W1 -> 64x256 ===================
#pragma unroll
    for (int mt = 0; mt < 2; mt++)
#pragma unroll
        for (int nt = 0; nt < 8; nt++)
#pragma unroll
            for (int j = 0; j < 4; j++) acc[mt][nt][j] = 0.f;

    int buf = 0;
    loadX(0, 0);
    loadB(W1, 256, D, 0, 0);
    cp_commit();

    for (int ks = 0; ks < 16; ks++) {
        if (ks < 15) { loadX(buf ^ 1, (ks + 1) * 32); loadB(W1, 256, D, buf ^ 1, (ks + 1) * 32); }
        cp_commit();
        cp_wait<1>(); __syncthreads();
#pragma unroll
        for (int ksub = 0; ksub < 2; ksub++) {
            const int koff = ksub * 16;
            unsigned a0[4], a1[4], bb[4][4];
            ldsm_x4(a0, lds_u32(&sm.sX[buf][a_row0][koff + a_kx]));
            ldsm_x4(a1, lds_u32(&sm.sX[buf][a_row0 + 16][koff + a_kx]));
#pragma unroll
            for (int np = 0; np < 4; np++)
                ldsm_x4(bb[np], lds_u32(&sm.sB[buf][warp_n * 64 + np * 16 + b_row8][koff + b_kx]));
#pragma unroll
            for (int np = 0; np < 4; np++) {
                mma_fp16(acc[0][2 * np],     a0, bb[np]);
                mma_fp16(acc[0][2 * np + 1], a0, bb[np] + 2);
                mma_fp16(acc[1][2 * np],     a1, bb[np]);
                mma_fp16(acc[1][2 * np + 1], a1, bb[np] + 2);
            }
        }
        __syncthreads();
        buf ^= 1;
    }
    loadB(W2, 256, H, 0, 0);
    cp_commit();

    // ---- epilogue 1 -> sH ----
    {
        const float* be  = eb1  + (size_t)e * H;
        const float* ge  = eg1  + (size_t)e * H;
        const float* bte = ebt1 + (size_t)e * H;
        const int cbase = warp_n * 64 + tg * 2;
#pragma unroll
        for (int mt = 0; mt < 2; mt++) { s[mt][0] = s[mt][1] = q[mt][0] = q[mt][1] = 0.f; }
#pragma unroll
        for (int mt = 0; mt < 2; mt++)
#pragma unroll
            for (int nt = 0; nt < 8; nt++) {
                int c = cbase + nt * 8;
                float bv0 = be[c], bv1 = be[c + 1];
                acc[mt][nt][0] += bv0; acc[mt][nt][1] += bv1;
                acc[mt][nt][2] += bv0; acc[mt][nt][3] += bv1;
                s[mt][0] += acc[mt][nt][0] + acc[mt][nt][1];
                q[mt][0] = fmaf(acc[mt][nt][0], acc[mt][nt][0], fmaf(acc[mt][nt][1], acc[mt][nt][1], q[mt][0]));
                s[mt][1] += acc[mt][nt][2] + acc[mt][nt][3];
                q[mt][1] = fmaf(acc[mt][nt][2], acc[mt][nt][2], fmaf(acc[mt][nt][3], acc[mt][nt][3], q[mt][1]));
            }
#pragma unroll
        for (int mt = 0; mt < 2; mt++)
#pragma unroll
            for (int h = 0; h < 2; h++)
#pragma unroll
                for (int off = 1; off <= 2; off <<= 1) {
                    s[mt][h] += __shfl_xor_sync(0xffffffffu, s[mt][h], off);
                    q[mt][h] += __shfl_xor_sync(0xffffffffu, q[mt][h], off);
                }
        __syncthreads();
        if (tg == 0) {
#pragma unroll
            for (int mt = 0; mt < 2; mt++)
#pragma unroll
                for (int h = 0; h < 2; h++) {
                    int r = warp_m * 32 + mt * 16 + gr + h * 8;
                    sm.red[warp_n][r][0] = s[mt][h];
                    sm.red[warp_n][r][1] = q[mt][h];
                }
        }
        __syncthreads();
        const float invN = 1.0f / H;
#pragma unroll
        for (int mt = 0; mt < 2; mt++)
#pragma unroll
            for (int h = 0; h < 2; h++) {
                int r = warp_m * 32 + mt * 16 + gr + h * 8;
                float ss = sm.red[0][r][0] + sm.red[1][r][0] + sm.red[2][r][0] + sm.red[3][r][0];
                float qq = sm.red[0][r][1] + sm.red[1][r][1] + sm.red[2][r][1] + sm.red[3][r][1];
                float m = ss * invN;
                mean[mt][h] = m;
                rstd[mt][h] = rsqrtf(qq * invN - m * m + 1e-5f);
            }
#pragma unroll
        for (int mt = 0; mt < 2; mt++) {
            int r0 = warp_m * 32 + mt * 16 + gr;
#pragma unroll
            for (int nt = 0; nt < 8; nt++) {
                int c = cbase + nt * 8;
                float g0 = ge[c], g1 = ge[c + 1], t0 = bte[c], t1 = bte[c + 1];
                float v00 = fmaxf((acc[mt][nt][0] - mean[mt][0]) * rstd[mt][0] * g0 + t0, 0.f);
                float v01 = fmaxf((acc[mt][nt][1] - mean[mt][0]) * rstd[mt][0] * g1 + t1, 0.f);
                float v10 = fmaxf((acc[mt][nt][2] - mean[mt][1]) * rstd[mt][1] * g0 + t0, 0.f);
                float v11 = fmaxf((acc[mt][nt][3] - mean[mt][1]) * rstd[mt][1] * g1 + t1, 0.f);
                *(unsigned*)&sm.sH[r0][c]     = pack_h2(__float2half_rn(v00), __float2half_rn(v01));
                *(unsigned*)&sm.sH[r0 + 8][c] = pack_h2(__float2half_rn(v10), __float2half_rn(v11));
            }
        }
    }

    // =================== Layer 2: sH @ W2 -> 64x256 ===================
#pragma unroll
    for (int mt = 0; mt < 2; mt++)
#pragma unroll
        for (int nt = 0; nt < 8; nt++)
#pragma unroll
            for (int j = 0; j < 4; j++) acc[mt][nt][j] = 0.f;

    buf = 0;
    for (int ks = 0; ks < 8; ks++) {
        if (ks < 7) loadB(W2, 256, H, buf ^ 1, (ks + 1) * 32);
        cp_commit();
        cp_wait<1>(); __syncthreads();
#pragma unroll
        for (int ksub = 0; ksub < 2; ksub++) {
            const int koffA = ks * 32 + ksub * 16;
            const int koffB = ksub * 16;
            unsigned a0[4], a1[4], bb[4][4];
            ldsm_x4(a0, lds_u32(&sm.sH[a_row0][koffA + a_kx]));
            ldsm_x4(a1, lds_u32(&sm.sH[a_row0 + 16][koffA + a_kx]));
#pragma unroll
            for (int np = 0; np < 4; np++)
                ldsm_x4(bb[np], lds_u32(&sm.sB[buf][warp_n * 64 + np * 16 + b_row8][koffB + b_kx]));
#pragma unroll
            for (int np = 0; np < 4; np++) {
                mma_fp16(acc[0][2 * np],     a0, bb[np]);
                mma_fp16(acc[0][2 * np + 1], a0, bb[np] + 2);
                mma_fp16(acc[1][2 * np],     a1, bb[np]);
                mma_fp16(acc[1][2 * np + 1], a1, bb[np] + 2);
            }
        }
        __syncthreads();
        buf ^= 1;
    }
    loadB(W3, 128, H, 0, 0);
    cp_commit();

    // ---- epilogue 2 -> sH ----
    {
        const float* be  = eb2  + (size_t)e * H;
        const float* ge  = eg2  + (size_t)e * H;
        const float* bte = ebt2 + (size_t)e * H;
        const int cbase = warp_n * 64 + tg * 2;
#pragma unroll
        for (int mt = 0; mt < 2; mt++) { s[mt][0] = s[mt][1] = q[mt][0] = q[mt][1] = 0.f; }
#pragma unroll
        for (int mt = 0; mt < 2; mt++)
#pragma unroll
            for (int nt = 0; nt < 8; nt++) {
                int c = cbase + nt * 8;
                float bv0 = be[c], bv1 = be[c + 1];
                acc[mt][nt][0] += bv0; acc[mt][nt][1] += bv1;
                acc[mt][nt][2] += bv0; acc[mt][nt][3] += bv1;
                s[mt][0] += acc[mt][nt][0] + acc[mt][nt][1];
                q[mt][0] = fmaf(acc[mt][nt][0], acc[mt][nt][0], fmaf(acc[mt][nt][1], acc[mt][nt][1], q[mt][0]));
                s[mt][1] += acc[mt][nt][2] + acc[mt][nt][3];
                q[mt][1] = fmaf(acc[mt][nt][2], acc[mt][nt][2], fmaf(acc[mt][nt][3], acc[mt][nt][3], q[mt][1]));
            }
#pragma unroll
        for (int mt = 0; mt < 2; mt++)
#pragma unroll
            for (int h = 0; h < 2; h++)
#pragma unroll
                for (int off = 1; off <= 2; off <<= 1) {
                    s[mt][h] += __shfl_xor_sync(0xffffffffu, s[mt][h], off);
                    q[mt][h] += __shfl_xor_sync(0xffffffffu, q[mt][h], off);
                }
        __syncthreads();
        if (tg == 0) {
#pragma unroll
            for (int mt = 0; mt < 2; mt++)
#pragma unroll
                for (int h = 0; h < 2; h++) {
                    int r = warp_m * 32 + mt * 16 + gr + h * 8;
                    sm.red[warp_n][r][0] = s[mt][h];
                    sm.red[warp_n][r][1] = q[mt][h];
                }
        }
        __syncthreads();
        const float invN = 1.0f / H;
#pragma unroll
        for (int mt = 0; mt < 2; mt++)
#pragma unroll
            for (int h = 0; h < 2; h++) {
                int r = warp_m * 32 + mt * 16 + gr + h * 8;
                float ss = sm.red[0][r][0] + sm.red[1][r][0] + sm.red[2][r][0] + sm.red[3][r][0];
                float qq = sm.red[0][r][1] + sm.red[1][r][1] + sm.red[2][r][1] + sm.red[3][r][1];
                float m = ss * invN;
                mean[mt][h] = m;
                rstd[mt][h] = rsqrtf(qq * invN - m * m + 1e-5f);
            }
        __syncthreads();   // all reads of sH (L2 mainloop) + red done before overwrite
#pragma unroll
        for (int mt = 0; mt < 2; mt++) {
            int r0 = warp_m * 32 + mt * 16 + gr;
#pragma unroll
            for (int nt = 0; nt < 8; nt++) {
                int c = cbase + nt * 8;
                float g0 = ge[c], g1 = ge[c + 1], t0 = bte[c], t1 = bte[c + 1];
                float v00 = fmaxf((acc[mt][nt][0] - mean[mt][0]) * rstd[mt][0] * g0 + t0, 0.f);
                float v01 = fmaxf((acc[mt][nt][1] - mean[mt][0]) * rstd[mt][0] * g1 + t1, 0.f);
                float v10 = fmaxf((acc[mt][nt][2] - mean[mt][1]) * rstd[mt][1] * g0 + t0, 0.f);
                float v11 = fmaxf((acc[mt][nt][3] - mean[mt][1]) * rstd[mt][1] * g1 + t1, 0.f);
                *(unsigned*)&sm.sH[r0][c]     = pack_h2(__float2half_rn(v00), __float2half_rn(v01));
                *(unsigned*)&sm.sH[r0 + 8][c] = pack_h2(__float2half_rn(v10), __float2half_rn(v11));
            }
        }
    }
    __syncthreads();

    // =================== Layer 3: sH @ W3 -> 64x128 ===================
#pragma unroll
    for (int mt = 0; mt < 2; mt++)
#pragma unroll
        for (int nt = 0; nt < 4; nt++)
#pragma unroll
            for (int j = 0; j < 4; j++) acc[mt][nt][j] = 0.f;

    buf = 0;
    for (int ks = 0; ks < 8; ks++) {
        if (ks < 7) loadB(W3, 128, H, buf ^ 1, (ks + 1) * 32);
        cp_commit();
        cp_wait<1>(); __syncthreads();
#pragma unroll
        for (int ksub = 0; ksub < 2; ksub++) {
            const int koffA = ks * 32 + ksub * 16;
            const int koffB = ksub * 16;
            unsigned a0[4], a1[4], bb[2][4];
            ldsm_x4(a0, lds_u32(&sm.sH[a_row0][koffA + a_kx]));
            ldsm_x4(a1, lds_u32(&sm.sH[a_row0 + 16][koffA + a_kx]));
#pragma unroll
            for (int np = 0; np < 2; np++)
                ldsm_x4(bb[np], lds_u32(&sm.sB[buf][warp_n * 32 + np * 16 + b_row8][koffB + b_kx]));
#pragma unroll
            for (int np = 0; np < 2; np++) {
                mma_fp16(acc[0][2 * np],     a0, bb[np]);
                mma_fp16(acc[0][2 * np + 1], a0, bb[np] + 2);
                mma_fp16(acc[1][2 * np],     a1, bb[np]);
                mma_fp16(acc[1][2 * np + 1], a1, bb[np] + 2);
            }
        }
        __syncthreads();
        buf ^= 1;
    }

    // ---- epilogue 3 -> eo (fp16) ----
    {
        const float* be  = eb3  + (size_t)e * OO;
        const float* ge  = eg3  + (size_t)e * OO;
        const float* bte = ebt3 + (size_t)e * OO;
        const int cbase = warp_n * 32 + tg * 2;
#pragma unroll
        for (int mt = 0; mt < 2; mt++) { s[mt][0] = s[mt][1] = q[mt][0] = q[mt][1] = 0.f; }
#pragma unroll
        for (int mt = 0; mt < 2; mt++)
#pragma unroll
            for (int nt = 0; nt < 4; nt++) {
                int c = cbase + nt * 8;
                float bv0 = be[c], bv1 = be[c + 1];
                acc[mt][nt][0] += bv0; acc[mt][nt][1] += bv1;
                acc[mt][nt][2] += bv0; acc[mt][nt][3] += bv1;
                s[mt][0] += acc[mt][nt][0] + acc[mt][nt][1];
                q[mt][0] = fmaf(acc[mt][nt][0], acc[mt][nt][0], fmaf(acc[mt][nt][1], acc[mt][nt][1], q[mt][0]));
                s[mt][1] += acc[mt][nt][2] + acc[mt][nt][3];
                q[mt][1] = fmaf(acc[mt][nt][2], acc[mt][nt][2], fmaf(acc[mt][nt][3], acc[mt][nt][3], q[mt][1]));
            }
#pragma unroll
        for (int mt = 0; mt < 2; mt++)
#pragma unroll
            for (int h = 0; h < 2; h++)
#pragma unroll
                for (int off = 1; off <= 2; off <<= 1) {
                    s[mt][h] += __shfl_xor_sync(0xffffffffu, s[mt][h], off);
                    q[mt][h] += __shfl_xor_sync(0xffffffffu, q[mt][h], off);
                }
        __syncthreads();
        if (tg == 0) {
#pragma unroll
            for (int mt = 0; mt < 2; mt++)
#pragma unroll
                for (int h = 0; h < 2; h++) {
                    int r = warp_m * 32 + mt * 16 + gr + h * 8;
                    sm.red[warp_n][r][0] = s[mt][h];
                    sm.red[warp_n][r][1] = q[mt][h];
                }
        }
        __syncthreads();
        const float invN = 1.0f / OO;
#pragma unroll
        for (int mt = 0; mt < 2; mt++)
#pragma unroll
            for (int h = 0; h < 2; h++) {
                int r = warp_m * 32 + mt * 16 + gr + h * 8;
                float ss = sm.red[0][r][0] + sm.red[1][r][0] + sm.red[2][r][0] + sm.red[3][r][0];
                float qq = sm.red[0][r][1] + sm.red[1][r][1] + sm.red[2][r][1] + sm.red[3][r][1];
                float m = ss * invN;
                mean[mt][h] = m;
                rstd[mt][h] = rsqrtf(qq * invN - m * m + 1e-5f);
            }
#pragma unroll
        for (int mt = 0; mt < 2; mt++) {
            int r0 = warp_m * 32 + mt * 16 + gr;
            size_t row0 = ((size_t)e * B + b0 + r0) * OO;
            size_t row1 = row0 + (size_t)8 * OO;
#pragma unroll
            for (int nt = 0; nt < 4; nt++) {
                int c = cbase + nt * 8;
                float g0 = ge[c], g1 = ge[c + 1], t0 = bte[c], t1 = bte[c + 1];
                float v00 = fmaxf((acc[mt][nt][0] - mean[mt][0]) * rstd[mt][0] * g0 + t0, 0.f);
                float v01 = fmaxf((acc[mt][nt][1] - mean[mt][0]) * rstd[mt][0] * g1 + t1, 0.f);
                float v10 = fmaxf((acc[mt][nt][2] - mean[mt][1]) * rstd[mt][1] * g0 + t0, 0.f);
                float v11 = fmaxf((acc[mt][nt][3] - mean[mt][1]) * rstd[mt][1] * g1 + t1, 0.f);
                *(unsigned*)&eo[row0 + c] = pack_h2(__float2half_rn(v00), __float2half_rn(v01));
                *(unsigned*)&eo[row1 + c] = pack_h2(__float2half_rn(v10), __float2half_rn(v11));
            }
        }
    }
}

// ---------------------------------------------------------------------------
// Fused gates (unchanged from R8 tiling — passing, small share of runtime).
// ---------------------------------------------------------------------------
struct GSmem {
    h16   sB[2][256][40];
    h16   sX[2][64][40];
    h16   ghs[64][266];
    float w2s[T_ * G_ * NE];
    float sw2s[G_ * E_];
    float b1s[256];
    float b2s[T_ * NE + E_];
};

__global__ void __launch_bounds__(256, 2)
gate_fused(const h16* __restrict__ xh, const h16* __restrict__ wgt,
           const float* __restrict__ tg_b1, const float* __restrict__ sg_b1,
           const float* __restrict__ tg_w2, const float* __restrict__ tg_b2,
           const float* __restrict__ sg_w2, const float* __restrict__ sg_b2,
           float* __restrict__ gw, float* __restrict__ sgw)
{
    extern __shared__ char raw[];
    GSmem& sm = *reinterpret_cast<GSmem*>(raw);

    const int b0  = blockIdx.x * 64;
    const int tid = threadIdx.x;
    const int wid = tid >> 5, lane = tid & 31;
    const int warp_m = wid & 3, warp_n = wid >> 2;
    const int gr = lane >> 2, tg = lane & 3;
    const int ar = warp_m * 16 + gr;
    const int l8 = lane & 7, lm = lane >> 3;
    const int a_row = warp_m * 16 + (lm & 1) * 8 + l8;
    const int a_kx  = (lm >> 1) * 8;
    const int b_row8 = (lm >> 1) * 8 + l8;
    const int b_kx   = (lm & 1) * 8;

    for (int i = tid; i < T_ * G_ * NE; i += 256) sm.w2s[i] = tg_w2[i];
    for (int i = tid; i < G_ * E_; i += 256) sm.sw2s[i] = sg_w2[i];
    sm.b1s[tid] = (tid < 192) ? tg_b1[tid] : sg_b1[tid - 192];
    if (tid < T_ * NE) sm.b2s[tid] = tg_b2[tid];
    else if (tid < T_ * NE + E_) sm.b2s[tid] = sg_b2[tid - T_ * NE];

    auto loadB = [&](int buf, int k0) {
        for (int i = tid; i < 256 * 4; i += 256) {
            int n = i >> 2, c = i & 3;
            cp16(&sm.sB[buf][n][c * 8], wgt + (size_t)n * D + k0 + c * 8);
        }
    };
    auto loadX = [&](int buf, int k0) {
        int r = tid >> 2, c = tid & 3;
        cp16(&sm.sX[buf][r][c * 8], xh + (size_t)(b0 + r) * D + k0 + c * 8);
    };

    float acc[16][4];
#pragma unroll
    for (int nt = 0; nt < 16; nt++)
#pragma unroll
        for (int j = 0; j < 4; j++) acc[nt][j] = 0.f;

    int buf = 0;
    loadX(0, 0);
    loadB(0, 0);
    cp_commit();

    for (int ks = 0; ks < 16; ks++) {
        if (ks < 15) { loadX(buf ^ 1, (ks + 1) * 32); loadB(buf ^ 1, (ks + 1) * 32); }
        cp_commit();
        cp_wait<1>(); __syncthreads();
#pragma unroll
        for (int ksub = 0; ksub < 2; ksub++) {
            const int koff = ksub * 16;
            unsigned ah[4];
            ldsm_x4(ah, lds_u32(&sm.sX[buf][a_row][koff + a_kx]));
#pragma unroll
            for (int np = 0; np < 8; np++) {
                unsigned bb[4];
                ldsm_x4(bb, lds_u32(&sm.sB[buf][warp_n * 128 + np * 16 + b_row8][koff + b_kx]));
                mma_fp16(acc[2 * np],     ah, bb);
                mma_fp16(acc[2 * np + 1], ah, bb + 2);
            }
        }
        __syncthreads();
        buf ^= 1;
    }

    {
        const int cbase = warp_n * 128 + tg * 2;
#pragma unroll
        for (int nt = 0; nt < 16; nt++) {
            int c = cbase + nt * 8;
            float bv0 = sm.b1s[c], bv1 = sm.b1s[c + 1];
            float v00 = fmaxf(acc[nt][0] + bv0, 0.f);
            float v01 = fmaxf(acc[nt][1] + bv1, 0.f);
            float v10 = fmaxf(acc[nt][2] + bv0, 0.f);
            float v11 = fmaxf(acc[nt][3] + bv1, 0.f);
            *(unsigned*)&sm.ghs[ar][c]     = pack_h2(__float2half_rn(v00), __float2half_rn(v01));
            *(unsigned*)&sm.ghs[ar + 8][c] = pack_h2(__float2half_rn(v10), __float2half_rn(v11));
        }
    }
    __syncthreads();

    if (tid < 192) {
        const int row = tid & 63, t = tid >> 6;
        float lg[NE];
#pragma unroll
        for (int j = 0; j < NE; j++) lg[j] = sm.b2s[t * NE + j];
        for (int g = 0; g < G_; g++) {
            float gv = __half2float(sm.ghs[row][t * 64 + g]);
            const float* w = &sm.w2s[(t * G_ + g) * NE];
#pragma unroll
            for (int j = 0; j < NE; j++) lg[j] = fmaf(gv, w[j], lg[j]);
        }
        float mx = -1e30f;
#pragma unroll
        for (int j = 0; j < NE; j++) mx = fmaxf(mx, lg[j]);
        float sum = 0.f;
#pragma unroll
        for (int j = 0; j < NE; j++) { lg[j] = __expf(lg[j] - mx); sum += lg[j]; }
        float inv = 1.0f / sum;
#pragma unroll
        for (int j = 0; j < NE; j++)
            gw[((size_t)t * B + b0 + row) * NE + j] = lg[j] * inv;
    } else {
        const int row = tid - 192;
        float lg[E_];
#pragma unroll
        for (int j = 0; j < E_; j++) lg[j] = sm.b2s[T_ * NE + j];
        for (int g = 0; g < G_; g++) {
            float gv = __half2float(sm.ghs[row][192 + g]);
            const float* w = &sm.sw2s[g * E_];
#pragma unroll
            for (int j = 0; j < E_; j++) lg[j] = fmaf(gv, w[j], lg[j]);
        }
        float mx = -1e30f;
#pragma unroll
        for (int j = 0; j < E_; j++) mx = fmaxf(mx, lg[j]);
        float sum = 0.f;
#pragma unroll
        for (int j = 0; j < E_; j++) { lg[j] = __expf(lg[j] - mx); sum += lg[j]; }
        float inv = 1.0f / sum;
#pragma unroll
        for (int j = 0; j < E_; j++)
            sgw[(size_t)(b0 + row) * E_ + j] = lg[j] * inv;
    }
}

// ---------------------------------------------------------------------------
__global__ void __launch_bounds__(256)
combine_kernel(const h16* __restrict__ eo, const float* __restrict__ gw,
               const float* __restrict__ sgw, float* __restrict__ out)
{
    const int b = blockIdx.x * 2 + (threadIdx.x >> 7);
    const int o = threadIdx.x & 127;

    float v[E_];
#pragma unroll
    for (int e = 0; e < E_; e++)
        v[e] = __half2float(eo[((size_t)e * B + b) * OO + o]);

#pragma unroll
    for (int t = 0; t < T_; t++) {
        const float* g = gw + ((size_t)t * B + b) * NE;
        float s = 0.f;
#pragma unroll
        for (int j = 0; j < NS; j++) s += g[j] * v[j];
#pragma unroll
        for (int n = 0; n < NT_TASK; n++) s += g[NS + n] * v[NS + t * NT_TASK + n];
        out[((size_t)t * B + b) * OO + o] = s;
    }

    const float* sg = sgw + (size_t)b * E_;
    float s = 0.f;
#pragma unroll
    for (int e = 0; e < E_; e++) s += sg[e] * v[e];
    out[((size_t)3 * B + b) * OO + o] = s;
}

// ---------------------------------------------------------------------------
extern "C" void kernel_launch(void* const* d_in, const int* in_sizes, int n_in,
                              void* d_out, int out_size)
{
    const float* x     = (const float*)d_in[0];
    const float* ew1   = (const float*)d_in[1];
    const float* eb1   = (const float*)d_in[2];
    const float* eg1   = (const float*)d_in[3];
    const float* ebt1  = (const float*)d_in[4];
    const float* ew2   = (const float*)d_in[5];
    const float* eb2   = (const float*)d_in[6];
    const float* eg2   = (const float*)d_in[7];
    const float* ebt2  = (const float*)d_in[8];
    const float* ew3   = (const float*)d_in[9];
    const float* eb3   = (const float*)d_in[10];
    const float* eg3   = (const float*)d_in[11];
    const float* ebt3  = (const float*)d_in[12];
    const float* tg_w1 = (const float*)d_in[13];
    const float* tg_b1 = (const float*)d_in[14];
    const float* tg_w2 = (const float*)d_in[15];
    const float* tg_b2 = (const float*)d_in[16];
    const float* sg_w1 = (const float*)d_in[17];
    const float* sg_b1 = (const float*)d_in[18];
    const float* sg_w2 = (const float*)d_in[19];
    const float* sg_b2 = (const float*)d_in[20];
    float* out = (float*)d_out;

    static h16 *xh = nullptr, *w1t, *w2t, *w3t, *wgt, *eo;
    static float *gw, *sgw;
    if (!xh) {
        cudaGetSymbolAddress((void**)&xh,  g_xh);
        cudaGetSymbolAddress((void**)&w1t, g_w1t);
        cudaGetSymbolAddress((void**)&w2t, g_w2t);
        cudaGetSymbolAddress((void**)&w3t, g_w3t);
        cudaGetSymbolAddress((void**)&wgt, g_wgt);
        cudaGetSymbolAddress((void**)&eo,  g_eo);
        cudaGetSymbolAddress((void**)&gw,  g_gw);
        cudaGetSymbolAddress((void**)&sgw, g_sgw);
        cudaFuncSetAttribute(expert_fused, cudaFuncAttributeMaxDynamicSharedMemorySize,
                             (int)sizeof(SmemT));
        cudaFuncSetAttribute(gate_fused, cudaFuncAttributeMaxDynamicSharedMemorySize,
                             (int)sizeof(GSmem));
    }

    prep_x_gate<<<16384 + 512, 256>>>((const float4*)x, (unsigned*)xh, tg_w1, sg_w1, wgt);
    prep_weights<<<dim3(224, E_), 256>>>(ew1, ew2, ew3, w1t, w2t, w3t);

    gate_fused<<<B / 64, 256, sizeof(GSmem)>>>(
        xh, wgt, tg_b1, sg_b1, tg_w2, tg_b2, sg_w2, sg_b2, gw, sgw);

    expert_fused<<<dim3(E_, B / 64), 256, sizeof(SmemT)>>>(
        xh, w1t, w2t, w3t,
        eb1, eg1, ebt1, eb2, eg2, ebt2, eb3, eg3, ebt3, eo);

    combine_kernel<<<B / 2, 256>>>(eo, gw, sgw, out);
}